// round 10
// baseline (speedup 1.0000x reference)
#include <cuda_runtime.h>
#include <cuda_fp16.h>
#include <cstdint>

#define BB    64
#define TT    512
#define HID   256
#define DI    512
#define DS    16
#define NHH   8
#define HD    64
#define DCONV 4
#define CCH   544    // DI + 2*DS
#define PROJ  1064   // 2*DI + 2*DS + NH
#define ROWS  (BB*TT) // 32768
#define NC    16
#define LC    32     // TT/NC
#define NT1   1152   // PROJ padded to 9*128

// ---------------- scratch (device globals; no allocation allowed) ----------
__device__ __align__(16) float g_zx[ROWS * PROJ];
__device__ __align__(16) float g_y[ROWS * DI];
__device__ __align__(16) float g_bc[ROWS * 32];
__device__ __align__(16) float g_hloc[BB * NHH * NC * HD * DS];
__device__ __align__(16) float g_hstart[BB * NHH * NC * HD * DS];
__device__ __align__(16) float g_cum[BB * NHH * TT];
__device__ __align__(16) __half g_xh[ROWS * HID];
__device__ __align__(16) __half g_xl[ROWS * HID];
__device__ __align__(16) __half g_yh[ROWS * DI];
__device__ __align__(16) __half g_yl[ROWS * DI];
__device__ __align__(16) __half g_ph[ROWS * HID];
__device__ __align__(16) __half g_pl[ROWS * HID];
__device__ __align__(16) float g_ap[ROWS * 128];
__device__ __align__(16) __half g_wt1[NT1 * HID];
__device__ __align__(16) __half g_wt2[HID * DI];
__device__ __align__(16) __half g_wk[128 * HID];
__device__ __align__(16) float g_kb[128];

// ---------------- helpers ---------------------------------------------------
__device__ __forceinline__ float siluf(float x) { return x / (1.f + __expf(-x)); }
__device__ __forceinline__ float softplusf(float x) {
    return (x > 20.f) ? x : log1pf(__expf(x));
}
__device__ __forceinline__ float sigmoidf_(float x) { return 1.f / (1.f + __expf(-x)); }
__device__ __forceinline__ float warpSum(float v) {
#pragma unroll
    for (int o = 16; o; o >>= 1) v += __shfl_xor_sync(0xffffffffu, v, o);
    return v;
}
__device__ __forceinline__ void fp16split(float v, __half* h, __half* l) {
    __half hi = __float2half_rn(v);
    *h = hi;
    *l = __float2half_rn(v - __half2float(hi));
}
__device__ __forceinline__ uint32_t smem_u32(const void* p) {
    uint32_t a;
    asm("{ .reg .u64 t; cvta.to.shared.u64 t, %1; cvt.u32.u64 %0, t; }"
        : "=r"(a) : "l"(p));
    return a;
}
#define SWZ(b) ((b) ^ (((b) >> 3) & 0x70))

__device__ __forceinline__ void ldsm_x4(uint32_t* r, uint32_t addr) {
    asm volatile("ldmatrix.sync.aligned.m8n8.x4.shared.b16 {%0,%1,%2,%3}, [%4];"
                 : "=r"(r[0]), "=r"(r[1]), "=r"(r[2]), "=r"(r[3]) : "r"(addr));
}
__device__ __forceinline__ void mma16816(float* c, const uint32_t* a, const uint32_t* b) {
    asm volatile("mma.sync.aligned.m16n8k16.row.col.f32.f16.f16.f32 "
                 "{%0,%1,%2,%3}, {%4,%5,%6,%7}, {%8,%9}, {%0,%1,%2,%3};"
                 : "+f"(c[0]), "+f"(c[1]), "+f"(c[2]), "+f"(c[3])
                 : "r"(a[0]), "r"(a[1]), "r"(a[2]), "r"(a[3]), "r"(b[0]), "r"(b[1]));
}
#define CP16(sa, gp) \
    asm volatile("cp.async.cg.shared.global [%0], [%1], 16;" :: "r"(sa), "l"(gp))
#define CP_COMMIT() asm volatile("cp.async.commit_group;" ::: "memory")
#define CP_WAIT1() asm volatile("cp.async.wait_group 1;" ::: "memory")
#define CP_WAIT0() asm volatile("cp.async.wait_group 0;" ::: "memory")

// ---------------- fp16 A-split GEMM via mma.sync, cp.async 2-stage ----------
// C[M,N] = A@W^T + bias (+res). Ah/Al: [M,K] fp16 row-major (hi/lo split).
// B: [NT,K] fp16 row-major (W transposed, zero-padded). K%64==0.
// CTA tile 128x128, BK=64, 8 warps (2x4), warp tile 64x32, 2 MMA passes.
// If oh != nullptr (requires N==HID): also write fp16 hi/lo of result to
// row m+1 (skip rows where (m+1)%TT==0).
#define TILE_B 16384
#define GSM_STAGE (3 * TILE_B)
__global__ __launch_bounds__(256) void gemm_mma(
    const __half* __restrict__ Ah, const __half* __restrict__ Al,
    const __half* __restrict__ B,
    const float* __restrict__ bias, const float* __restrict__ res,
    float* __restrict__ C,
    __half* __restrict__ oh, __half* __restrict__ ol,
    int K, int N)
{
    extern __shared__ __align__(16) uint8_t dsm[];
    uint32_t sbase = smem_u32(dsm);

    int tid = threadIdx.x;
    int wid = tid >> 5, lane = tid & 31;
    int bm = blockIdx.y * 128, bn = blockIdx.x * 128;
    int wm = (wid >> 2) * 64;
    int wn = (wid & 3) * 32;

    // loader: row = tid/2, element half = (tid&1)*32; 4 x 16B chunks per tile
    int lrow = tid >> 1;
    int lhe  = (tid & 1) * 32;
    const __half* pAh = Ah + (size_t)(bm + lrow) * K + lhe;
    const __half* pAl = Al + (size_t)(bm + lrow) * K + lhe;
    const __half* pB  = B  + (size_t)(bn + lrow) * K + lhe;
    uint32_t so[4];
#pragma unroll
    for (int i = 0; i < 4; i++)
        so[i] = SWZ((uint32_t)(lrow * 128 + (tid & 1) * 64 + i * 16));

    float acc[4][4][4];
#pragma unroll
    for (int i = 0; i < 4; i++)
#pragma unroll
        for (int j = 0; j < 4; j++)
#pragma unroll
            for (int q = 0; q < 4; q++) acc[i][j][q] = 0.f;

    int aRow = lane & 15;
    int aKb  = (lane >> 4) << 4;
    int bRow = ((lane >> 4) << 3) + (lane & 7);
    int bKb  = ((lane >> 3) & 1) << 4;

    const int KC = K >> 6;

    // prologue: stage 0
    {
        uint32_t st = sbase;
#pragma unroll
        for (int i = 0; i < 4; i++) {
            CP16(st + so[i],              pAh + i * 8);
            CP16(st + TILE_B + so[i],     pAl + i * 8);
            CP16(st + 2 * TILE_B + so[i], pB  + i * 8);
        }
        CP_COMMIT();
    }

    for (int c = 0; c < KC; c++) {
        if (c + 1 < KC) {
            int e = (c + 1) * 64;
            uint32_t st = sbase + ((c + 1) & 1) * GSM_STAGE;
#pragma unroll
            for (int i = 0; i < 4; i++) {
                CP16(st + so[i],              pAh + e + i * 8);
                CP16(st + TILE_B + so[i],     pAl + e + i * 8);
                CP16(st + 2 * TILE_B + so[i], pB  + e + i * 8);
            }
            CP_COMMIT();
            CP_WAIT1();
        } else {
            CP_WAIT0();
        }
        __syncthreads();

        uint32_t st = sbase + (c & 1) * GSM_STAGE;
        uint32_t sAH = st, sAL = st + TILE_B, sB = st + 2 * TILE_B;

#pragma unroll
        for (int ks = 0; ks < 4; ks++) {
            int kb2 = ks * 32;    // byte offset of k16 slice
            uint32_t ah[4][4], al[4][4], bh[2][4];
#pragma unroll
            for (int mt = 0; mt < 4; mt++) {
                uint32_t off = SWZ((uint32_t)(wm + mt * 16 + aRow) * 128 + kb2 + aKb);
                ldsm_x4(ah[mt], sAH + off);
                ldsm_x4(al[mt], sAL + off);
            }
#pragma unroll
            for (int np = 0; np < 2; np++) {
                uint32_t off = SWZ((uint32_t)(wn + np * 16 + bRow) * 128 + kb2 + bKb);
                ldsm_x4(bh[np], sB + off);
            }
#pragma unroll
            for (int mt = 0; mt < 4; mt++) {
#pragma unroll
                for (int nt = 0; nt < 4; nt++) {
                    const uint32_t* pbh = &bh[nt >> 1][(nt & 1) * 2];
                    mma16816(acc[mt][nt], ah[mt], pbh);
                    mma16816(acc[mt][nt], al[mt], pbh);
                }
            }
        }
        __syncthreads();
    }

    // epilogue
    int mrow0 = bm + wm + (lane >> 2);
    int ncol0 = bn + wn + (lane & 3) * 2;
#pragma unroll
    for (int mt = 0; mt < 4; mt++) {
#pragma unroll
        for (int half = 0; half < 2; half++) {
            int m = mrow0 + mt * 16 + half * 8;
            float* crow = C ? C + (size_t)m * N : nullptr;
            const float* rrow = res ? res + (size_t)m * N : nullptr;
            int mp = m + 1;
            bool doshift = (oh != nullptr) && ((mp & (TT - 1)) != 0);
#pragma unroll
            for (int nt = 0; nt < 4; nt++) {
                int n = ncol0 + nt * 8;
                if (n + 1 < N) {
                    float v0 = acc[mt][nt][half * 2 + 0] + bias[n];
                    float v1 = acc[mt][nt][half * 2 + 1] + bias[n + 1];
                    if (res) { v0 += rrow[n]; v1 += rrow[n + 1]; }
                    if (crow) { crow[n] = v0; crow[n + 1] = v1; }
                    if (doshift) {
                        __half h0, l0, h1, l1;
                        fp16split(v0, &h0, &l0);
                        fp16split(v1, &h1, &l1);
                        __half2 hp, lp;
                        hp.x = h0; hp.y = h1; lp.x = l0; lp.y = l1;
                        *(__half2*)(oh + (size_t)mp * N + n) = hp;
                        *(__half2*)(ol + (size_t)mp * N + n) = lp;
                    }
                } else if (n < N) {
                    float v0 = acc[mt][nt][half * 2 + 0] + bias[n];
                    if (res) v0 += rrow[n];
                    if (crow) crow[n] = v0;
                }
            }
        }
    }
}

// ---------------- merged weight prep ----------------------------------------
#define W1SZ (NT1 * HID)
#define W2SZ (HID * DI)
#define WKSZ (128 * HID)
__global__ void prep_k(const float* __restrict__ in_w, const float* __restrict__ out_w,
                       const float* __restrict__ kp_w1, const float* __restrict__ kg_w1,
                       const float* __restrict__ kp_b1, const float* __restrict__ kg_b1,
                       __half* __restrict__ w1, __half* __restrict__ w2,
                       __half* __restrict__ wk, float* __restrict__ kb) {
    int idx = blockIdx.x * blockDim.x + threadIdx.x;
    if (idx < W1SZ) {
        int n = idx / HID, k = idx % HID;
        float v = (n < PROJ) ? in_w[(size_t)k * PROJ + n] : 0.f;
        w1[idx] = __float2half_rn(v);
    } else if (idx < W1SZ + W2SZ) {
        int i = idx - W1SZ;
        int n = i / DI, k = i % DI;
        w2[i] = __float2half_rn(out_w[(size_t)k * HID + n]);
    } else if (idx < W1SZ + W2SZ + WKSZ) {
        int i = idx - W1SZ - W2SZ;
        int n = i / HID, k = i % HID;
        float v = (n < 64) ? kp_w1[(size_t)k * 64 + n] : kg_w1[(size_t)k * 64 + (n - 64)];
        wk[i] = __float2half_rn(v);
        if (i < 128) kb[i] = (i < 64) ? kp_b1[i] : kg_b1[i - 64];
    }
}

__global__ void initrow_k(const float* __restrict__ init_state,
                          __half* __restrict__ oh, __half* __restrict__ ol) {
    int b = blockIdx.x;
    int tid = threadIdx.x;
    float4 v = ((const float4*)init_state)[tid];
    float o[4] = {v.x, v.y, v.z, v.w};
    __half hh[4], ll[4];
#pragma unroll
    for (int i = 0; i < 4; i++) fp16split(o[i], &hh[i], &ll[i]);
    size_t base = (size_t)(b * TT) * HID + tid * 4;
    *(uint2*)(oh + base) = *(uint2*)hh;
    *(uint2*)(ol + base) = *(uint2*)ll;
}

// ---------------- 1) rmsnorm -> fp16 hi/lo (warp per row) -------------------
__global__ void rmsnorm_cvt_k(const float* __restrict__ x, const float* __restrict__ w,
                              __half* __restrict__ oh, __half* __restrict__ ol) {
    int r = blockIdx.x * 4 + (threadIdx.x >> 5);
    int lane = threadIdx.x & 31;
    const float4* xr = (const float4*)(x + (size_t)r * HID);
    float4 v0 = xr[lane], v1 = xr[lane + 32];
    float ss = v0.x*v0.x + v0.y*v0.y + v0.z*v0.z + v0.w*v0.w
             + v1.x*v1.x + v1.y*v1.y + v1.z*v1.z + v1.w*v1.w;
    ss = warpSum(ss);
    float sc = rsqrtf(ss / HID + 1e-5f);
    const float4* wr = (const float4*)w;
    float4 w0 = wr[lane], w1 = wr[lane + 32];
    float o0[4] = {v0.x*sc*w0.x, v0.y*sc*w0.y, v0.z*sc*w0.z, v0.w*sc*w0.w};
    float o1[4] = {v1.x*sc*w1.x, v1.y*sc*w1.y, v1.z*sc*w1.z, v1.w*sc*w1.w};
    __half h0[4], l0[4], h1[4], l1[4];
#pragma unroll
    for (int i = 0; i < 4; i++) { fp16split(o0[i], &h0[i], &l0[i]); fp16split(o1[i], &h1[i], &l1[i]); }
    size_t base = (size_t)r * HID;
    *(uint2*)(oh + base + lane * 4) = *(uint2*)h0;
    *(uint2*)(oh + base + (lane + 32) * 4) = *(uint2*)h1;
    *(uint2*)(ol + base + lane * 4) = *(uint2*)l0;
    *(uint2*)(ol + base + (lane + 32) * 4) = *(uint2*)l1;
}

// ---------------- 4a) fused conv+silu + chunked scan local pass -------------
__global__ __launch_bounds__(64) void scanA_k(
    const float* __restrict__ zx, const float* __restrict__ cw,
    const float* __restrict__ cbv,
    const float* __restrict__ dt_bias, const float* __restrict__ A_log,
    const float* __restrict__ Dp, float* __restrict__ y,
    float* __restrict__ hloc, float* __restrict__ cum, float* __restrict__ bc)
{
    __shared__ float sBC[LC][32];
    __shared__ float sdt[LC];
    int h = blockIdx.x, b = blockIdx.y, c = blockIdx.z;
    int d = threadIdx.x;
    int t0 = c * LC;
    size_t rowbase = (size_t)(b * TT + t0);

    for (int i = d; i < LC * 32; i += 64) {
        int t = i >> 5, j = i & 31;
        int ch = 512 + j;
        float acc = cbv[ch];
#pragma unroll
        for (int k = 0; k < DCONV; k++) {
            int tt = t0 + t - (DCONV - 1) + k;
            if (tt >= 0)
                acc = fmaf(zx[((size_t)(b * TT + tt)) * PROJ + DI + ch],
                           cw[k * CCH + ch], acc);
        }
        float v = siluf(acc);
        sBC[t][j] = v;
        if (h == 0) bc[(rowbase + t) * 32 + j] = v;
    }
    float dtb = dt_bias[h];
    for (int i = d; i < LC; i += 64)
        sdt[i] = softplusf(zx[(rowbase + i) * PROJ + 2 * DI + 2 * DS + h] + dtb);
    __syncthreads();

    int ch = h * HD + d;
    float w0 = cw[0 * CCH + ch], w1 = cw[1 * CCH + ch];
    float w2 = cw[2 * CCH + ch], w3 = cw[3 * CCH + ch];
    float cb0 = cbv[ch];
    const float* xcol = zx + DI + ch;
    float r0 = 0.f, r1 = 0.f, r2 = 0.f;
    {
        int tb = t0 - 3;
        if (tb >= 0)     r0 = xcol[(size_t)(b * TT + tb) * PROJ];
        if (tb + 1 >= 0) r1 = xcol[(size_t)(b * TT + tb + 1) * PROJ];
        if (tb + 2 >= 0) r2 = xcol[(size_t)(b * TT + tb + 2) * PROJ];
    }

    float A = -__expf(A_log[h]);
    float Dh = Dp[h];
    float hr[DS];
#pragma unroll
    for (int s = 0; s < DS; s++) hr[s] = 0.f;
    float cm = 1.f;

    float* yp = y + rowbase * DI + h * HD + d;
    float* cmp = cum + ((size_t)(b * NHH + h)) * TT + t0;

    for (int t = 0; t < LC; t++) {
        float raw = xcol[(rowbase + t) * PROJ];
        float x = siluf(fmaf(raw, w3, fmaf(r2, w2, fmaf(r1, w1, fmaf(r0, w0, cb0)))));
        r0 = r1; r1 = r2; r2 = raw;

        float dtsp = sdt[t];
        float dA = __expf(dtsp * A);
        cm *= dA;
        if (d == 0) cmp[t] = cm;
        float dtx = dtsp * x;
        float yvp[4] = {Dh * x, 0.f, 0.f, 0.f};
        float Bv[16], Cv[16];
        *(float4*)&Bv[0]  = *(const float4*)&sBC[t][0];
        *(float4*)&Bv[4]  = *(const float4*)&sBC[t][4];
        *(float4*)&Bv[8]  = *(const float4*)&sBC[t][8];
        *(float4*)&Bv[12] = *(const float4*)&sBC[t][12];
        *(float4*)&Cv[0]  = *(const float4*)&sBC[t][16];
        *(float4*)&Cv[4]  = *(const float4*)&sBC[t][20];
        *(float4*)&Cv[8]  = *(const float4*)&sBC[t][24];
        *(float4*)&Cv[12] = *(const float4*)&sBC[t][28];
#pragma unroll
        for (int s = 0; s < DS; s++) {
            hr[s] = fmaf(hr[s], dA, dtx * Bv[s]);
            yvp[s & 3] = fmaf(hr[s], Cv[s], yvp[s & 3]);
        }
        yp[(size_t)t * DI] = (yvp[0] + yvp[1]) + (yvp[2] + yvp[3]);
    }

    float* hl = hloc + ((size_t)((b * NHH + h) * NC + c)) * (DS * HD);
#pragma unroll
    for (int s = 0; s < DS; s++) hl[s * HD + d] = hr[s];
}

// ---------------- 4b) chain chunk states ------------------------------------
__global__ __launch_bounds__(64) void scanB_k(const float* __restrict__ hloc,
                                              const float* __restrict__ cum,
                                              float* __restrict__ hstart)
{
    int h = blockIdx.x, b = blockIdx.y, d = threadIdx.x;
    size_t base = (size_t)(b * NHH + h);
    float hs[DS];
#pragma unroll
    for (int s = 0; s < DS; s++) hs[s] = 0.f;
    for (int c = 0; c < NC; c++) {
        float* hsp = hstart + (base * NC + c) * (DS * HD);
#pragma unroll
        for (int s = 0; s < DS; s++) hsp[s * HD + d] = hs[s];
        float P = cum[base * TT + c * LC + LC - 1];
        const float* hl = hloc + (base * NC + c) * (DS * HD);
#pragma unroll
        for (int s = 0; s < DS; s++) hs[s] = fmaf(hs[s], P, hl[s * HD + d]);
    }
}

// ---------------- 4c) correction --------------------------------------------
__global__ __launch_bounds__(64) void scanC_k(const float* __restrict__ bc,
                                              const float* __restrict__ hstart,
                                              const float* __restrict__ cum,
                                              float* __restrict__ y)
{
    __shared__ float sC[LC][16];
    __shared__ float scm[LC];
    int h = blockIdx.x, b = blockIdx.y, c = blockIdx.z + 1;
    int d = threadIdx.x;
    int t0 = c * LC;
    size_t rowbase = (size_t)(b * TT + t0);
    size_t base = (size_t)(b * NHH + h);

    for (int i = d; i < LC * 16; i += 64) {
        int t = i >> 4, j = i & 15;
        sC[t][j] = bc[(rowbase + t) * 32 + 16 + j];
    }
    for (int i = d; i < LC; i += 64) scm[i] = cum[base * TT + t0 + i];

    float hs[DS];
    const float* hsp = hstart + (base * NC + c) * (DS * HD);
#pragma unroll
    for (int s = 0; s < DS; s++) hs[s] = hsp[s * HD + d];
    __syncthreads();

    float* yp = y + rowbase * DI + h * HD + d;
    for (int t = 0; t < LC; t++) {
        float Cv[16];
        *(float4*)&Cv[0]  = *(const float4*)&sC[t][0];
        *(float4*)&Cv[4]  = *(const float4*)&sC[t][4];
        *(float4*)&Cv[8]  = *(const float4*)&sC[t][8];
        *(float4*)&Cv[12] = *(const float4*)&sC[t][12];
        float acc = 0.f;
#pragma unroll
        for (int s = 0; s < DS; s++) acc = fmaf(hs[s], Cv[s], acc);
        yp[(size_t)t * DI] += acc * scm[t];
    }
}

// ---------------- 5) gate + rmsnorm -> fp16 (warp per row) ------------------
__global__ void gatenorm_cvt_k(const float* __restrict__ y, const float* __restrict__ zx,
                               const float* __restrict__ gw,
                               __half* __restrict__ oh, __half* __restrict__ ol) {
    int r = blockIdx.x * 4 + (threadIdx.x >> 5);
    int lane = threadIdx.x & 31;
    const float4* yr = (const float4*)(y + (size_t)r * DI);
    const float4* zr = (const float4*)(zx + (size_t)r * PROJ);
    float4 g[4];
    float ss = 0.f;
#pragma unroll
    for (int k = 0; k < 4; k++) {
        float4 yv = yr[lane + 32 * k];
        float4 zv = zr[lane + 32 * k];
        g[k].x = yv.x * siluf(zv.x); g[k].y = yv.y * siluf(zv.y);
        g[k].z = yv.z * siluf(zv.z); g[k].w = yv.w * siluf(zv.w);
        ss += g[k].x*g[k].x + g[k].y*g[k].y + g[k].z*g[k].z + g[k].w*g[k].w;
    }
    ss = warpSum(ss);
    float sc = rsqrtf(ss / DI + 1e-5f);
    const float4* wr = (const float4*)gw;
    size_t base = (size_t)r * DI;
#pragma unroll
    for (int k = 0; k < 4; k++) {
        float4 wv = wr[lane + 32 * k];
        float o[4] = {g[k].x*sc*wv.x, g[k].y*sc*wv.y, g[k].z*sc*wv.z, g[k].w*sc*wv.w};
        __half hh[4], ll[4];
#pragma unroll
        for (int i = 0; i < 4; i++) fp16split(o[i], &hh[i], &ll[i]);
        *(uint2*)(oh + base + (lane + 32 * k) * 4) = *(uint2*)hh;
        *(uint2*)(ol + base + (lane + 32 * k) * 4) = *(uint2*)ll;
    }
}

// ---------------- 7b) Kalman finish -----------------------------------------
__global__ __launch_bounds__(64) void kalman_fin_k(
    const float* __restrict__ AP, const float* __restrict__ z_t,
    const float* __restrict__ kg_w1,
    const float* __restrict__ kp_w2, const float* __restrict__ kp_b2,
    const float* __restrict__ km_w1, const float* __restrict__ km_b1,
    const float* __restrict__ km_w2, const float* __restrict__ km_b2,
    const float* __restrict__ kg_w2, const float* __restrict__ kg_b2,
    const float* __restrict__ kW, float* __restrict__ out)
{
    __shared__ float redv[2], redg[2];
    int r = blockIdx.x;
    int tid = threadIdx.x;
    float z = z_t[r];
    float ap = AP[(size_t)r * 128 + tid];
    float ag = AP[(size_t)r * 128 + 64 + tid];
    ag = fmaf(z, kg_w1[HID * 64 + tid], ag);
    float vp = siluf(ap) * kp_w2[tid];
    float gp = siluf(ag) * kg_w2[tid];
    vp = warpSum(vp);
    gp = warpSum(gp);
    if ((tid & 31) == 0) { redv[tid >> 5] = vp; redg[tid >> 5] = gp; }
    __syncthreads();
    if (tid == 0) {
        float v_prior = softplusf(redv[0] + redv[1] + kp_b2[0]);
        float Kt = sigmoidf_(redg[0] + redg[1] + kg_b2[0]);
        float macc = km_b2[0];
#pragma unroll
        for (int k = 0; k < 32; k++)
            macc = fmaf(siluf(fmaf(z, km_w1[k], km_b1[k])), km_w2[k], macc);
        float m_t = softplusf(macc);
        float vpost = v_prior + Kt * (m_t - kW[0] * v_prior);
        vpost = fminf(fmaxf(vpost, 1e-6f), 10.f);
        out[r] = vpost;
    }
}

// ---------------- 8) per-batch softmax reductions ---------------------------
__global__ void reduce_k(float* __restrict__ out) {
    __shared__ float sa[256], sb[256];
    int b = blockIdx.x;
    int tid = threadIdx.x;
    const float* v = out + (size_t)b * TT;
    float v0 = v[tid], v1 = v[tid + 256];

    sa[tid] = fmaxf(v0, v1);
    sb[tid] = fminf(v0, v1);
    __syncthreads();
    for (int s = 128; s > 0; s >>= 1) {
        if (tid < s) {
            sa[tid] = fmaxf(sa[tid], sa[tid + s]);
            sb[tid] = fminf(sb[tid], sb[tid + s]);
        }
        __syncthreads();
    }
    float mx = sa[0], mn = sb[0];
    __syncthreads();

    float e0 = __expf(v0 - mx), e1 = __expf(v1 - mx);
    sa[tid] = e0 + e1;
    sb[tid] = e0 * v0 + e1 * v1;
    __syncthreads();
    for (int s = 128; s > 0; s >>= 1) {
        if (tid < s) { sa[tid] += sa[tid + s]; sb[tid] += sb[tid + s]; }
        __syncthreads();
    }
    float spden = sa[0], spnum = sb[0];
    __syncthreads();

    float f0 = __expf(mn - v0), f1 = __expf(mn - v1);
    sa[tid] = f0 + f1;
    sb[tid] = f0 * v0 + f1 * v1;
    __syncthreads();
    for (int s = 128; s > 0; s >>= 1) {
        if (tid < s) { sa[tid] += sa[tid + s]; sb[tid] += sb[tid + s]; }
        __syncthreads();
    }
    if (tid == 0) {
        out[ROWS + b] = spnum / spden;
        out[ROWS + BB + b] = sb[0] / sa[0];
    }
}

// ---------------- launcher ---------------------------------------------------
extern "C" void kernel_launch(void* const* d_in, const int* in_sizes, int n_in,
                              void* d_out, int out_size) {
    const float* tokens   = (const float*)d_in[0];
    const float* z_t      = (const float*)d_in[1];
    const float* norm_w   = (const float*)d_in[2];
    const float* in_w     = (const float*)d_in[3];
    const float* in_b     = (const float*)d_in[4];
    const float* conv_w   = (const float*)d_in[5];
    const float* conv_b   = (const float*)d_in[6];
    const float* dt_bias  = (const float*)d_in[7];
    const float* A_log    = (const float*)d_in[8];
    const float* Dp       = (const float*)d_in[9];
    const float* gnorm_w  = (const float*)d_in[10];
    const float* out_w    = (const float*)d_in[11];
    const float* out_b    = (const float*)d_in[12];
    const float* kp_w1    = (const float*)d_in[13];
    const float* kp_b1    = (const float*)d_in[14];
    const float* kp_w2    = (const float*)d_in[15];
    const float* kp_b2    = (const float*)d_in[16];
    const float* km_w1    = (const float*)d_in[17];
    const float* km_b1    = (const float*)d_in[18];
    const float* km_w2    = (const float*)d_in[19];
    const float* km_b2    = (const float*)d_in[20];
    const float* kg_w1    = (const float*)d_in[21];
    const float* kg_b1    = (const float*)d_in[22];
    const float* kg_w2    = (const float*)d_in[23];
    const float* kg_b2    = (const float*)d_in[24];
    const float* kW       = (const float*)d_in[25];
    const float* init_st  = (const float*)d_in[26];
    float* out = (float*)d_out;

    float *zx, *y, *bc, *hloc, *hstart, *cum, *ap, *kb;
    __half *xh, *xl, *yh, *yl, *ph, *pl, *wt1, *wt2, *wk;
    cudaGetSymbolAddress((void**)&zx,     g_zx);
    cudaGetSymbolAddress((void**)&y,      g_y);
    cudaGetSymbolAddress((void**)&bc,     g_bc);
    cudaGetSymbolAddress((void**)&hloc,   g_hloc);
    cudaGetSymbolAddress((void**)&hstart, g_hstart);
    cudaGetSymbolAddress((void**)&cum,    g_cum);
    cudaGetSymbolAddress((void**)&ap,     g_ap);
    cudaGetSymbolAddress((void**)&kb,     g_kb);
    cudaGetSymbolAddress((void**)&xh,     g_xh);
    cudaGetSymbolAddress((void**)&xl,     g_xl);
    cudaGetSymbolAddress((void**)&yh,     g_yh);
    cudaGetSymbolAddress((void**)&yl,     g_yl);
    cudaGetSymbolAddress((void**)&ph,     g_ph);
    cudaGetSymbolAddress((void**)&pl,     g_pl);
    cudaGetSymbolAddress((void**)&wt1,    g_wt1);
    cudaGetSymbolAddress((void**)&wt2,    g_wt2);
    cudaGetSymbolAddress((void**)&wk,     g_wk);

    cudaFuncSetAttribute(gemm_mma, cudaFuncAttributeMaxDynamicSharedMemorySize,
                         2 * GSM_STAGE);

    // weight prep (merged, single fp16) + t=0 Kalman rows
    prep_k<<<(W1SZ + W2SZ + WKSZ + 255) / 256, 256>>>(
        in_w, out_w, kp_w1, kg_w1, kp_b1, kg_b1, wt1, wt2, wk, kb);
    initrow_k<<<BB, 64>>>(init_st, ph, pl);

    // 1) rmsnorm -> fp16 split (warp per row)
    rmsnorm_cvt_k<<<ROWS / 4, 128>>>(tokens, norm_w, xh, xl);
    // 2) in-proj GEMM
    gemm_mma<<<dim3(NT1 / 128, ROWS / 128), 256, 2 * GSM_STAGE>>>(
        xh, xl, wt1, in_b, nullptr, zx, nullptr, nullptr, HID, PROJ);
    // 3+4) fused conv + chunked scan
    scanA_k<<<dim3(NHH, BB, NC), 64>>>(zx, conv_w, conv_b, dt_bias, A_log, Dp,
                                       y, hloc, cum, bc);
    scanB_k<<<dim3(NHH, BB), 64>>>(hloc, cum, hstart);
    scanC_k<<<dim3(NHH, BB, NC - 1), 64>>>(bc, hstart, cum, y);
    // 5) gate + rmsnorm (warp per row)
    gatenorm_cvt_k<<<ROWS / 4, 128>>>(y, zx, gnorm_w, yh, yl);
    // 6) out-proj GEMM + residual, fused shift+cvt into ph/pl
    gemm_mma<<<dim3(HID / 128, ROWS / 128), 256, 2 * GSM_STAGE>>>(
        yh, yl, wt2, out_b, tokens, nullptr, ph, pl, DI, HID);
    // 7) Kalman GEMM -> finish
    gemm_mma<<<dim3(1, ROWS / 128), 256, 2 * GSM_STAGE>>>(
        ph, pl, wk, kb, nullptr, ap, nullptr, nullptr, HID, 128);
    kalman_fin_k<<<ROWS, 64>>>(ap, z_t, kg_w1,
                               kp_w2, kp_b2, km_w1, km_b1, km_w2, km_b2,
                               kg_w2, kg_b2, kW, out);
    // 8) per-batch reductions
    reduce_k<<<BB, 256>>>(out);
}

// round 11
// speedup vs baseline: 1.1435x; 1.1435x over previous
#include <cuda_runtime.h>
#include <cuda_fp16.h>
#include <cstdint>

#define BB    64
#define TT    512
#define HID   256
#define DI    512
#define DS    16
#define NHH   8
#define HD    64
#define DCONV 4
#define CCH   544    // DI + 2*DS
#define PROJ  1064   // 2*DI + 2*DS + NH
#define ROWS  (BB*TT) // 32768
#define NC    16
#define LC    32     // TT/NC
#define NT1   1152   // PROJ padded to 9*128

// ---------------- scratch (device globals; no allocation allowed) ----------
__device__ __align__(16) float g_zx[ROWS * PROJ];
__device__ __align__(16) float g_y[ROWS * DI];
__device__ __align__(16) float g_bc[ROWS * 32];
__device__ __align__(16) float g_hloc[BB * NHH * NC * HD * DS];
__device__ __align__(16) float g_hstart[BB * NHH * NC * HD * DS];
__device__ __align__(16) float g_cum[BB * NHH * TT];
__device__ __align__(16) __half g_xh[ROWS * HID];
__device__ __align__(16) __half g_xl[ROWS * HID];
__device__ __align__(16) __half g_yh[ROWS * DI];
__device__ __align__(16) __half g_yl[ROWS * DI];
__device__ __align__(16) __half g_ph[ROWS * HID];
__device__ __align__(16) __half g_pl[ROWS * HID];
__device__ __align__(16) float g_ap[ROWS * 128];
__device__ __align__(16) __half g_wt1[NT1 * HID];
__device__ __align__(16) __half g_wt2[HID * DI];
__device__ __align__(16) __half g_wk[128 * HID];
__device__ __align__(16) float g_kb[128];

// ---------------- helpers ---------------------------------------------------
__device__ __forceinline__ float siluf(float x) { return x / (1.f + __expf(-x)); }
__device__ __forceinline__ float softplusf(float x) {
    return (x > 20.f) ? x : log1pf(__expf(x));
}
__device__ __forceinline__ float sigmoidf_(float x) { return 1.f / (1.f + __expf(-x)); }
__device__ __forceinline__ float warpSum(float v) {
#pragma unroll
    for (int o = 16; o; o >>= 1) v += __shfl_xor_sync(0xffffffffu, v, o);
    return v;
}
__device__ __forceinline__ void fp16split(float v, __half* h, __half* l) {
    __half hi = __float2half_rn(v);
    *h = hi;
    *l = __float2half_rn(v - __half2float(hi));
}
__device__ __forceinline__ uint32_t smem_u32(const void* p) {
    uint32_t a;
    asm("{ .reg .u64 t; cvta.to.shared.u64 t, %1; cvt.u32.u64 %0, t; }"
        : "=r"(a) : "l"(p));
    return a;
}
#define SWZ(b) ((b) ^ (((b) >> 3) & 0x70))

__device__ __forceinline__ void ldsm_x4(uint32_t* r, uint32_t addr) {
    asm volatile("ldmatrix.sync.aligned.m8n8.x4.shared.b16 {%0,%1,%2,%3}, [%4];"
                 : "=r"(r[0]), "=r"(r[1]), "=r"(r[2]), "=r"(r[3]) : "r"(addr));
}
__device__ __forceinline__ void mma16816(float* c, const uint32_t* a, const uint32_t* b) {
    asm volatile("mma.sync.aligned.m16n8k16.row.col.f32.f16.f16.f32 "
                 "{%0,%1,%2,%3}, {%4,%5,%6,%7}, {%8,%9}, {%0,%1,%2,%3};"
                 : "+f"(c[0]), "+f"(c[1]), "+f"(c[2]), "+f"(c[3])
                 : "r"(a[0]), "r"(a[1]), "r"(a[2]), "r"(a[3]), "r"(b[0]), "r"(b[1]));
}
#define CP16(sa, gp) \
    asm volatile("cp.async.cg.shared.global [%0], [%1], 16;" :: "r"(sa), "l"(gp))
#define CP_COMMIT() asm volatile("cp.async.commit_group;" ::: "memory")
#define CP_WAIT1() asm volatile("cp.async.wait_group 1;" ::: "memory")
#define CP_WAIT0() asm volatile("cp.async.wait_group 0;" ::: "memory")

// ---------------- fp16 A-split GEMM via mma.sync, cp.async 2-stage ----------
// C[M,N] = A@W^T + bias (+res). Ah/Al: [M,K] fp16 row-major (hi/lo split).
// B: [NT,K] fp16 row-major (W transposed, zero-padded). K%32==0.
// CTA tile 128x128, BK=32, 8 warps (2x4), warp tile 64x32, 2 MMA passes.
// If oh != nullptr (requires N==HID): also write fp16 hi/lo of result to
// row m+1 (skip rows where (m+1)%TT==0).
#define TILE_B 8192
#define GSM_STAGE (3 * TILE_B)
__global__ __launch_bounds__(256, 2) void gemm_mma(
    const __half* __restrict__ Ah, const __half* __restrict__ Al,
    const __half* __restrict__ B,
    const float* __restrict__ bias, const float* __restrict__ res,
    float* __restrict__ C,
    __half* __restrict__ oh, __half* __restrict__ ol,
    int K, int N)
{
    extern __shared__ __align__(16) uint8_t dsm[];
    uint32_t sbase = smem_u32(dsm);

    int tid = threadIdx.x;
    int wid = tid >> 5, lane = tid & 31;
    int bm = blockIdx.y * 128, bn = blockIdx.x * 128;
    int wm = (wid >> 2) * 64;
    int wn = (wid & 3) * 32;

    // loader: row = tid/2, two 16B chunks per tile (64B rows)
    int lrow = tid >> 1;
    int lke  = (tid & 1) * 16;       // element offset 0/16 within 32-wide chunk
    const __half* pAh = Ah + (size_t)(bm + lrow) * K + lke;
    const __half* pAl = Al + (size_t)(bm + lrow) * K + lke;
    const __half* pB  = B  + (size_t)(bn + lrow) * K + lke;
    uint32_t so0 = SWZ((uint32_t)(lrow * 64 + lke * 2));
    uint32_t so1 = SWZ((uint32_t)(lrow * 64 + lke * 2 + 16));

    float acc[4][4][4];
#pragma unroll
    for (int i = 0; i < 4; i++)
#pragma unroll
        for (int j = 0; j < 4; j++)
#pragma unroll
            for (int q = 0; q < 4; q++) acc[i][j][q] = 0.f;

    int aRow = lane & 15;
    int aKb  = (lane >> 4) << 4;
    int bRow = ((lane >> 4) << 3) + (lane & 7);
    int bKb  = ((lane >> 3) & 1) << 4;

    const int KC = K >> 5;

    // prologue: stage 0
    {
        uint32_t st = sbase;
        CP16(st + so0,              pAh);      CP16(st + so1,              pAh + 8);
        CP16(st + TILE_B + so0,     pAl);      CP16(st + TILE_B + so1,     pAl + 8);
        CP16(st + 2 * TILE_B + so0, pB);       CP16(st + 2 * TILE_B + so1, pB + 8);
        CP_COMMIT();
    }

    for (int c = 0; c < KC; c++) {
        if (c + 1 < KC) {
            int e = (c + 1) * 32;
            uint32_t st = sbase + ((c + 1) & 1) * GSM_STAGE;
            CP16(st + so0,              pAh + e);  CP16(st + so1,              pAh + e + 8);
            CP16(st + TILE_B + so0,     pAl + e);  CP16(st + TILE_B + so1,     pAl + e + 8);
            CP16(st + 2 * TILE_B + so0, pB + e);   CP16(st + 2 * TILE_B + so1, pB + e + 8);
            CP_COMMIT();
            CP_WAIT1();
        } else {
            CP_WAIT0();
        }
        __syncthreads();

        uint32_t st = sbase + (c & 1) * GSM_STAGE;
        uint32_t sAH = st, sAL = st + TILE_B, sB = st + 2 * TILE_B;

#pragma unroll
        for (int ks = 0; ks < 2; ks++) {
            int kb = ks * 32;
            uint32_t ah[4][4], al[4][4], bh[2][4];
#pragma unroll
            for (int mt = 0; mt < 4; mt++) {
                uint32_t off = SWZ((uint32_t)(wm + mt * 16 + aRow) * 64 + kb + aKb);
                ldsm_x4(ah[mt], sAH + off);
                ldsm_x4(al[mt], sAL + off);
            }
#pragma unroll
            for (int np = 0; np < 2; np++) {
                uint32_t off = SWZ((uint32_t)(wn + np * 16 + bRow) * 64 + kb + bKb);
                ldsm_x4(bh[np], sB + off);
            }
#pragma unroll
            for (int mt = 0; mt < 4; mt++) {
#pragma unroll
                for (int nt = 0; nt < 4; nt++) {
                    const uint32_t* pbh = &bh[nt >> 1][(nt & 1) * 2];
                    mma16816(acc[mt][nt], ah[mt], pbh);
                    mma16816(acc[mt][nt], al[mt], pbh);
                }
            }
        }
        __syncthreads();
    }

    // epilogue
    int mrow0 = bm + wm + (lane >> 2);
    int ncol0 = bn + wn + (lane & 3) * 2;
#pragma unroll
    for (int mt = 0; mt < 4; mt++) {
#pragma unroll
        for (int half = 0; half < 2; half++) {
            int m = mrow0 + mt * 16 + half * 8;
            float* crow = C ? C + (size_t)m * N : nullptr;
            const float* rrow = res ? res + (size_t)m * N : nullptr;
            int mp = m + 1;
            bool doshift = (oh != nullptr) && ((mp & (TT - 1)) != 0);
#pragma unroll
            for (int nt = 0; nt < 4; nt++) {
                int n = ncol0 + nt * 8;
                if (n + 1 < N) {
                    float v0 = acc[mt][nt][half * 2 + 0] + bias[n];
                    float v1 = acc[mt][nt][half * 2 + 1] + bias[n + 1];
                    if (res) { v0 += rrow[n]; v1 += rrow[n + 1]; }
                    if (crow) { crow[n] = v0; crow[n + 1] = v1; }
                    if (doshift) {
                        __half h0, l0, h1, l1;
                        fp16split(v0, &h0, &l0);
                        fp16split(v1, &h1, &l1);
                        __half2 hp, lp;
                        hp.x = h0; hp.y = h1; lp.x = l0; lp.y = l1;
                        *(__half2*)(oh + (size_t)mp * N + n) = hp;
                        *(__half2*)(ol + (size_t)mp * N + n) = lp;
                    }
                } else if (n < N) {
                    float v0 = acc[mt][nt][half * 2 + 0] + bias[n];
                    if (res) v0 += rrow[n];
                    if (crow) crow[n] = v0;
                }
            }
        }
    }
}

// ---------------- merged weight prep ----------------------------------------
#define W1SZ (NT1 * HID)
#define W2SZ (HID * DI)
#define WKSZ (128 * HID)
__global__ void prep_k(const float* __restrict__ in_w, const float* __restrict__ out_w,
                       const float* __restrict__ kp_w1, const float* __restrict__ kg_w1,
                       const float* __restrict__ kp_b1, const float* __restrict__ kg_b1,
                       __half* __restrict__ w1, __half* __restrict__ w2,
                       __half* __restrict__ wk, float* __restrict__ kb) {
    int idx = blockIdx.x * blockDim.x + threadIdx.x;
    if (idx < W1SZ) {
        int n = idx / HID, k = idx % HID;
        float v = (n < PROJ) ? in_w[(size_t)k * PROJ + n] : 0.f;
        w1[idx] = __float2half_rn(v);
    } else if (idx < W1SZ + W2SZ) {
        int i = idx - W1SZ;
        int n = i / DI, k = i % DI;
        w2[i] = __float2half_rn(out_w[(size_t)k * HID + n]);
    } else if (idx < W1SZ + W2SZ + WKSZ) {
        int i = idx - W1SZ - W2SZ;
        int n = i / HID, k = i % HID;
        float v = (n < 64) ? kp_w1[(size_t)k * 64 + n] : kg_w1[(size_t)k * 64 + (n - 64)];
        wk[i] = __float2half_rn(v);
        if (i < 128) kb[i] = (i < 64) ? kp_b1[i] : kg_b1[i - 64];
    }
}

__global__ void initrow_k(const float* __restrict__ init_state,
                          __half* __restrict__ oh, __half* __restrict__ ol) {
    int b = blockIdx.x;
    int tid = threadIdx.x;
    float4 v = ((const float4*)init_state)[tid];
    float o[4] = {v.x, v.y, v.z, v.w};
    __half hh[4], ll[4];
#pragma unroll
    for (int i = 0; i < 4; i++) fp16split(o[i], &hh[i], &ll[i]);
    size_t base = (size_t)(b * TT) * HID + tid * 4;
    *(uint2*)(oh + base) = *(uint2*)hh;
    *(uint2*)(ol + base) = *(uint2*)ll;
}

// ---------------- 1) rmsnorm -> fp16 hi/lo (warp per row) -------------------
__global__ void rmsnorm_cvt_k(const float* __restrict__ x, const float* __restrict__ w,
                              __half* __restrict__ oh, __half* __restrict__ ol) {
    int r = blockIdx.x * 4 + (threadIdx.x >> 5);
    int lane = threadIdx.x & 31;
    const float4* xr = (const float4*)(x + (size_t)r * HID);
    float4 v0 = xr[lane], v1 = xr[lane + 32];
    float ss = v0.x*v0.x + v0.y*v0.y + v0.z*v0.z + v0.w*v0.w
             + v1.x*v1.x + v1.y*v1.y + v1.z*v1.z + v1.w*v1.w;
    ss = warpSum(ss);
    float sc = rsqrtf(ss / HID + 1e-5f);
    const float4* wr = (const float4*)w;
    float4 w0 = wr[lane], w1 = wr[lane + 32];
    float o0[4] = {v0.x*sc*w0.x, v0.y*sc*w0.y, v0.z*sc*w0.z, v0.w*sc*w0.w};
    float o1[4] = {v1.x*sc*w1.x, v1.y*sc*w1.y, v1.z*sc*w1.z, v1.w*sc*w1.w};
    __half h0[4], l0[4], h1[4], l1[4];
#pragma unroll
    for (int i = 0; i < 4; i++) { fp16split(o0[i], &h0[i], &l0[i]); fp16split(o1[i], &h1[i], &l1[i]); }
    size_t base = (size_t)r * HID;
    *(uint2*)(oh + base + lane * 4) = *(uint2*)h0;
    *(uint2*)(oh + base + (lane + 32) * 4) = *(uint2*)h1;
    *(uint2*)(ol + base + lane * 4) = *(uint2*)l0;
    *(uint2*)(ol + base + (lane + 32) * 4) = *(uint2*)l1;
}

// ---------------- 4a) fused conv+silu + chunked scan local pass -------------
__global__ __launch_bounds__(64) void scanA_k(
    const float* __restrict__ zx, const float* __restrict__ cw,
    const float* __restrict__ cbv,
    const float* __restrict__ dt_bias, const float* __restrict__ A_log,
    const float* __restrict__ Dp, float* __restrict__ y,
    float* __restrict__ hloc, float* __restrict__ cum, float* __restrict__ bc)
{
    __shared__ float sBC[LC][32];
    __shared__ float sdt[LC];
    int h = blockIdx.x, b = blockIdx.y, c = blockIdx.z;
    int d = threadIdx.x;
    int t0 = c * LC;
    size_t rowbase = (size_t)(b * TT + t0);

    for (int i = d; i < LC * 32; i += 64) {
        int t = i >> 5, j = i & 31;
        int ch = 512 + j;
        float acc = cbv[ch];
#pragma unroll
        for (int k = 0; k < DCONV; k++) {
            int tt = t0 + t - (DCONV - 1) + k;
            if (tt >= 0)
                acc = fmaf(zx[((size_t)(b * TT + tt)) * PROJ + DI + ch],
                           cw[k * CCH + ch], acc);
        }
        float v = siluf(acc);
        sBC[t][j] = v;
        if (h == 0) bc[(rowbase + t) * 32 + j] = v;
    }
    float dtb = dt_bias[h];
    for (int i = d; i < LC; i += 64)
        sdt[i] = softplusf(zx[(rowbase + i) * PROJ + 2 * DI + 2 * DS + h] + dtb);
    __syncthreads();

    int ch = h * HD + d;
    float w0 = cw[0 * CCH + ch], w1 = cw[1 * CCH + ch];
    float w2 = cw[2 * CCH + ch], w3 = cw[3 * CCH + ch];
    float cb0 = cbv[ch];
    const float* xcol = zx + DI + ch;
    float r0 = 0.f, r1 = 0.f, r2 = 0.f;
    {
        int tb = t0 - 3;
        if (tb >= 0)     r0 = xcol[(size_t)(b * TT + tb) * PROJ];
        if (tb + 1 >= 0) r1 = xcol[(size_t)(b * TT + tb + 1) * PROJ];
        if (tb + 2 >= 0) r2 = xcol[(size_t)(b * TT + tb + 2) * PROJ];
    }

    float A = -__expf(A_log[h]);
    float Dh = Dp[h];
    float hr[DS];
#pragma unroll
    for (int s = 0; s < DS; s++) hr[s] = 0.f;
    float cm = 1.f;

    float* yp = y + rowbase * DI + h * HD + d;
    float* cmp = cum + ((size_t)(b * NHH + h)) * TT + t0;

    for (int t = 0; t < LC; t++) {
        float raw = xcol[(rowbase + t) * PROJ];
        float x = siluf(fmaf(raw, w3, fmaf(r2, w2, fmaf(r1, w1, fmaf(r0, w0, cb0)))));
        r0 = r1; r1 = r2; r2 = raw;

        float dtsp = sdt[t];
        float dA = __expf(dtsp * A);
        cm *= dA;
        if (d == 0) cmp[t] = cm;
        float dtx = dtsp * x;
        float yvp[4] = {Dh * x, 0.f, 0.f, 0.f};
        float Bv[16], Cv[16];
        *(float4*)&Bv[0]  = *(const float4*)&sBC[t][0];
        *(float4*)&Bv[4]  = *(const float4*)&sBC[t][4];
        *(float4*)&Bv[8]  = *(const float4*)&sBC[t][8];
        *(float4*)&Bv[12] = *(const float4*)&sBC[t][12];
        *(float4*)&Cv[0]  = *(const float4*)&sBC[t][16];
        *(float4*)&Cv[4]  = *(const float4*)&sBC[t][20];
        *(float4*)&Cv[8]  = *(const float4*)&sBC[t][24];
        *(float4*)&Cv[12] = *(const float4*)&sBC[t][28];
#pragma unroll
        for (int s = 0; s < DS; s++) {
            hr[s] = fmaf(hr[s], dA, dtx * Bv[s]);
            yvp[s & 3] = fmaf(hr[s], Cv[s], yvp[s & 3]);
        }
        yp[(size_t)t * DI] = (yvp[0] + yvp[1]) + (yvp[2] + yvp[3]);
    }

    float* hl = hloc + ((size_t)((b * NHH + h) * NC + c)) * (DS * HD);
#pragma unroll
    for (int s = 0; s < DS; s++) hl[s * HD + d] = hr[s];
}

// ---------------- 4b) chain chunk states ------------------------------------
__global__ __launch_bounds__(64) void scanB_k(const float* __restrict__ hloc,
                                              const float* __restrict__ cum,
                                              float* __restrict__ hstart)
{
    int h = blockIdx.x, b = blockIdx.y, d = threadIdx.x;
    size_t base = (size_t)(b * NHH + h);
    float hs[DS];
#pragma unroll
    for (int s = 0; s < DS; s++) hs[s] = 0.f;
    for (int c = 0; c < NC; c++) {
        float* hsp = hstart + (base * NC + c) * (DS * HD);
#pragma unroll
        for (int s = 0; s < DS; s++) hsp[s * HD + d] = hs[s];
        float P = cum[base * TT + c * LC + LC - 1];
        const float* hl = hloc + (base * NC + c) * (DS * HD);
#pragma unroll
        for (int s = 0; s < DS; s++) hs[s] = fmaf(hs[s], P, hl[s * HD + d]);
    }
}

// ---------------- 4c) correction --------------------------------------------
__global__ __launch_bounds__(64) void scanC_k(const float* __restrict__ bc,
                                              const float* __restrict__ hstart,
                                              const float* __restrict__ cum,
                                              float* __restrict__ y)
{
    __shared__ float sC[LC][16];
    __shared__ float scm[LC];
    int h = blockIdx.x, b = blockIdx.y, c = blockIdx.z + 1;
    int d = threadIdx.x;
    int t0 = c * LC;
    size_t rowbase = (size_t)(b * TT + t0);
    size_t base = (size_t)(b * NHH + h);

    for (int i = d; i < LC * 16; i += 64) {
        int t = i >> 4, j = i & 15;
        sC[t][j] = bc[(rowbase + t) * 32 + 16 + j];
    }
    for (int i = d; i < LC; i += 64) scm[i] = cum[base * TT + t0 + i];

    float hs[DS];
    const float* hsp = hstart + (base * NC + c) * (DS * HD);
#pragma unroll
    for (int s = 0; s < DS; s++) hs[s] = hsp[s * HD + d];
    __syncthreads();

    float* yp = y + rowbase * DI + h * HD + d;
    for (int t = 0; t < LC; t++) {
        float Cv[16];
        *(float4*)&Cv[0]  = *(const float4*)&sC[t][0];
        *(float4*)&Cv[4]  = *(const float4*)&sC[t][4];
        *(float4*)&Cv[8]  = *(const float4*)&sC[t][8];
        *(float4*)&Cv[12] = *(const float4*)&sC[t][12];
        float acc = 0.f;
#pragma unroll
        for (int s = 0; s < DS; s++) acc = fmaf(hs[s], Cv[s], acc);
        yp[(size_t)t * DI] += acc * scm[t];
    }
}

// ---------------- 5) gate + rmsnorm -> fp16 (warp per row) ------------------
__global__ void gatenorm_cvt_k(const float* __restrict__ y, const float* __restrict__ zx,
                               const float* __restrict__ gw,
                               __half* __restrict__ oh, __half* __restrict__ ol) {
    int r = blockIdx.x * 4 + (threadIdx.x >> 5);
    int lane = threadIdx.x & 31;
    const float4* yr = (const float4*)(y + (size_t)r * DI);
    const float4* zr = (const float4*)(zx + (size_t)r * PROJ);
    float4 g[4];
    float ss = 0.f;
#pragma unroll
    for (int k = 0; k < 4; k++) {
        float4 yv = yr[lane + 32 * k];
        float4 zv = zr[lane + 32 * k];
        g[k].x = yv.x * siluf(zv.x); g[k].y = yv.y * siluf(zv.y);
        g[k].z = yv.z * siluf(zv.z); g[k].w = yv.w * siluf(zv.w);
        ss += g[k].x*g[k].x + g[k].y*g[k].y + g[k].z*g[k].z + g[k].w*g[k].w;
    }
    ss = warpSum(ss);
    float sc = rsqrtf(ss / DI + 1e-5f);
    const float4* wr = (const float4*)gw;
    size_t base = (size_t)r * DI;
#pragma unroll
    for (int k = 0; k < 4; k++) {
        float4 wv = wr[lane + 32 * k];
        float o[4] = {g[k].x*sc*wv.x, g[k].y*sc*wv.y, g[k].z*sc*wv.z, g[k].w*sc*wv.w};
        __half hh[4], ll[4];
#pragma unroll
        for (int i = 0; i < 4; i++) fp16split(o[i], &hh[i], &ll[i]);
        *(uint2*)(oh + base + (lane + 32 * k) * 4) = *(uint2*)hh;
        *(uint2*)(ol + base + (lane + 32 * k) * 4) = *(uint2*)ll;
    }
}

// ---------------- 7b) Kalman finish -----------------------------------------
__global__ __launch_bounds__(64) void kalman_fin_k(
    const float* __restrict__ AP, const float* __restrict__ z_t,
    const float* __restrict__ kg_w1,
    const float* __restrict__ kp_w2, const float* __restrict__ kp_b2,
    const float* __restrict__ km_w1, const float* __restrict__ km_b1,
    const float* __restrict__ km_w2, const float* __restrict__ km_b2,
    const float* __restrict__ kg_w2, const float* __restrict__ kg_b2,
    const float* __restrict__ kW, float* __restrict__ out)
{
    __shared__ float redv[2], redg[2];
    int r = blockIdx.x;
    int tid = threadIdx.x;
    float z = z_t[r];
    float ap = AP[(size_t)r * 128 + tid];
    float ag = AP[(size_t)r * 128 + 64 + tid];
    ag = fmaf(z, kg_w1[HID * 64 + tid], ag);
    float vp = siluf(ap) * kp_w2[tid];
    float gp = siluf(ag) * kg_w2[tid];
    vp = warpSum(vp);
    gp = warpSum(gp);
    if ((tid & 31) == 0) { redv[tid >> 5] = vp; redg[tid >> 5] = gp; }
    __syncthreads();
    if (tid == 0) {
        float v_prior = softplusf(redv[0] + redv[1] + kp_b2[0]);
        float Kt = sigmoidf_(redg[0] + redg[1] + kg_b2[0]);
        float macc = km_b2[0];
#pragma unroll
        for (int k = 0; k < 32; k++)
            macc = fmaf(siluf(fmaf(z, km_w1[k], km_b1[k])), km_w2[k], macc);
        float m_t = softplusf(macc);
        float vpost = v_prior + Kt * (m_t - kW[0] * v_prior);
        vpost = fminf(fmaxf(vpost, 1e-6f), 10.f);
        out[r] = vpost;
    }
}

// ---------------- 8) per-batch softmax reductions ---------------------------
__global__ void reduce_k(float* __restrict__ out) {
    __shared__ float sa[256], sb[256];
    int b = blockIdx.x;
    int tid = threadIdx.x;
    const float* v = out + (size_t)b * TT;
    float v0 = v[tid], v1 = v[tid + 256];

    sa[tid] = fmaxf(v0, v1);
    sb[tid] = fminf(v0, v1);
    __syncthreads();
    for (int s = 128; s > 0; s >>= 1) {
        if (tid < s) {
            sa[tid] = fmaxf(sa[tid], sa[tid + s]);
            sb[tid] = fminf(sb[tid], sb[tid + s]);
        }
        __syncthreads();
    }
    float mx = sa[0], mn = sb[0];
    __syncthreads();

    float e0 = __expf(v0 - mx), e1 = __expf(v1 - mx);
    sa[tid] = e0 + e1;
    sb[tid] = e0 * v0 + e1 * v1;
    __syncthreads();
    for (int s = 128; s > 0; s >>= 1) {
        if (tid < s) { sa[tid] += sa[tid + s]; sb[tid] += sb[tid + s]; }
        __syncthreads();
    }
    float spden = sa[0], spnum = sb[0];
    __syncthreads();

    float f0 = __expf(mn - v0), f1 = __expf(mn - v1);
    sa[tid] = f0 + f1;
    sb[tid] = f0 * v0 + f1 * v1;
    __syncthreads();
    for (int s = 128; s > 0; s >>= 1) {
        if (tid < s) { sa[tid] += sa[tid + s]; sb[tid] += sb[tid + s]; }
        __syncthreads();
    }
    if (tid == 0) {
        out[ROWS + b] = spnum / spden;
        out[ROWS + BB + b] = sb[0] / sa[0];
    }
}

// ---------------- launcher ---------------------------------------------------
extern "C" void kernel_launch(void* const* d_in, const int* in_sizes, int n_in,
                              void* d_out, int out_size) {
    const float* tokens   = (const float*)d_in[0];
    const float* z_t      = (const float*)d_in[1];
    const float* norm_w   = (const float*)d_in[2];
    const float* in_w     = (const float*)d_in[3];
    const float* in_b     = (const float*)d_in[4];
    const float* conv_w   = (const float*)d_in[5];
    const float* conv_b   = (const float*)d_in[6];
    const float* dt_bias  = (const float*)d_in[7];
    const float* A_log    = (const float*)d_in[8];
    const float* Dp       = (const float*)d_in[9];
    const float* gnorm_w  = (const float*)d_in[10];
    const float* out_w    = (const float*)d_in[11];
    const float* out_b    = (const float*)d_in[12];
    const float* kp_w1    = (const float*)d_in[13];
    const float* kp_b1    = (const float*)d_in[14];
    const float* kp_w2    = (const float*)d_in[15];
    const float* kp_b2    = (const float*)d_in[16];
    const float* km_w1    = (const float*)d_in[17];
    const float* km_b1    = (const float*)d_in[18];
    const float* km_w2    = (const float*)d_in[19];
    const float* km_b2    = (const float*)d_in[20];
    const float* kg_w1    = (const float*)d_in[21];
    const float* kg_b1    = (const float*)d_in[22];
    const float* kg_w2    = (const float*)d_in[23];
    const float* kg_b2    = (const float*)d_in[24];
    const float* kW       = (const float*)d_in[25];
    const float* init_st  = (const float*)d_in[26];
    float* out = (float*)d_out;

    float *zx, *y, *bc, *hloc, *hstart, *cum, *ap, *kb;
    __half *xh, *xl, *yh, *yl, *ph, *pl, *wt1, *wt2, *wk;
    cudaGetSymbolAddress((void**)&zx,     g_zx);
    cudaGetSymbolAddress((void**)&y,      g_y);
    cudaGetSymbolAddress((void**)&bc,     g_bc);
    cudaGetSymbolAddress((void**)&hloc,   g_hloc);
    cudaGetSymbolAddress((void**)&hstart, g_hstart);
    cudaGetSymbolAddress((void**)&cum,    g_cum);
    cudaGetSymbolAddress((void**)&ap,     g_ap);
    cudaGetSymbolAddress((void**)&kb,     g_kb);
    cudaGetSymbolAddress((void**)&xh,     g_xh);
    cudaGetSymbolAddress((void**)&xl,     g_xl);
    cudaGetSymbolAddress((void**)&yh,     g_yh);
    cudaGetSymbolAddress((void**)&yl,     g_yl);
    cudaGetSymbolAddress((void**)&ph,     g_ph);
    cudaGetSymbolAddress((void**)&pl,     g_pl);
    cudaGetSymbolAddress((void**)&wt1,    g_wt1);
    cudaGetSymbolAddress((void**)&wt2,    g_wt2);
    cudaGetSymbolAddress((void**)&wk,     g_wk);

    cudaFuncSetAttribute(gemm_mma, cudaFuncAttributeMaxDynamicSharedMemorySize,
                         2 * GSM_STAGE);

    // weight prep (merged, single fp16) + t=0 Kalman rows
    prep_k<<<(W1SZ + W2SZ + WKSZ + 255) / 256, 256>>>(
        in_w, out_w, kp_w1, kg_w1, kp_b1, kg_b1, wt1, wt2, wk, kb);
    initrow_k<<<BB, 64>>>(init_st, ph, pl);

    // 1) rmsnorm -> fp16 split (warp per row)
    rmsnorm_cvt_k<<<ROWS / 4, 128>>>(tokens, norm_w, xh, xl);
    // 2) in-proj GEMM
    gemm_mma<<<dim3(NT1 / 128, ROWS / 128), 256, 2 * GSM_STAGE>>>(
        xh, xl, wt1, in_b, nullptr, zx, nullptr, nullptr, HID, PROJ);
    // 3+4) fused conv + chunked scan
    scanA_k<<<dim3(NHH, BB, NC), 64>>>(zx, conv_w, conv_b, dt_bias, A_log, Dp,
                                       y, hloc, cum, bc);
    scanB_k<<<dim3(NHH, BB), 64>>>(hloc, cum, hstart);
    scanC_k<<<dim3(NHH, BB, NC - 1), 64>>>(bc, hstart, cum, y);
    // 5) gate + rmsnorm (warp per row)
    gatenorm_cvt_k<<<ROWS / 4, 128>>>(y, zx, gnorm_w, yh, yl);
    // 6) out-proj GEMM + residual, fused shift+cvt into ph/pl
    gemm_mma<<<dim3(HID / 128, ROWS / 128), 256, 2 * GSM_STAGE>>>(
        yh, yl, wt2, out_b, tokens, nullptr, ph, pl, DI, HID);
    // 7) Kalman GEMM -> finish
    gemm_mma<<<dim3(1, ROWS / 128), 256, 2 * GSM_STAGE>>>(
        ph, pl, wk, kb, nullptr, ap, nullptr, nullptr, HID, 128);
    kalman_fin_k<<<ROWS, 64>>>(ap, z_t, kg_w1,
                               kp_w2, kp_b2, km_w1, km_b1, km_w2, km_b2,
                               kg_w2, kg_b2, kW, out);
    // 8) per-batch reductions
    reduce_k<<<BB, 256>>>(out);
}

// round 12
// speedup vs baseline: 1.1467x; 1.0028x over previous
#include <cuda_runtime.h>
#include <cuda_fp16.h>
#include <cstdint>

#define BB    64
#define TT    512
#define HID   256
#define DI    512
#define DS    16
#define NHH   8
#define HD    64
#define DCONV 4
#define CCH   544    // DI + 2*DS
#define PROJ  1064   // 2*DI + 2*DS + NH
#define ROWS  (BB*TT) // 32768
#define NC    16
#define LC    32     // TT/NC
#define NT1   1152   // PROJ padded to 9*128

// ---------------- scratch (device globals; no allocation allowed) ----------
__device__ __align__(16) float g_zx[ROWS * PROJ];
__device__ __align__(16) float g_y[ROWS * DI];
__device__ __align__(16) float g_bc[ROWS * 32];
__device__ __align__(16) float g_hloc[BB * NHH * NC * HD * DS];
__device__ __align__(16) float g_hstart[BB * NHH * NC * HD * DS];
__device__ __align__(16) float g_cum[BB * NHH * TT];
__device__ __align__(16) __half g_xh[ROWS * HID];
__device__ __align__(16) __half g_xl[ROWS * HID];
__device__ __align__(16) __half g_yh[ROWS * DI];
__device__ __align__(16) __half g_yl[ROWS * DI];
__device__ __align__(16) __half g_ph[ROWS * HID];
__device__ __align__(16) __half g_pl[ROWS * HID];
__device__ __align__(16) float g_ap[ROWS * 128];
__device__ __align__(16) __half g_wt1[NT1 * HID];
__device__ __align__(16) __half g_wt2[HID * DI];
__device__ __align__(16) __half g_wk[128 * HID];
__device__ __align__(16) float g_kb[128];

// ---------------- helpers ---------------------------------------------------
__device__ __forceinline__ float siluf(float x) { return x / (1.f + __expf(-x)); }
__device__ __forceinline__ float softplusf(float x) {
    return (x > 20.f) ? x : log1pf(__expf(x));
}
__device__ __forceinline__ float sigmoidf_(float x) { return 1.f / (1.f + __expf(-x)); }
__device__ __forceinline__ float warpSum(float v) {
#pragma unroll
    for (int o = 16; o; o >>= 1) v += __shfl_xor_sync(0xffffffffu, v, o);
    return v;
}
__device__ __forceinline__ void fp16split(float v, __half* h, __half* l) {
    __half hi = __float2half_rn(v);
    *h = hi;
    *l = __float2half_rn(v - __half2float(hi));
}
__device__ __forceinline__ uint32_t smem_u32(const void* p) {
    uint32_t a;
    asm("{ .reg .u64 t; cvta.to.shared.u64 t, %1; cvt.u32.u64 %0, t; }"
        : "=r"(a) : "l"(p));
    return a;
}
#define SWZ(b) ((b) ^ (((b) >> 3) & 0x70))

__device__ __forceinline__ void ldsm_x4(uint32_t* r, uint32_t addr) {
    asm volatile("ldmatrix.sync.aligned.m8n8.x4.shared.b16 {%0,%1,%2,%3}, [%4];"
                 : "=r"(r[0]), "=r"(r[1]), "=r"(r[2]), "=r"(r[3]) : "r"(addr));
}
__device__ __forceinline__ void mma16816(float* c, const uint32_t* a, const uint32_t* b) {
    asm volatile("mma.sync.aligned.m16n8k16.row.col.f32.f16.f16.f32 "
                 "{%0,%1,%2,%3}, {%4,%5,%6,%7}, {%8,%9}, {%0,%1,%2,%3};"
                 : "+f"(c[0]), "+f"(c[1]), "+f"(c[2]), "+f"(c[3])
                 : "r"(a[0]), "r"(a[1]), "r"(a[2]), "r"(a[3]), "r"(b[0]), "r"(b[1]));
}
#define CP16(sa, gp) \
    asm volatile("cp.async.cg.shared.global [%0], [%1], 16;" :: "r"(sa), "l"(gp))
#define CP_COMMIT() asm volatile("cp.async.commit_group;" ::: "memory")
#define CP_WAIT1() asm volatile("cp.async.wait_group 1;" ::: "memory")
#define CP_WAIT0() asm volatile("cp.async.wait_group 0;" ::: "memory")

// ---------------- fp16 A-split GEMM via mma.sync, cp.async 2-stage ----------
// C[M,N] = A@W^T + bias (+res). Ah/Al: [M,K] fp16 row-major (hi/lo split).
// B: [NT,K] fp16 row-major (W transposed, zero-padded). K%64==0.
// CTA tile 128x128, BK=64, 8 warps (2x4), warp tile 64x32, 2 MMA passes.
// If oh != nullptr (requires N==HID): also write fp16 hi/lo of result to
// row m+1 (skip rows where (m+1)%TT==0).
#define TILE_B 16384
#define GSM_STAGE (3 * TILE_B)
__global__ __launch_bounds__(256, 2) void gemm_mma(
    const __half* __restrict__ Ah, const __half* __restrict__ Al,
    const __half* __restrict__ B,
    const float* __restrict__ bias, const float* __restrict__ res,
    float* __restrict__ C,
    __half* __restrict__ oh, __half* __restrict__ ol,
    int K, int N)
{
    extern __shared__ __align__(16) uint8_t dsm[];
    uint32_t sbase = smem_u32(dsm);

    int tid = threadIdx.x;
    int wid = tid >> 5, lane = tid & 31;
    int bm = blockIdx.y * 128, bn = blockIdx.x * 128;
    int wm = (wid >> 2) * 64;
    int wn = (wid & 3) * 32;

    // loader: row = tid/2, element half = (tid&1)*32; 4 x 16B chunks per tile
    int lrow = tid >> 1;
    int lhe  = (tid & 1) * 32;
    const __half* pAh = Ah + (size_t)(bm + lrow) * K + lhe;
    const __half* pAl = Al + (size_t)(bm + lrow) * K + lhe;
    const __half* pB  = B  + (size_t)(bn + lrow) * K + lhe;
    uint32_t so[4];
#pragma unroll
    for (int i = 0; i < 4; i++)
        so[i] = SWZ((uint32_t)(lrow * 128 + (tid & 1) * 64 + i * 16));

    float acc[4][4][4];
#pragma unroll
    for (int i = 0; i < 4; i++)
#pragma unroll
        for (int j = 0; j < 4; j++)
#pragma unroll
            for (int q = 0; q < 4; q++) acc[i][j][q] = 0.f;

    int aRow = lane & 15;
    int aKb  = (lane >> 4) << 4;
    int bRow = ((lane >> 4) << 3) + (lane & 7);
    int bKb  = ((lane >> 3) & 1) << 4;

    const int KC = K >> 6;

    // prologue: stage 0
    {
        uint32_t st = sbase;
#pragma unroll
        for (int i = 0; i < 4; i++) {
            CP16(st + so[i],              pAh + i * 8);
            CP16(st + TILE_B + so[i],     pAl + i * 8);
            CP16(st + 2 * TILE_B + so[i], pB  + i * 8);
        }
        CP_COMMIT();
    }

    for (int c = 0; c < KC; c++) {
        if (c + 1 < KC) {
            int e = (c + 1) * 64;
            uint32_t st = sbase + ((c + 1) & 1) * GSM_STAGE;
#pragma unroll
            for (int i = 0; i < 4; i++) {
                CP16(st + so[i],              pAh + e + i * 8);
                CP16(st + TILE_B + so[i],     pAl + e + i * 8);
                CP16(st + 2 * TILE_B + so[i], pB  + e + i * 8);
            }
            CP_COMMIT();
            CP_WAIT1();
        } else {
            CP_WAIT0();
        }
        __syncthreads();

        uint32_t st = sbase + (c & 1) * GSM_STAGE;
        uint32_t sAH = st, sAL = st + TILE_B, sB = st + 2 * TILE_B;

#pragma unroll
        for (int ks = 0; ks < 4; ks++) {
            int kb2 = ks * 32;    // byte offset of k16 slice in 128B row
            uint32_t ah[4][4], al[4][4], bh[2][4];
#pragma unroll
            for (int mt = 0; mt < 4; mt++) {
                uint32_t off = SWZ((uint32_t)(wm + mt * 16 + aRow) * 128 + kb2 + aKb);
                ldsm_x4(ah[mt], sAH + off);
                ldsm_x4(al[mt], sAL + off);
            }
#pragma unroll
            for (int np = 0; np < 2; np++) {
                uint32_t off = SWZ((uint32_t)(wn + np * 16 + bRow) * 128 + kb2 + bKb);
                ldsm_x4(bh[np], sB + off);
            }
#pragma unroll
            for (int mt = 0; mt < 4; mt++) {
#pragma unroll
                for (int nt = 0; nt < 4; nt++) {
                    const uint32_t* pbh = &bh[nt >> 1][(nt & 1) * 2];
                    mma16816(acc[mt][nt], ah[mt], pbh);
                    mma16816(acc[mt][nt], al[mt], pbh);
                }
            }
        }
        __syncthreads();
    }

    // epilogue
    int mrow0 = bm + wm + (lane >> 2);
    int ncol0 = bn + wn + (lane & 3) * 2;
#pragma unroll
    for (int mt = 0; mt < 4; mt++) {
#pragma unroll
        for (int half = 0; half < 2; half++) {
            int m = mrow0 + mt * 16 + half * 8;
            float* crow = C ? C + (size_t)m * N : nullptr;
            const float* rrow = res ? res + (size_t)m * N : nullptr;
            int mp = m + 1;
            bool doshift = (oh != nullptr) && ((mp & (TT - 1)) != 0);
#pragma unroll
            for (int nt = 0; nt < 4; nt++) {
                int n = ncol0 + nt * 8;
                if (n + 1 < N) {
                    float v0 = acc[mt][nt][half * 2 + 0] + bias[n];
                    float v1 = acc[mt][nt][half * 2 + 1] + bias[n + 1];
                    if (res) { v0 += rrow[n]; v1 += rrow[n + 1]; }
                    if (crow) { crow[n] = v0; crow[n + 1] = v1; }
                    if (doshift) {
                        __half h0, l0, h1, l1;
                        fp16split(v0, &h0, &l0);
                        fp16split(v1, &h1, &l1);
                        __half2 hp, lp;
                        hp.x = h0; hp.y = h1; lp.x = l0; lp.y = l1;
                        *(__half2*)(oh + (size_t)mp * N + n) = hp;
                        *(__half2*)(ol + (size_t)mp * N + n) = lp;
                    }
                } else if (n < N) {
                    float v0 = acc[mt][nt][half * 2 + 0] + bias[n];
                    if (res) v0 += rrow[n];
                    if (crow) crow[n] = v0;
                }
            }
        }
    }
}

// ---------------- merged weight prep ----------------------------------------
#define W1SZ (NT1 * HID)
#define W2SZ (HID * DI)
#define WKSZ (128 * HID)
__global__ void prep_k(const float* __restrict__ in_w, const float* __restrict__ out_w,
                       const float* __restrict__ kp_w1, const float* __restrict__ kg_w1,
                       const float* __restrict__ kp_b1, const float* __restrict__ kg_b1,
                       __half* __restrict__ w1, __half* __restrict__ w2,
                       __half* __restrict__ wk, float* __restrict__ kb) {
    int idx = blockIdx.x * blockDim.x + threadIdx.x;
    if (idx < W1SZ) {
        int n = idx / HID, k = idx % HID;
        float v = (n < PROJ) ? in_w[(size_t)k * PROJ + n] : 0.f;
        w1[idx] = __float2half_rn(v);
    } else if (idx < W1SZ + W2SZ) {
        int i = idx - W1SZ;
        int n = i / DI, k = i % DI;
        w2[i] = __float2half_rn(out_w[(size_t)k * HID + n]);
    } else if (idx < W1SZ + W2SZ + WKSZ) {
        int i = idx - W1SZ - W2SZ;
        int n = i / HID, k = i % HID;
        float v = (n < 64) ? kp_w1[(size_t)k * 64 + n] : kg_w1[(size_t)k * 64 + (n - 64)];
        wk[i] = __float2half_rn(v);
        if (i < 128) kb[i] = (i < 64) ? kp_b1[i] : kg_b1[i - 64];
    }
}

__global__ void initrow_k(const float* __restrict__ init_state,
                          __half* __restrict__ oh, __half* __restrict__ ol) {
    int b = blockIdx.x;
    int tid = threadIdx.x;
    float4 v = ((const float4*)init_state)[tid];
    float o[4] = {v.x, v.y, v.z, v.w};
    __half hh[4], ll[4];
#pragma unroll
    for (int i = 0; i < 4; i++) fp16split(o[i], &hh[i], &ll[i]);
    size_t base = (size_t)(b * TT) * HID + tid * 4;
    *(uint2*)(oh + base) = *(uint2*)hh;
    *(uint2*)(ol + base) = *(uint2*)ll;
}

// ---------------- 1) rmsnorm -> fp16 hi/lo (warp per row) -------------------
__global__ void rmsnorm_cvt_k(const float* __restrict__ x, const float* __restrict__ w,
                              __half* __restrict__ oh, __half* __restrict__ ol) {
    int r = blockIdx.x * 4 + (threadIdx.x >> 5);
    int lane = threadIdx.x & 31;
    const float4* xr = (const float4*)(x + (size_t)r * HID);
    float4 v0 = xr[lane], v1 = xr[lane + 32];
    float ss = v0.x*v0.x + v0.y*v0.y + v0.z*v0.z + v0.w*v0.w
             + v1.x*v1.x + v1.y*v1.y + v1.z*v1.z + v1.w*v1.w;
    ss = warpSum(ss);
    float sc = rsqrtf(ss / HID + 1e-5f);
    const float4* wr = (const float4*)w;
    float4 w0 = wr[lane], w1 = wr[lane + 32];
    float o0[4] = {v0.x*sc*w0.x, v0.y*sc*w0.y, v0.z*sc*w0.z, v0.w*sc*w0.w};
    float o1[4] = {v1.x*sc*w1.x, v1.y*sc*w1.y, v1.z*sc*w1.z, v1.w*sc*w1.w};
    __half h0[4], l0[4], h1[4], l1[4];
#pragma unroll
    for (int i = 0; i < 4; i++) { fp16split(o0[i], &h0[i], &l0[i]); fp16split(o1[i], &h1[i], &l1[i]); }
    size_t base = (size_t)r * HID;
    *(uint2*)(oh + base + lane * 4) = *(uint2*)h0;
    *(uint2*)(oh + base + (lane + 32) * 4) = *(uint2*)h1;
    *(uint2*)(ol + base + lane * 4) = *(uint2*)l0;
    *(uint2*)(ol + base + (lane + 32) * 4) = *(uint2*)l1;
}

// ---------------- 4a) fused conv+silu + chunked scan local pass -------------
__global__ __launch_bounds__(64) void scanA_k(
    const float* __restrict__ zx, const float* __restrict__ cw,
    const float* __restrict__ cbv,
    const float* __restrict__ dt_bias, const float* __restrict__ A_log,
    const float* __restrict__ Dp, float* __restrict__ y,
    float* __restrict__ hloc, float* __restrict__ cum, float* __restrict__ bc)
{
    __shared__ float sBC[LC][32];
    __shared__ float sdt[LC];
    int h = blockIdx.x, b = blockIdx.y, c = blockIdx.z;
    int d = threadIdx.x;
    int t0 = c * LC;
    size_t rowbase = (size_t)(b * TT + t0);

    for (int i = d; i < LC * 32; i += 64) {
        int t = i >> 5, j = i & 31;
        int ch = 512 + j;
        float acc = cbv[ch];
#pragma unroll
        for (int k = 0; k < DCONV; k++) {
            int tt = t0 + t - (DCONV - 1) + k;
            if (tt >= 0)
                acc = fmaf(zx[((size_t)(b * TT + tt)) * PROJ + DI + ch],
                           cw[k * CCH + ch], acc);
        }
        float v = siluf(acc);
        sBC[t][j] = v;
        if (h == 0) bc[(rowbase + t) * 32 + j] = v;
    }
    float dtb = dt_bias[h];
    for (int i = d; i < LC; i += 64)
        sdt[i] = softplusf(zx[(rowbase + i) * PROJ + 2 * DI + 2 * DS + h] + dtb);
    __syncthreads();

    int ch = h * HD + d;
    float w0 = cw[0 * CCH + ch], w1 = cw[1 * CCH + ch];
    float w2 = cw[2 * CCH + ch], w3 = cw[3 * CCH + ch];
    float cb0 = cbv[ch];
    const float* xcol = zx + DI + ch;
    float r0 = 0.f, r1 = 0.f, r2 = 0.f;
    {
        int tb = t0 - 3;
        if (tb >= 0)     r0 = xcol[(size_t)(b * TT + tb) * PROJ];
        if (tb + 1 >= 0) r1 = xcol[(size_t)(b * TT + tb + 1) * PROJ];
        if (tb + 2 >= 0) r2 = xcol[(size_t)(b * TT + tb + 2) * PROJ];
    }

    float A = -__expf(A_log[h]);
    float Dh = Dp[h];
    float hr[DS];
#pragma unroll
    for (int s = 0; s < DS; s++) hr[s] = 0.f;
    float cm = 1.f;

    float* yp = y + rowbase * DI + h * HD + d;
    float* cmp = cum + ((size_t)(b * NHH + h)) * TT + t0;

    for (int t = 0; t < LC; t++) {
        float raw = xcol[(rowbase + t) * PROJ];
        float x = siluf(fmaf(raw, w3, fmaf(r2, w2, fmaf(r1, w1, fmaf(r0, w0, cb0)))));
        r0 = r1; r1 = r2; r2 = raw;

        float dtsp = sdt[t];
        float dA = __expf(dtsp * A);
        cm *= dA;
        if (d == 0) cmp[t] = cm;
        float dtx = dtsp * x;
        float yvp[4] = {Dh * x, 0.f, 0.f, 0.f};
        float Bv[16], Cv[16];
        *(float4*)&Bv[0]  = *(const float4*)&sBC[t][0];
        *(float4*)&Bv[4]  = *(const float4*)&sBC[t][4];
        *(float4*)&Bv[8]  = *(const float4*)&sBC[t][8];
        *(float4*)&Bv[12] = *(const float4*)&sBC[t][12];
        *(float4*)&Cv[0]  = *(const float4*)&sBC[t][16];
        *(float4*)&Cv[4]  = *(const float4*)&sBC[t][20];
        *(float4*)&Cv[8]  = *(const float4*)&sBC[t][24];
        *(float4*)&Cv[12] = *(const float4*)&sBC[t][28];
#pragma unroll
        for (int s = 0; s < DS; s++) {
            hr[s] = fmaf(hr[s], dA, dtx * Bv[s]);
            yvp[s & 3] = fmaf(hr[s], Cv[s], yvp[s & 3]);
        }
        yp[(size_t)t * DI] = (yvp[0] + yvp[1]) + (yvp[2] + yvp[3]);
    }

    float* hl = hloc + ((size_t)((b * NHH + h) * NC + c)) * (DS * HD);
#pragma unroll
    for (int s = 0; s < DS; s++) hl[s * HD + d] = hr[s];
}

// ---------------- 4b) chain chunk states ------------------------------------
__global__ __launch_bounds__(64) void scanB_k(const float* __restrict__ hloc,
                                              const float* __restrict__ cum,
                                              float* __restrict__ hstart)
{
    int h = blockIdx.x, b = blockIdx.y, d = threadIdx.x;
    size_t base = (size_t)(b * NHH + h);
    float hs[DS];
#pragma unroll
    for (int s = 0; s < DS; s++) hs[s] = 0.f;
    for (int c = 0; c < NC; c++) {
        float* hsp = hstart + (base * NC + c) * (DS * HD);
#pragma unroll
        for (int s = 0; s < DS; s++) hsp[s * HD + d] = hs[s];
        float P = cum[base * TT + c * LC + LC - 1];
        const float* hl = hloc + (base * NC + c) * (DS * HD);
#pragma unroll
        for (int s = 0; s < DS; s++) hs[s] = fmaf(hs[s], P, hl[s * HD + d]);
    }
}

// ---------------- 4c) correction --------------------------------------------
__global__ __launch_bounds__(64) void scanC_k(const float* __restrict__ bc,
                                              const float* __restrict__ hstart,
                                              const float* __restrict__ cum,
                                              float* __restrict__ y)
{
    __shared__ float sC[LC][16];
    __shared__ float scm[LC];
    int h = blockIdx.x, b = blockIdx.y, c = blockIdx.z + 1;
    int d = threadIdx.x;
    int t0 = c * LC;
    size_t rowbase = (size_t)(b * TT + t0);
    size_t base = (size_t)(b * NHH + h);

    for (int i = d; i < LC * 16; i += 64) {
        int t = i >> 4, j = i & 15;
        sC[t][j] = bc[(rowbase + t) * 32 + 16 + j];
    }
    for (int i = d; i < LC; i += 64) scm[i] = cum[base * TT + t0 + i];

    float hs[DS];
    const float* hsp = hstart + (base * NC + c) * (DS * HD);
#pragma unroll
    for (int s = 0; s < DS; s++) hs[s] = hsp[s * HD + d];
    __syncthreads();

    float* yp = y + rowbase * DI + h * HD + d;
    for (int t = 0; t < LC; t++) {
        float Cv[16];
        *(float4*)&Cv[0]  = *(const float4*)&sC[t][0];
        *(float4*)&Cv[4]  = *(const float4*)&sC[t][4];
        *(float4*)&Cv[8]  = *(const float4*)&sC[t][8];
        *(float4*)&Cv[12] = *(const float4*)&sC[t][12];
        float acc = 0.f;
#pragma unroll
        for (int s = 0; s < DS; s++) acc = fmaf(hs[s], Cv[s], acc);
        yp[(size_t)t * DI] += acc * scm[t];
    }
}

// ---------------- 5) gate + rmsnorm -> fp16 (warp per row) ------------------
__global__ void gatenorm_cvt_k(const float* __restrict__ y, const float* __restrict__ zx,
                               const float* __restrict__ gw,
                               __half* __restrict__ oh, __half* __restrict__ ol) {
    int r = blockIdx.x * 4 + (threadIdx.x >> 5);
    int lane = threadIdx.x & 31;
    const float4* yr = (const float4*)(y + (size_t)r * DI);
    const float4* zr = (const float4*)(zx + (size_t)r * PROJ);
    float4 g[4];
    float ss = 0.f;
#pragma unroll
    for (int k = 0; k < 4; k++) {
        float4 yv = yr[lane + 32 * k];
        float4 zv = zr[lane + 32 * k];
        g[k].x = yv.x * siluf(zv.x); g[k].y = yv.y * siluf(zv.y);
        g[k].z = yv.z * siluf(zv.z); g[k].w = yv.w * siluf(zv.w);
        ss += g[k].x*g[k].x + g[k].y*g[k].y + g[k].z*g[k].z + g[k].w*g[k].w;
    }
    ss = warpSum(ss);
    float sc = rsqrtf(ss / DI + 1e-5f);
    const float4* wr = (const float4*)gw;
    size_t base = (size_t)r * DI;
#pragma unroll
    for (int k = 0; k < 4; k++) {
        float4 wv = wr[lane + 32 * k];
        float o[4] = {g[k].x*sc*wv.x, g[k].y*sc*wv.y, g[k].z*sc*wv.z, g[k].w*sc*wv.w};
        __half hh[4], ll[4];
#pragma unroll
        for (int i = 0; i < 4; i++) fp16split(o[i], &hh[i], &ll[i]);
        *(uint2*)(oh + base + (lane + 32 * k) * 4) = *(uint2*)hh;
        *(uint2*)(ol + base + (lane + 32 * k) * 4) = *(uint2*)ll;
    }
}

// ---------------- 7b) Kalman finish -----------------------------------------
__global__ __launch_bounds__(64) void kalman_fin_k(
    const float* __restrict__ AP, const float* __restrict__ z_t,
    const float* __restrict__ kg_w1,
    const float* __restrict__ kp_w2, const float* __restrict__ kp_b2,
    const float* __restrict__ km_w1, const float* __restrict__ km_b1,
    const float* __restrict__ km_w2, const float* __restrict__ km_b2,
    const float* __restrict__ kg_w2, const float* __restrict__ kg_b2,
    const float* __restrict__ kW, float* __restrict__ out)
{
    __shared__ float redv[2], redg[2];
    int r = blockIdx.x;
    int tid = threadIdx.x;
    float z = z_t[r];
    float ap = AP[(size_t)r * 128 + tid];
    float ag = AP[(size_t)r * 128 + 64 + tid];
    ag = fmaf(z, kg_w1[HID * 64 + tid], ag);
    float vp = siluf(ap) * kp_w2[tid];
    float gp = siluf(ag) * kg_w2[tid];
    vp = warpSum(vp);
    gp = warpSum(gp);
    if ((tid & 31) == 0) { redv[tid >> 5] = vp; redg[tid >> 5] = gp; }
    __syncthreads();
    if (tid == 0) {
        float v_prior = softplusf(redv[0] + redv[1] + kp_b2[0]);
        float Kt = sigmoidf_(redg[0] + redg[1] + kg_b2[0]);
        float macc = km_b2[0];
#pragma unroll
        for (int k = 0; k < 32; k++)
            macc = fmaf(siluf(fmaf(z, km_w1[k], km_b1[k])), km_w2[k], macc);
        float m_t = softplusf(macc);
        float vpost = v_prior + Kt * (m_t - kW[0] * v_prior);
        vpost = fminf(fmaxf(vpost, 1e-6f), 10.f);
        out[r] = vpost;
    }
}

// ---------------- 8) per-batch softmax reductions ---------------------------
__global__ void reduce_k(float* __restrict__ out) {
    __shared__ float sa[256], sb[256];
    int b = blockIdx.x;
    int tid = threadIdx.x;
    const float* v = out + (size_t)b * TT;
    float v0 = v[tid], v1 = v[tid + 256];

    sa[tid] = fmaxf(v0, v1);
    sb[tid] = fminf(v0, v1);
    __syncthreads();
    for (int s = 128; s > 0; s >>= 1) {
        if (tid < s) {
            sa[tid] = fmaxf(sa[tid], sa[tid + s]);
            sb[tid] = fminf(sb[tid], sb[tid + s]);
        }
        __syncthreads();
    }
    float mx = sa[0], mn = sb[0];
    __syncthreads();

    float e0 = __expf(v0 - mx), e1 = __expf(v1 - mx);
    sa[tid] = e0 + e1;
    sb[tid] = e0 * v0 + e1 * v1;
    __syncthreads();
    for (int s = 128; s > 0; s >>= 1) {
        if (tid < s) { sa[tid] += sa[tid + s]; sb[tid] += sb[tid + s]; }
        __syncthreads();
    }
    float spden = sa[0], spnum = sb[0];
    __syncthreads();

    float f0 = __expf(mn - v0), f1 = __expf(mn - v1);
    sa[tid] = f0 + f1;
    sb[tid] = f0 * v0 + f1 * v1;
    __syncthreads();
    for (int s = 128; s > 0; s >>= 1) {
        if (tid < s) { sa[tid] += sa[tid + s]; sb[tid] += sb[tid + s]; }
        __syncthreads();
    }
    if (tid == 0) {
        out[ROWS + b] = spnum / spden;
        out[ROWS + BB + b] = sb[0] / sa[0];
    }
}

// ---------------- launcher ---------------------------------------------------
extern "C" void kernel_launch(void* const* d_in, const int* in_sizes, int n_in,
                              void* d_out, int out_size) {
    const float* tokens   = (const float*)d_in[0];
    const float* z_t      = (const float*)d_in[1];
    const float* norm_w   = (const float*)d_in[2];
    const float* in_w     = (const float*)d_in[3];
    const float* in_b     = (const float*)d_in[4];
    const float* conv_w   = (const float*)d_in[5];
    const float* conv_b   = (const float*)d_in[6];
    const float* dt_bias  = (const float*)d_in[7];
    const float* A_log    = (const float*)d_in[8];
    const float* Dp       = (const float*)d_in[9];
    const float* gnorm_w  = (const float*)d_in[10];
    const float* out_w    = (const float*)d_in[11];
    const float* out_b    = (const float*)d_in[12];
    const float* kp_w1    = (const float*)d_in[13];
    const float* kp_b1    = (const float*)d_in[14];
    const float* kp_w2    = (const float*)d_in[15];
    const float* kp_b2    = (const float*)d_in[16];
    const float* km_w1    = (const float*)d_in[17];
    const float* km_b1    = (const float*)d_in[18];
    const float* km_w2    = (const float*)d_in[19];
    const float* km_b2    = (const float*)d_in[20];
    const float* kg_w1    = (const float*)d_in[21];
    const float* kg_b1    = (const float*)d_in[22];
    const float* kg_w2    = (const float*)d_in[23];
    const float* kg_b2    = (const float*)d_in[24];
    const float* kW       = (const float*)d_in[25];
    const float* init_st  = (const float*)d_in[26];
    float* out = (float*)d_out;

    float *zx, *y, *bc, *hloc, *hstart, *cum, *ap, *kb;
    __half *xh, *xl, *yh, *yl, *ph, *pl, *wt1, *wt2, *wk;
    cudaGetSymbolAddress((void**)&zx,     g_zx);
    cudaGetSymbolAddress((void**)&y,      g_y);
    cudaGetSymbolAddress((void**)&bc,     g_bc);
    cudaGetSymbolAddress((void**)&hloc,   g_hloc);
    cudaGetSymbolAddress((void**)&hstart, g_hstart);
    cudaGetSymbolAddress((void**)&cum,    g_cum);
    cudaGetSymbolAddress((void**)&ap,     g_ap);
    cudaGetSymbolAddress((void**)&kb,     g_kb);
    cudaGetSymbolAddress((void**)&xh,     g_xh);
    cudaGetSymbolAddress((void**)&xl,     g_xl);
    cudaGetSymbolAddress((void**)&yh,     g_yh);
    cudaGetSymbolAddress((void**)&yl,     g_yl);
    cudaGetSymbolAddress((void**)&ph,     g_ph);
    cudaGetSymbolAddress((void**)&pl,     g_pl);
    cudaGetSymbolAddress((void**)&wt1,    g_wt1);
    cudaGetSymbolAddress((void**)&wt2,    g_wt2);
    cudaGetSymbolAddress((void**)&wk,     g_wk);

    cudaFuncSetAttribute(gemm_mma, cudaFuncAttributeMaxDynamicSharedMemorySize,
                         2 * GSM_STAGE);

    // weight prep (merged, single fp16) + t=0 Kalman rows
    prep_k<<<(W1SZ + W2SZ + WKSZ + 255) / 256, 256>>>(
        in_w, out_w, kp_w1, kg_w1, kp_b1, kg_b1, wt1, wt2, wk, kb);
    initrow_k<<<BB, 64>>>(init_st, ph, pl);

    // 1) rmsnorm -> fp16 split (warp per row)
    rmsnorm_cvt_k<<<ROWS / 4, 128>>>(tokens, norm_w, xh, xl);
    // 2) in-proj GEMM
    gemm_mma<<<dim3(NT1 / 128, ROWS / 128), 256, 2 * GSM_STAGE>>>(
        xh, xl, wt1, in_b, nullptr, zx, nullptr, nullptr, HID, PROJ);
    // 3+4) fused conv + chunked scan
    scanA_k<<<dim3(NHH, BB, NC), 64>>>(zx, conv_w, conv_b, dt_bias, A_log, Dp,
                                       y, hloc, cum, bc);
    scanB_k<<<dim3(NHH, BB), 64>>>(hloc, cum, hstart);
    scanC_k<<<dim3(NHH, BB, NC - 1), 64>>>(bc, hstart, cum, y);
    // 5) gate + rmsnorm (warp per row)
    gatenorm_cvt_k<<<ROWS / 4, 128>>>(y, zx, gnorm_w, yh, yl);
    // 6) out-proj GEMM + residual, fused shift+cvt into ph/pl
    gemm_mma<<<dim3(HID / 128, ROWS / 128), 256, 2 * GSM_STAGE>>>(
        yh, yl, wt2, out_b, tokens, nullptr, ph, pl, DI, HID);
    // 7) Kalman GEMM -> finish
    gemm_mma<<<dim3(1, ROWS / 128), 256, 2 * GSM_STAGE>>>(
        ph, pl, wk, kb, nullptr, ap, nullptr, nullptr, HID, 128);
    kalman_fin_k<<<ROWS, 64>>>(ap, z_t, kg_w1,
                               kp_w2, kp_b2, km_w1, km_b1, km_w2, km_b2,
                               kg_w2, kg_b2, kW, out);
    // 8) per-batch reductions
    reduce_k<<<BB, 256>>>(out);
}

// round 13
// speedup vs baseline: 1.3592x; 1.1853x over previous
#include <cuda_runtime.h>
#include <cuda_fp16.h>
#include <cstdint>

#define BB    64
#define TT    512
#define HID   256
#define DI    512
#define DS    16
#define NHH   8
#define HD    64
#define DCONV 4
#define CCH   544    // DI + 2*DS
#define PROJ  1064   // 2*DI + 2*DS + NH
#define ROWS  (BB*TT) // 32768
#define NC    16
#define LC    32     // TT/NC
#define NT1   1152   // PROJ padded to 9*128

// ---------------- scratch (device globals; no allocation allowed) ----------
__device__ __align__(16) float g_zx[ROWS * PROJ];
__device__ __align__(16) float g_y[ROWS * DI];
__device__ __align__(16) float g_bc[ROWS * 32];
__device__ __align__(16) float g_hloc[BB * NHH * NC * HD * DS];
__device__ __align__(16) float g_hstart[BB * NHH * NC * HD * DS];
__device__ __align__(16) float g_cum[BB * NHH * TT];
__device__ __align__(16) __half g_xh[ROWS * HID];
__device__ __align__(16) __half g_yh[ROWS * DI];
__device__ __align__(16) __half g_ph[ROWS * HID];
__device__ __align__(16) float g_ap[ROWS * 128];
__device__ __align__(16) __half g_wt1[NT1 * HID];
__device__ __align__(16) __half g_wt2[HID * DI];
__device__ __align__(16) __half g_wk[128 * HID];
__device__ __align__(16) float g_kb[128];

// ---------------- helpers ---------------------------------------------------
__device__ __forceinline__ float siluf(float x) { return x / (1.f + __expf(-x)); }
__device__ __forceinline__ float softplusf(float x) {
    return (x > 20.f) ? x : log1pf(__expf(x));
}
__device__ __forceinline__ float sigmoidf_(float x) { return 1.f / (1.f + __expf(-x)); }
__device__ __forceinline__ float warpSum(float v) {
#pragma unroll
    for (int o = 16; o; o >>= 1) v += __shfl_xor_sync(0xffffffffu, v, o);
    return v;
}
__device__ __forceinline__ uint32_t smem_u32(const void* p) {
    uint32_t a;
    asm("{ .reg .u64 t; cvta.to.shared.u64 t, %1; cvt.u32.u64 %0, t; }"
        : "=r"(a) : "l"(p));
    return a;
}
#define SWZ(b) ((b) ^ (((b) >> 3) & 0x70))

__device__ __forceinline__ void ldsm_x4(uint32_t* r, uint32_t addr) {
    asm volatile("ldmatrix.sync.aligned.m8n8.x4.shared.b16 {%0,%1,%2,%3}, [%4];"
                 : "=r"(r[0]), "=r"(r[1]), "=r"(r[2]), "=r"(r[3]) : "r"(addr));
}
__device__ __forceinline__ void mma16816(float* c, const uint32_t* a, const uint32_t* b) {
    asm volatile("mma.sync.aligned.m16n8k16.row.col.f32.f16.f16.f32 "
                 "{%0,%1,%2,%3}, {%4,%5,%6,%7}, {%8,%9}, {%0,%1,%2,%3};"
                 : "+f"(c[0]), "+f"(c[1]), "+f"(c[2]), "+f"(c[3])
                 : "r"(a[0]), "r"(a[1]), "r"(a[2]), "r"(a[3]), "r"(b[0]), "r"(b[1]));
}
#define CP16(sa, gp) \
    asm volatile("cp.async.cg.shared.global [%0], [%1], 16;" :: "r"(sa), "l"(gp))
#define CP_COMMIT() asm volatile("cp.async.commit_group;" ::: "memory")
#define CP_WAIT1() asm volatile("cp.async.wait_group 1;" ::: "memory")
#define CP_WAIT0() asm volatile("cp.async.wait_group 0;" ::: "memory")

// ---------------- fp16 GEMM via mma.sync, cp.async 2-stage ------------------
// C[M,N] = A@W^T + bias (+res). A: [M,K] fp16 row-major.
// B: [NT,K] fp16 row-major (W transposed, zero-padded). K%64==0.
// CTA tile 128x128, BK=64, 8 warps (2x4), warp tile 64x32, 1 MMA pass.
// If oh != nullptr (requires N==HID): also write fp16 of result to row m+1
// (skip rows where (m+1)%TT==0).
#define TILE_B 16384
#define GSM_STAGE (2 * TILE_B)
__global__ __launch_bounds__(256, 2) void gemm_mma(
    const __half* __restrict__ A, const __half* __restrict__ B,
    const float* __restrict__ bias, const float* __restrict__ res,
    float* __restrict__ C, __half* __restrict__ oh,
    int K, int N)
{
    extern __shared__ __align__(16) uint8_t dsm[];
    uint32_t sbase = smem_u32(dsm);

    int tid = threadIdx.x;
    int wid = tid >> 5, lane = tid & 31;
    int bm = blockIdx.y * 128, bn = blockIdx.x * 128;
    int wm = (wid >> 2) * 64;
    int wn = (wid & 3) * 32;

    // loader: row = tid/2, element half = (tid&1)*32; 4 x 16B chunks per tile
    int lrow = tid >> 1;
    int lhe  = (tid & 1) * 32;
    const __half* pA = A + (size_t)(bm + lrow) * K + lhe;
    const __half* pB = B + (size_t)(bn + lrow) * K + lhe;
    uint32_t so[4];
#pragma unroll
    for (int i = 0; i < 4; i++)
        so[i] = SWZ((uint32_t)(lrow * 128 + (tid & 1) * 64 + i * 16));

    float acc[4][4][4];
#pragma unroll
    for (int i = 0; i < 4; i++)
#pragma unroll
        for (int j = 0; j < 4; j++)
#pragma unroll
            for (int q = 0; q < 4; q++) acc[i][j][q] = 0.f;

    int aRow = lane & 15;
    int aKb  = (lane >> 4) << 4;
    int bRow = ((lane >> 4) << 3) + (lane & 7);
    int bKb  = ((lane >> 3) & 1) << 4;

    const int KC = K >> 6;

    // prologue: stage 0
    {
        uint32_t st = sbase;
#pragma unroll
        for (int i = 0; i < 4; i++) {
            CP16(st + so[i],          pA + i * 8);
            CP16(st + TILE_B + so[i], pB + i * 8);
        }
        CP_COMMIT();
    }

    for (int c = 0; c < KC; c++) {
        if (c + 1 < KC) {
            int e = (c + 1) * 64;
            uint32_t st = sbase + ((c + 1) & 1) * GSM_STAGE;
#pragma unroll
            for (int i = 0; i < 4; i++) {
                CP16(st + so[i],          pA + e + i * 8);
                CP16(st + TILE_B + so[i], pB + e + i * 8);
            }
            CP_COMMIT();
            CP_WAIT1();
        } else {
            CP_WAIT0();
        }
        __syncthreads();

        uint32_t st = sbase + (c & 1) * GSM_STAGE;
        uint32_t sA = st, sB = st + TILE_B;

#pragma unroll
        for (int ks = 0; ks < 4; ks++) {
            int kb2 = ks * 32;    // byte offset of k16 slice in 128B row
            uint32_t ah[4][4], bh[2][4];
#pragma unroll
            for (int mt = 0; mt < 4; mt++) {
                uint32_t off = SWZ((uint32_t)(wm + mt * 16 + aRow) * 128 + kb2 + aKb);
                ldsm_x4(ah[mt], sA + off);
            }
#pragma unroll
            for (int np = 0; np < 2; np++) {
                uint32_t off = SWZ((uint32_t)(wn + np * 16 + bRow) * 128 + kb2 + bKb);
                ldsm_x4(bh[np], sB + off);
            }
#pragma unroll
            for (int mt = 0; mt < 4; mt++) {
#pragma unroll
                for (int nt = 0; nt < 4; nt++) {
                    const uint32_t* pbh = &bh[nt >> 1][(nt & 1) * 2];
                    mma16816(acc[mt][nt], ah[mt], pbh);
                }
            }
        }
        __syncthreads();
    }

    // epilogue
    int mrow0 = bm + wm + (lane >> 2);
    int ncol0 = bn + wn + (lane & 3) * 2;
#pragma unroll
    for (int mt = 0; mt < 4; mt++) {
#pragma unroll
        for (int half = 0; half < 2; half++) {
            int m = mrow0 + mt * 16 + half * 8;
            float* crow = C ? C + (size_t)m * N : nullptr;
            const float* rrow = res ? res + (size_t)m * N : nullptr;
            int mp = m + 1;
            bool doshift = (oh != nullptr) && ((mp & (TT - 1)) != 0);
#pragma unroll
            for (int nt = 0; nt < 4; nt++) {
                int n = ncol0 + nt * 8;
                if (n + 1 < N) {
                    float v0 = acc[mt][nt][half * 2 + 0] + bias[n];
                    float v1 = acc[mt][nt][half * 2 + 1] + bias[n + 1];
                    if (res) { v0 += rrow[n]; v1 += rrow[n + 1]; }
                    if (crow) { crow[n] = v0; crow[n + 1] = v1; }
                    if (doshift) {
                        __half2 hp;
                        hp.x = __float2half_rn(v0);
                        hp.y = __float2half_rn(v1);
                        *(__half2*)(oh + (size_t)mp * N + n) = hp;
                    }
                } else if (n < N) {
                    float v0 = acc[mt][nt][half * 2 + 0] + bias[n];
                    if (res) v0 += rrow[n];
                    if (crow) crow[n] = v0;
                }
            }
        }
    }
}

// ---------------- merged weight prep ----------------------------------------
#define W1SZ (NT1 * HID)
#define W2SZ (HID * DI)
#define WKSZ (128 * HID)
__global__ void prep_k(const float* __restrict__ in_w, const float* __restrict__ out_w,
                       const float* __restrict__ kp_w1, const float* __restrict__ kg_w1,
                       const float* __restrict__ kp_b1, const float* __restrict__ kg_b1,
                       __half* __restrict__ w1, __half* __restrict__ w2,
                       __half* __restrict__ wk, float* __restrict__ kb) {
    int idx = blockIdx.x * blockDim.x + threadIdx.x;
    if (idx < W1SZ) {
        int n = idx / HID, k = idx % HID;
        float v = (n < PROJ) ? in_w[(size_t)k * PROJ + n] : 0.f;
        w1[idx] = __float2half_rn(v);
    } else if (idx < W1SZ + W2SZ) {
        int i = idx - W1SZ;
        int n = i / DI, k = i % DI;
        w2[i] = __float2half_rn(out_w[(size_t)k * HID + n]);
    } else if (idx < W1SZ + W2SZ + WKSZ) {
        int i = idx - W1SZ - W2SZ;
        int n = i / HID, k = i % HID;
        float v = (n < 64) ? kp_w1[(size_t)k * 64 + n] : kg_w1[(size_t)k * 64 + (n - 64)];
        wk[i] = __float2half_rn(v);
        if (i < 128) kb[i] = (i < 64) ? kp_b1[i] : kg_b1[i - 64];
    }
}

__global__ void initrow_k(const float* __restrict__ init_state,
                          __half* __restrict__ oh) {
    int b = blockIdx.x;
    int tid = threadIdx.x;
    float4 v = ((const float4*)init_state)[tid];
    __half hh[4] = {__float2half_rn(v.x), __float2half_rn(v.y),
                    __float2half_rn(v.z), __float2half_rn(v.w)};
    size_t base = (size_t)(b * TT) * HID + tid * 4;
    *(uint2*)(oh + base) = *(uint2*)hh;
}

// ---------------- 1) rmsnorm -> fp16 (warp per row) -------------------------
__global__ void rmsnorm_cvt_k(const float* __restrict__ x, const float* __restrict__ w,
                              __half* __restrict__ oh) {
    int r = blockIdx.x * 4 + (threadIdx.x >> 5);
    int lane = threadIdx.x & 31;
    const float4* xr = (const float4*)(x + (size_t)r * HID);
    float4 v0 = xr[lane], v1 = xr[lane + 32];
    float ss = v0.x*v0.x + v0.y*v0.y + v0.z*v0.z + v0.w*v0.w
             + v1.x*v1.x + v1.y*v1.y + v1.z*v1.z + v1.w*v1.w;
    ss = warpSum(ss);
    float sc = rsqrtf(ss / HID + 1e-5f);
    const float4* wr = (const float4*)w;
    float4 w0 = wr[lane], w1 = wr[lane + 32];
    __half h0[4] = {__float2half_rn(v0.x*sc*w0.x), __float2half_rn(v0.y*sc*w0.y),
                    __float2half_rn(v0.z*sc*w0.z), __float2half_rn(v0.w*sc*w0.w)};
    __half h1[4] = {__float2half_rn(v1.x*sc*w1.x), __float2half_rn(v1.y*sc*w1.y),
                    __float2half_rn(v1.z*sc*w1.z), __float2half_rn(v1.w*sc*w1.w)};
    size_t base = (size_t)r * HID;
    *(uint2*)(oh + base + lane * 4) = *(uint2*)h0;
    *(uint2*)(oh + base + (lane + 32) * 4) = *(uint2*)h1;
}

// ---------------- 4a) fused conv+silu + chunked scan local pass -------------
__global__ __launch_bounds__(64) void scanA_k(
    const float* __restrict__ zx, const float* __restrict__ cw,
    const float* __restrict__ cbv,
    const float* __restrict__ dt_bias, const float* __restrict__ A_log,
    const float* __restrict__ Dp, float* __restrict__ y,
    float* __restrict__ hloc, float* __restrict__ cum, float* __restrict__ bc)
{
    __shared__ float sBC[LC][32];
    __shared__ float sdt[LC];
    int h = blockIdx.x, b = blockIdx.y, c = blockIdx.z;
    int d = threadIdx.x;
    int t0 = c * LC;
    size_t rowbase = (size_t)(b * TT + t0);

    for (int i = d; i < LC * 32; i += 64) {
        int t = i >> 5, j = i & 31;
        int ch = 512 + j;
        float acc = cbv[ch];
#pragma unroll
        for (int k = 0; k < DCONV; k++) {
            int tt = t0 + t - (DCONV - 1) + k;
            if (tt >= 0)
                acc = fmaf(zx[((size_t)(b * TT + tt)) * PROJ + DI + ch],
                           cw[k * CCH + ch], acc);
        }
        float v = siluf(acc);
        sBC[t][j] = v;
        if (h == 0) bc[(rowbase + t) * 32 + j] = v;
    }
    float dtb = dt_bias[h];
    for (int i = d; i < LC; i += 64)
        sdt[i] = softplusf(zx[(rowbase + i) * PROJ + 2 * DI + 2 * DS + h] + dtb);
    __syncthreads();

    int ch = h * HD + d;
    float w0 = cw[0 * CCH + ch], w1 = cw[1 * CCH + ch];
    float w2 = cw[2 * CCH + ch], w3 = cw[3 * CCH + ch];
    float cb0 = cbv[ch];
    const float* xcol = zx + DI + ch;
    float r0 = 0.f, r1 = 0.f, r2 = 0.f;
    {
        int tb = t0 - 3;
        if (tb >= 0)     r0 = xcol[(size_t)(b * TT + tb) * PROJ];
        if (tb + 1 >= 0) r1 = xcol[(size_t)(b * TT + tb + 1) * PROJ];
        if (tb + 2 >= 0) r2 = xcol[(size_t)(b * TT + tb + 2) * PROJ];
    }

    float A = -__expf(A_log[h]);
    float Dh = Dp[h];
    float hr[DS];
#pragma unroll
    for (int s = 0; s < DS; s++) hr[s] = 0.f;
    float cm = 1.f;

    float* yp = y + rowbase * DI + h * HD + d;
    float* cmp = cum + ((size_t)(b * NHH + h)) * TT + t0;

    for (int t = 0; t < LC; t++) {
        float raw = xcol[(rowbase + t) * PROJ];
        float x = siluf(fmaf(raw, w3, fmaf(r2, w2, fmaf(r1, w1, fmaf(r0, w0, cb0)))));
        r0 = r1; r1 = r2; r2 = raw;

        float dtsp = sdt[t];
        float dA = __expf(dtsp * A);
        cm *= dA;
        if (d == 0) cmp[t] = cm;
        float dtx = dtsp * x;
        float yvp[4] = {Dh * x, 0.f, 0.f, 0.f};
        float Bv[16], Cv[16];
        *(float4*)&Bv[0]  = *(const float4*)&sBC[t][0];
        *(float4*)&Bv[4]  = *(const float4*)&sBC[t][4];
        *(float4*)&Bv[8]  = *(const float4*)&sBC[t][8];
        *(float4*)&Bv[12] = *(const float4*)&sBC[t][12];
        *(float4*)&Cv[0]  = *(const float4*)&sBC[t][16];
        *(float4*)&Cv[4]  = *(const float4*)&sBC[t][20];
        *(float4*)&Cv[8]  = *(const float4*)&sBC[t][24];
        *(float4*)&Cv[12] = *(const float4*)&sBC[t][28];
#pragma unroll
        for (int s = 0; s < DS; s++) {
            hr[s] = fmaf(hr[s], dA, dtx * Bv[s]);
            yvp[s & 3] = fmaf(hr[s], Cv[s], yvp[s & 3]);
        }
        yp[(size_t)t * DI] = (yvp[0] + yvp[1]) + (yvp[2] + yvp[3]);
    }

    float* hl = hloc + ((size_t)((b * NHH + h) * NC + c)) * (DS * HD);
#pragma unroll
    for (int s = 0; s < DS; s++) hl[s * HD + d] = hr[s];
}

// ---------------- 4b) chain chunk states ------------------------------------
__global__ __launch_bounds__(64) void scanB_k(const float* __restrict__ hloc,
                                              const float* __restrict__ cum,
                                              float* __restrict__ hstart)
{
    int h = blockIdx.x, b = blockIdx.y, d = threadIdx.x;
    size_t base = (size_t)(b * NHH + h);
    float hs[DS];
#pragma unroll
    for (int s = 0; s < DS; s++) hs[s] = 0.f;
    for (int c = 0; c < NC; c++) {
        float* hsp = hstart + (base * NC + c) * (DS * HD);
#pragma unroll
        for (int s = 0; s < DS; s++) hsp[s * HD + d] = hs[s];
        float P = cum[base * TT + c * LC + LC - 1];
        const float* hl = hloc + (base * NC + c) * (DS * HD);
#pragma unroll
        for (int s = 0; s < DS; s++) hs[s] = fmaf(hs[s], P, hl[s * HD + d]);
    }
}

// ---------------- 4c) correction --------------------------------------------
__global__ __launch_bounds__(64) void scanC_k(const float* __restrict__ bc,
                                              const float* __restrict__ hstart,
                                              const float* __restrict__ cum,
                                              float* __restrict__ y)
{
    __shared__ float sC[LC][16];
    __shared__ float scm[LC];
    int h = blockIdx.x, b = blockIdx.y, c = blockIdx.z + 1;
    int d = threadIdx.x;
    int t0 = c * LC;
    size_t rowbase = (size_t)(b * TT + t0);
    size_t base = (size_t)(b * NHH + h);

    for (int i = d; i < LC * 16; i += 64) {
        int t = i >> 4, j = i & 15;
        sC[t][j] = bc[(rowbase + t) * 32 + 16 + j];
    }
    for (int i = d; i < LC; i += 64) scm[i] = cum[base * TT + t0 + i];

    float hs[DS];
    const float* hsp = hstart + (base * NC + c) * (DS * HD);
#pragma unroll
    for (int s = 0; s < DS; s++) hs[s] = hsp[s * HD + d];
    __syncthreads();

    float* yp = y + rowbase * DI + h * HD + d;
    for (int t = 0; t < LC; t++) {
        float Cv[16];
        *(float4*)&Cv[0]  = *(const float4*)&sC[t][0];
        *(float4*)&Cv[4]  = *(const float4*)&sC[t][4];
        *(float4*)&Cv[8]  = *(const float4*)&sC[t][8];
        *(float4*)&Cv[12] = *(const float4*)&sC[t][12];
        float acc = 0.f;
#pragma unroll
        for (int s = 0; s < DS; s++) acc = fmaf(hs[s], Cv[s], acc);
        yp[(size_t)t * DI] += acc * scm[t];
    }
}

// ---------------- 5) gate + rmsnorm -> fp16 (warp per row) ------------------
__global__ void gatenorm_cvt_k(const float* __restrict__ y, const float* __restrict__ zx,
                               const float* __restrict__ gw,
                               __half* __restrict__ oh) {
    int r = blockIdx.x * 4 + (threadIdx.x >> 5);
    int lane = threadIdx.x & 31;
    const float4* yr = (const float4*)(y + (size_t)r * DI);
    const float4* zr = (const float4*)(zx + (size_t)r * PROJ);
    float4 g[4];
    float ss = 0.f;
#pragma unroll
    for (int k = 0; k < 4; k++) {
        float4 yv = yr[lane + 32 * k];
        float4 zv = zr[lane + 32 * k];
        g[k].x = yv.x * siluf(zv.x); g[k].y = yv.y * siluf(zv.y);
        g[k].z = yv.z * siluf(zv.z); g[k].w = yv.w * siluf(zv.w);
        ss += g[k].x*g[k].x + g[k].y*g[k].y + g[k].z*g[k].z + g[k].w*g[k].w;
    }
    ss = warpSum(ss);
    float sc = rsqrtf(ss / DI + 1e-5f);
    const float4* wr = (const float4*)gw;
    size_t base = (size_t)r * DI;
#pragma unroll
    for (int k = 0; k < 4; k++) {
        float4 wv = wr[lane + 32 * k];
        __half hh[4] = {__float2half_rn(g[k].x*sc*wv.x), __float2half_rn(g[k].y*sc*wv.y),
                        __float2half_rn(g[k].z*sc*wv.z), __float2half_rn(g[k].w*sc*wv.w)};
        *(uint2*)(oh + base + (lane + 32 * k) * 4) = *(uint2*)hh;
    }
}

// ---------------- 7b) Kalman finish -----------------------------------------
__global__ __launch_bounds__(64) void kalman_fin_k(
    const float* __restrict__ AP, const float* __restrict__ z_t,
    const float* __restrict__ kg_w1,
    const float* __restrict__ kp_w2, const float* __restrict__ kp_b2,
    const float* __restrict__ km_w1, const float* __restrict__ km_b1,
    const float* __restrict__ km_w2, const float* __restrict__ km_b2,
    const float* __restrict__ kg_w2, const float* __restrict__ kg_b2,
    const float* __restrict__ kW, float* __restrict__ out)
{
    __shared__ float redv[2], redg[2];
    int r = blockIdx.x;
    int tid = threadIdx.x;
    float z = z_t[r];
    float ap = AP[(size_t)r * 128 + tid];
    float ag = AP[(size_t)r * 128 + 64 + tid];
    ag = fmaf(z, kg_w1[HID * 64 + tid], ag);
    float vp = siluf(ap) * kp_w2[tid];
    float gp = siluf(ag) * kg_w2[tid];
    vp = warpSum(vp);
    gp = warpSum(gp);
    if ((tid & 31) == 0) { redv[tid >> 5] = vp; redg[tid >> 5] = gp; }
    __syncthreads();
    if (tid == 0) {
        float v_prior = softplusf(redv[0] + redv[1] + kp_b2[0]);
        float Kt = sigmoidf_(redg[0] + redg[1] + kg_b2[0]);
        float macc = km_b2[0];
#pragma unroll
        for (int k = 0; k < 32; k++)
            macc = fmaf(siluf(fmaf(z, km_w1[k], km_b1[k])), km_w2[k], macc);
        float m_t = softplusf(macc);
        float vpost = v_prior + Kt * (m_t - kW[0] * v_prior);
        vpost = fminf(fmaxf(vpost, 1e-6f), 10.f);
        out[r] = vpost;
    }
}

// ---------------- 8) per-batch softmax reductions ---------------------------
__global__ void reduce_k(float* __restrict__ out) {
    __shared__ float sa[256], sb[256];
    int b = blockIdx.x;
    int tid = threadIdx.x;
    const float* v = out + (size_t)b * TT;
    float v0 = v[tid], v1 = v[tid + 256];

    sa[tid] = fmaxf(v0, v1);
    sb[tid] = fminf(v0, v1);
    __syncthreads();
    for (int s = 128; s > 0; s >>= 1) {
        if (tid < s) {
            sa[tid] = fmaxf(sa[tid], sa[tid + s]);
            sb[tid] = fminf(sb[tid], sb[tid + s]);
        }
        __syncthreads();
    }
    float mx = sa[0], mn = sb[0];
    __syncthreads();

    float e0 = __expf(v0 - mx), e1 = __expf(v1 - mx);
    sa[tid] = e0 + e1;
    sb[tid] = e0 * v0 + e1 * v1;
    __syncthreads();
    for (int s = 128; s > 0; s >>= 1) {
        if (tid < s) { sa[tid] += sa[tid + s]; sb[tid] += sb[tid + s]; }
        __syncthreads();
    }
    float spden = sa[0], spnum = sb[0];
    __syncthreads();

    float f0 = __expf(mn - v0), f1 = __expf(mn - v1);
    sa[tid] = f0 + f1;
    sb[tid] = f0 * v0 + f1 * v1;
    __syncthreads();
    for (int s = 128; s > 0; s >>= 1) {
        if (tid < s) { sa[tid] += sa[tid + s]; sb[tid] += sb[tid + s]; }
        __syncthreads();
    }
    if (tid == 0) {
        out[ROWS + b] = spnum / spden;
        out[ROWS + BB + b] = sb[0] / sa[0];
    }
}

// ---------------- launcher ---------------------------------------------------
extern "C" void kernel_launch(void* const* d_in, const int* in_sizes, int n_in,
                              void* d_out, int out_size) {
    const float* tokens   = (const float*)d_in[0];
    const float* z_t      = (const float*)d_in[1];
    const float* norm_w   = (const float*)d_in[2];
    const float* in_w     = (const float*)d_in[3];
    const float* in_b     = (const float*)d_in[4];
    const float* conv_w   = (const float*)d_in[5];
    const float* conv_b   = (const float*)d_in[6];
    const float* dt_bias  = (const float*)d_in[7];
    const float* A_log    = (const float*)d_in[8];
    const float* Dp       = (const float*)d_in[9];
    const float* gnorm_w  = (const float*)d_in[10];
    const float* out_w    = (const float*)d_in[11];
    const float* out_b    = (const float*)d_in[12];
    const float* kp_w1    = (const float*)d_in[13];
    const float* kp_b1    = (const float*)d_in[14];
    const float* kp_w2    = (const float*)d_in[15];
    const float* kp_b2    = (const float*)d_in[16];
    const float* km_w1    = (const float*)d_in[17];
    const float* km_b1    = (const float*)d_in[18];
    const float* km_w2    = (const float*)d_in[19];
    const float* km_b2    = (const float*)d_in[20];
    const float* kg_w1    = (const float*)d_in[21];
    const float* kg_b1    = (const float*)d_in[22];
    const float* kg_w2    = (const float*)d_in[23];
    const float* kg_b2    = (const float*)d_in[24];
    const float* kW       = (const float*)d_in[25];
    const float* init_st  = (const float*)d_in[26];
    float* out = (float*)d_out;

    float *zx, *y, *bc, *hloc, *hstart, *cum, *ap, *kb;
    __half *xh, *yh, *ph, *wt1, *wt2, *wk;
    cudaGetSymbolAddress((void**)&zx,     g_zx);
    cudaGetSymbolAddress((void**)&y,      g_y);
    cudaGetSymbolAddress((void**)&bc,     g_bc);
    cudaGetSymbolAddress((void**)&hloc,   g_hloc);
    cudaGetSymbolAddress((void**)&hstart, g_hstart);
    cudaGetSymbolAddress((void**)&cum,    g_cum);
    cudaGetSymbolAddress((void**)&ap,     g_ap);
    cudaGetSymbolAddress((void**)&kb,     g_kb);
    cudaGetSymbolAddress((void**)&xh,     g_xh);
    cudaGetSymbolAddress((void**)&yh,     g_yh);
    cudaGetSymbolAddress((void**)&ph,     g_ph);
    cudaGetSymbolAddress((void**)&wt1,    g_wt1);
    cudaGetSymbolAddress((void**)&wt2,    g_wt2);
    cudaGetSymbolAddress((void**)&wk,     g_wk);

    cudaFuncSetAttribute(gemm_mma, cudaFuncAttributeMaxDynamicSharedMemorySize,
                         2 * GSM_STAGE);

    // weight prep (merged, single fp16) + t=0 Kalman rows
    prep_k<<<(W1SZ + W2SZ + WKSZ + 255) / 256, 256>>>(
        in_w, out_w, kp_w1, kg_w1, kp_b1, kg_b1, wt1, wt2, wk, kb);
    initrow_k<<<BB, 64>>>(init_st, ph);

    // 1) rmsnorm -> fp16 (warp per row)
    rmsnorm_cvt_k<<<ROWS / 4, 128>>>(tokens, norm_w, xh);
    // 2) in-proj GEMM
    gemm_mma<<<dim3(NT1 / 128, ROWS / 128), 256, 2 * GSM_STAGE>>>(
        xh, wt1, in_b, nullptr, zx, nullptr, HID, PROJ);
    // 3+4) fused conv + chunked scan
    scanA_k<<<dim3(NHH, BB, NC), 64>>>(zx, conv_w, conv_b, dt_bias, A_log, Dp,
                                       y, hloc, cum, bc);
    scanB_k<<<dim3(NHH, BB), 64>>>(hloc, cum, hstart);
    scanC_k<<<dim3(NHH, BB, NC - 1), 64>>>(bc, hstart, cum, y);
    // 5) gate + rmsnorm (warp per row)
    gatenorm_cvt_k<<<ROWS / 4, 128>>>(y, zx, gnorm_w, yh);
    // 6) out-proj GEMM + residual, fused shift+cvt into ph
    gemm_mma<<<dim3(HID / 128, ROWS / 128), 256, 2 * GSM_STAGE>>>(
        yh, wt2, out_b, tokens, nullptr, ph, DI, HID);
    // 7) Kalman GEMM -> finish
    gemm_mma<<<dim3(1, ROWS / 128), 256, 2 * GSM_STAGE>>>(
        ph, wk, kb, nullptr, ap, nullptr, HID, 128);
    kalman_fin_k<<<ROWS, 64>>>(ap, z_t, kg_w1,
                               kp_w2, kp_b2, km_w1, km_b1, km_w2, km_b2,
                               kg_w2, kg_b2, kW, out);
    // 8) per-batch reductions
    reduce_k<<<BB, 256>>>(out);
}

// round 14
// speedup vs baseline: 1.5556x; 1.1445x over previous
#include <cuda_runtime.h>
#include <cuda_fp16.h>
#include <cstdint>

#define BB    64
#define TT    512
#define HID   256
#define DI    512
#define DS    16
#define NHH   8
#define HD    64
#define DCONV 4
#define CCH   544    // DI + 2*DS
#define PROJ  1064   // 2*DI + 2*DS + NH
#define ROWS  (BB*TT) // 32768
#define NC    16
#define LC    32     // TT/NC
#define NT1   1152   // PROJ padded to 9*128

// ---------------- scratch (device globals; no allocation allowed) ----------
__device__ __align__(16) __half g_zx[ROWS * PROJ];
__device__ __align__(16) float g_y[ROWS * DI];
__device__ __align__(16) float g_bc[ROWS * 32];
__device__ __align__(16) float g_hloc[BB * NHH * NC * HD * DS];
__device__ __align__(16) float g_hstart[BB * NHH * NC * HD * DS];
__device__ __align__(16) float g_cum[BB * NHH * TT];
__device__ __align__(16) __half g_xh[ROWS * HID];
__device__ __align__(16) __half g_yh[ROWS * DI];
__device__ __align__(16) __half g_ph[ROWS * HID];
__device__ __align__(16) float g_ap[ROWS * 128];
__device__ __align__(16) __half g_wt1[NT1 * HID];
__device__ __align__(16) __half g_wt2[HID * DI];
__device__ __align__(16) __half g_wk[128 * HID];
__device__ __align__(16) float g_kb[128];

// ---------------- helpers ---------------------------------------------------
__device__ __forceinline__ float siluf(float x) { return x / (1.f + __expf(-x)); }
__device__ __forceinline__ float softplusf(float x) {
    return (x > 20.f) ? x : log1pf(__expf(x));
}
__device__ __forceinline__ float sigmoidf_(float x) { return 1.f / (1.f + __expf(-x)); }
__device__ __forceinline__ float warpSum(float v) {
#pragma unroll
    for (int o = 16; o; o >>= 1) v += __shfl_xor_sync(0xffffffffu, v, o);
    return v;
}
__device__ __forceinline__ uint32_t smem_u32(const void* p) {
    uint32_t a;
    asm("{ .reg .u64 t; cvta.to.shared.u64 t, %1; cvt.u32.u64 %0, t; }"
        : "=r"(a) : "l"(p));
    return a;
}
#define SWZ(b) ((b) ^ (((b) >> 3) & 0x70))

__device__ __forceinline__ void ldsm_x4(uint32_t* r, uint32_t addr) {
    asm volatile("ldmatrix.sync.aligned.m8n8.x4.shared.b16 {%0,%1,%2,%3}, [%4];"
                 : "=r"(r[0]), "=r"(r[1]), "=r"(r[2]), "=r"(r[3]) : "r"(addr));
}
__device__ __forceinline__ void mma16816(float* c, const uint32_t* a, const uint32_t* b) {
    asm volatile("mma.sync.aligned.m16n8k16.row.col.f32.f16.f16.f32 "
                 "{%0,%1,%2,%3}, {%4,%5,%6,%7}, {%8,%9}, {%0,%1,%2,%3};"
                 : "+f"(c[0]), "+f"(c[1]), "+f"(c[2]), "+f"(c[3])
                 : "r"(a[0]), "r"(a[1]), "r"(a[2]), "r"(a[3]), "r"(b[0]), "r"(b[1]));
}
#define CP16(sa, gp) \
    asm volatile("cp.async.cg.shared.global [%0], [%1], 16;" :: "r"(sa), "l"(gp))
#define CP_COMMIT() asm volatile("cp.async.commit_group;" ::: "memory")
#define CP_WAIT1() asm volatile("cp.async.wait_group 1;" ::: "memory")
#define CP_WAIT0() asm volatile("cp.async.wait_group 0;" ::: "memory")

// ---------------- fp16 GEMM via mma.sync, cp.async 2-stage ------------------
// A: [M,K] fp16 row-major. B: [NT,K] fp16 row-major (W^T, zero-padded). K%64==0.
// CTA tile 128x128, BK=64, 8 warps (2x4), warp tile 64x32.
// Output options: C (fp32 full), ch (fp16 full), oh (fp16 shifted to row m+1,
// skipping (m+1)%TT==0; requires N==HID).
#define TILE_B 16384
#define GSM_STAGE (2 * TILE_B)
__global__ __launch_bounds__(256, 2) void gemm_mma(
    const __half* __restrict__ A, const __half* __restrict__ B,
    const float* __restrict__ bias, const float* __restrict__ res,
    float* __restrict__ C, __half* __restrict__ ch, __half* __restrict__ oh,
    int K, int N)
{
    extern __shared__ __align__(16) uint8_t dsm[];
    uint32_t sbase = smem_u32(dsm);

    int tid = threadIdx.x;
    int wid = tid >> 5, lane = tid & 31;
    int bm = blockIdx.y * 128, bn = blockIdx.x * 128;
    int wm = (wid >> 2) * 64;
    int wn = (wid & 3) * 32;

    int lrow = tid >> 1;
    int lhe  = (tid & 1) * 32;
    const __half* pA = A + (size_t)(bm + lrow) * K + lhe;
    const __half* pB = B + (size_t)(bn + lrow) * K + lhe;
    uint32_t so[4];
#pragma unroll
    for (int i = 0; i < 4; i++)
        so[i] = SWZ((uint32_t)(lrow * 128 + (tid & 1) * 64 + i * 16));

    float acc[4][4][4];
#pragma unroll
    for (int i = 0; i < 4; i++)
#pragma unroll
        for (int j = 0; j < 4; j++)
#pragma unroll
            for (int q = 0; q < 4; q++) acc[i][j][q] = 0.f;

    int aRow = lane & 15;
    int aKb  = (lane >> 4) << 4;
    int bRow = ((lane >> 4) << 3) + (lane & 7);
    int bKb  = ((lane >> 3) & 1) << 4;

    const int KC = K >> 6;

    {
        uint32_t st = sbase;
#pragma unroll
        for (int i = 0; i < 4; i++) {
            CP16(st + so[i],          pA + i * 8);
            CP16(st + TILE_B + so[i], pB + i * 8);
        }
        CP_COMMIT();
    }

    for (int c = 0; c < KC; c++) {
        if (c + 1 < KC) {
            int e = (c + 1) * 64;
            uint32_t st = sbase + ((c + 1) & 1) * GSM_STAGE;
#pragma unroll
            for (int i = 0; i < 4; i++) {
                CP16(st + so[i],          pA + e + i * 8);
                CP16(st + TILE_B + so[i], pB + e + i * 8);
            }
            CP_COMMIT();
            CP_WAIT1();
        } else {
            CP_WAIT0();
        }
        __syncthreads();

        uint32_t st = sbase + (c & 1) * GSM_STAGE;
        uint32_t sA = st, sB = st + TILE_B;

#pragma unroll
        for (int ks = 0; ks < 4; ks++) {
            int kb2 = ks * 32;
            uint32_t ah[4][4], bh[2][4];
#pragma unroll
            for (int mt = 0; mt < 4; mt++) {
                uint32_t off = SWZ((uint32_t)(wm + mt * 16 + aRow) * 128 + kb2 + aKb);
                ldsm_x4(ah[mt], sA + off);
            }
#pragma unroll
            for (int np = 0; np < 2; np++) {
                uint32_t off = SWZ((uint32_t)(wn + np * 16 + bRow) * 128 + kb2 + bKb);
                ldsm_x4(bh[np], sB + off);
            }
#pragma unroll
            for (int mt = 0; mt < 4; mt++) {
#pragma unroll
                for (int nt = 0; nt < 4; nt++) {
                    const uint32_t* pbh = &bh[nt >> 1][(nt & 1) * 2];
                    mma16816(acc[mt][nt], ah[mt], pbh);
                }
            }
        }
        __syncthreads();
    }

    // epilogue
    int mrow0 = bm + wm + (lane >> 2);
    int ncol0 = bn + wn + (lane & 3) * 2;
#pragma unroll
    for (int mt = 0; mt < 4; mt++) {
#pragma unroll
        for (int half = 0; half < 2; half++) {
            int m = mrow0 + mt * 16 + half * 8;
            float* crow = C ? C + (size_t)m * N : nullptr;
            __half* chrow = ch ? ch + (size_t)m * N : nullptr;
            const float* rrow = res ? res + (size_t)m * N : nullptr;
            int mp = m + 1;
            bool doshift = (oh != nullptr) && ((mp & (TT - 1)) != 0);
#pragma unroll
            for (int nt = 0; nt < 4; nt++) {
                int n = ncol0 + nt * 8;
                if (n + 1 < N) {
                    float v0 = acc[mt][nt][half * 2 + 0] + bias[n];
                    float v1 = acc[mt][nt][half * 2 + 1] + bias[n + 1];
                    if (res) { v0 += rrow[n]; v1 += rrow[n + 1]; }
                    if (crow) { crow[n] = v0; crow[n + 1] = v1; }
                    if (chrow) {
                        __half2 hp;
                        hp.x = __float2half_rn(v0);
                        hp.y = __float2half_rn(v1);
                        *(__half2*)(chrow + n) = hp;
                    }
                    if (doshift) {
                        __half2 hp;
                        hp.x = __float2half_rn(v0);
                        hp.y = __float2half_rn(v1);
                        *(__half2*)(oh + (size_t)mp * N + n) = hp;
                    }
                } else if (n < N) {
                    float v0 = acc[mt][nt][half * 2 + 0] + bias[n];
                    if (res) v0 += rrow[n];
                    if (crow) crow[n] = v0;
                    if (chrow) chrow[n] = __float2half_rn(v0);
                }
            }
        }
    }
}

// ---------------- merged weight prep ----------------------------------------
#define W1SZ (NT1 * HID)
#define W2SZ (HID * DI)
#define WKSZ (128 * HID)
__global__ void prep_k(const float* __restrict__ in_w, const float* __restrict__ out_w,
                       const float* __restrict__ kp_w1, const float* __restrict__ kg_w1,
                       const float* __restrict__ kp_b1, const float* __restrict__ kg_b1,
                       __half* __restrict__ w1, __half* __restrict__ w2,
                       __half* __restrict__ wk, float* __restrict__ kb) {
    int idx = blockIdx.x * blockDim.x + threadIdx.x;
    if (idx < W1SZ) {
        int n = idx / HID, k = idx % HID;
        float v = (n < PROJ) ? in_w[(size_t)k * PROJ + n] : 0.f;
        w1[idx] = __float2half_rn(v);
    } else if (idx < W1SZ + W2SZ) {
        int i = idx - W1SZ;
        int n = i / DI, k = i % DI;
        w2[i] = __float2half_rn(out_w[(size_t)k * HID + n]);
    } else if (idx < W1SZ + W2SZ + WKSZ) {
        int i = idx - W1SZ - W2SZ;
        int n = i / HID, k = i % HID;
        float v = (n < 64) ? kp_w1[(size_t)k * 64 + n] : kg_w1[(size_t)k * 64 + (n - 64)];
        wk[i] = __float2half_rn(v);
        if (i < 128) kb[i] = (i < 64) ? kp_b1[i] : kg_b1[i - 64];
    }
}

__global__ void initrow_k(const float* __restrict__ init_state,
                          __half* __restrict__ oh) {
    int b = blockIdx.x;
    int tid = threadIdx.x;
    float4 v = ((const float4*)init_state)[tid];
    __half hh[4] = {__float2half_rn(v.x), __float2half_rn(v.y),
                    __float2half_rn(v.z), __float2half_rn(v.w)};
    size_t base = (size_t)(b * TT) * HID + tid * 4;
    *(uint2*)(oh + base) = *(uint2*)hh;
}

// ---------------- 1) rmsnorm -> fp16 (warp per row) -------------------------
__global__ void rmsnorm_cvt_k(const float* __restrict__ x, const float* __restrict__ w,
                              __half* __restrict__ oh) {
    int r = blockIdx.x * 4 + (threadIdx.x >> 5);
    int lane = threadIdx.x & 31;
    const float4* xr = (const float4*)(x + (size_t)r * HID);
    float4 v0 = xr[lane], v1 = xr[lane + 32];
    float ss = v0.x*v0.x + v0.y*v0.y + v0.z*v0.z + v0.w*v0.w
             + v1.x*v1.x + v1.y*v1.y + v1.z*v1.z + v1.w*v1.w;
    ss = warpSum(ss);
    float sc = rsqrtf(ss / HID + 1e-5f);
    const float4* wr = (const float4*)w;
    float4 w0 = wr[lane], w1 = wr[lane + 32];
    __half h0[4] = {__float2half_rn(v0.x*sc*w0.x), __float2half_rn(v0.y*sc*w0.y),
                    __float2half_rn(v0.z*sc*w0.z), __float2half_rn(v0.w*sc*w0.w)};
    __half h1[4] = {__float2half_rn(v1.x*sc*w1.x), __float2half_rn(v1.y*sc*w1.y),
                    __float2half_rn(v1.z*sc*w1.z), __float2half_rn(v1.w*sc*w1.w)};
    size_t base = (size_t)r * HID;
    *(uint2*)(oh + base + lane * 4) = *(uint2*)h0;
    *(uint2*)(oh + base + (lane + 32) * 4) = *(uint2*)h1;
}

// ---------------- 4a) fused conv+silu + chunked scan local pass -------------
__global__ __launch_bounds__(64) void scanA_k(
    const __half* __restrict__ zx, const float* __restrict__ cw,
    const float* __restrict__ cbv,
    const float* __restrict__ dt_bias, const float* __restrict__ A_log,
    const float* __restrict__ Dp, float* __restrict__ y,
    float* __restrict__ hloc, float* __restrict__ cum, float* __restrict__ bc)
{
    __shared__ float sBC[LC][32];
    __shared__ float sdt[LC];
    int h = blockIdx.x, b = blockIdx.y, c = blockIdx.z;
    int d = threadIdx.x;
    int t0 = c * LC;
    size_t rowbase = (size_t)(b * TT + t0);

    for (int i = d; i < LC * 32; i += 64) {
        int t = i >> 5, j = i & 31;
        int ch = 512 + j;
        float acc = cbv[ch];
#pragma unroll
        for (int k = 0; k < DCONV; k++) {
            int tt = t0 + t - (DCONV - 1) + k;
            if (tt >= 0)
                acc = fmaf(__half2float(zx[((size_t)(b * TT + tt)) * PROJ + DI + ch]),
                           cw[k * CCH + ch], acc);
        }
        float v = siluf(acc);
        sBC[t][j] = v;
        if (h == 0) bc[(rowbase + t) * 32 + j] = v;
    }
    float dtb = dt_bias[h];
    for (int i = d; i < LC; i += 64)
        sdt[i] = softplusf(__half2float(zx[(rowbase + i) * PROJ + 2 * DI + 2 * DS + h]) + dtb);
    __syncthreads();

    int ch = h * HD + d;
    float w0 = cw[0 * CCH + ch], w1 = cw[1 * CCH + ch];
    float w2 = cw[2 * CCH + ch], w3 = cw[3 * CCH + ch];
    float cb0 = cbv[ch];
    const __half* xcol = zx + DI + ch;
    float r0 = 0.f, r1 = 0.f, r2 = 0.f;
    {
        int tb = t0 - 3;
        if (tb >= 0)     r0 = __half2float(xcol[(size_t)(b * TT + tb) * PROJ]);
        if (tb + 1 >= 0) r1 = __half2float(xcol[(size_t)(b * TT + tb + 1) * PROJ]);
        if (tb + 2 >= 0) r2 = __half2float(xcol[(size_t)(b * TT + tb + 2) * PROJ]);
    }

    float A = -__expf(A_log[h]);
    float Dh = Dp[h];
    float hr[DS];
#pragma unroll
    for (int s = 0; s < DS; s++) hr[s] = 0.f;
    float cm = 1.f;

    float* yp = y + rowbase * DI + h * HD + d;
    float* cmp = cum + ((size_t)(b * NHH + h)) * TT + t0;

    for (int t = 0; t < LC; t++) {
        float raw = __half2float(xcol[(rowbase + t) * PROJ]);
        float x = siluf(fmaf(raw, w3, fmaf(r2, w2, fmaf(r1, w1, fmaf(r0, w0, cb0)))));
        r0 = r1; r1 = r2; r2 = raw;

        float dtsp = sdt[t];
        float dA = __expf(dtsp * A);
        cm *= dA;
        if (d == 0) cmp[t] = cm;
        float dtx = dtsp * x;
        float yvp[4] = {Dh * x, 0.f, 0.f, 0.f};
        float Bv[16], Cv[16];
        *(float4*)&Bv[0]  = *(const float4*)&sBC[t][0];
        *(float4*)&Bv[4]  = *(const float4*)&sBC[t][4];
        *(float4*)&Bv[8]  = *(const float4*)&sBC[t][8];
        *(float4*)&Bv[12] = *(const float4*)&sBC[t][12];
        *(float4*)&Cv[0]  = *(const float4*)&sBC[t][16];
        *(float4*)&Cv[4]  = *(const float4*)&sBC[t][20];
        *(float4*)&Cv[8]  = *(const float4*)&sBC[t][24];
        *(float4*)&Cv[12] = *(const float4*)&sBC[t][28];
#pragma unroll
        for (int s = 0; s < DS; s++) {
            hr[s] = fmaf(hr[s], dA, dtx * Bv[s]);
            yvp[s & 3] = fmaf(hr[s], Cv[s], yvp[s & 3]);
        }
        yp[(size_t)t * DI] = (yvp[0] + yvp[1]) + (yvp[2] + yvp[3]);
    }

    float* hl = hloc + ((size_t)((b * NHH + h) * NC + c)) * (DS * HD);
#pragma unroll
    for (int s = 0; s < DS; s++) hl[s * HD + d] = hr[s];
}

// ---------------- 4b) chain chunk states ------------------------------------
__global__ __launch_bounds__(64) void scanB_k(const float* __restrict__ hloc,
                                              const float* __restrict__ cum,
                                              float* __restrict__ hstart)
{
    int h = blockIdx.x, b = blockIdx.y, d = threadIdx.x;
    size_t base = (size_t)(b * NHH + h);
    float hs[DS];
#pragma unroll
    for (int s = 0; s < DS; s++) hs[s] = 0.f;
    for (int c = 0; c < NC; c++) {
        float* hsp = hstart + (base * NC + c) * (DS * HD);
#pragma unroll
        for (int s = 0; s < DS; s++) hsp[s * HD + d] = hs[s];
        float P = cum[base * TT + c * LC + LC - 1];
        const float* hl = hloc + (base * NC + c) * (DS * HD);
#pragma unroll
        for (int s = 0; s < DS; s++) hs[s] = fmaf(hs[s], P, hl[s * HD + d]);
    }
}

// ---------------- 4c) correction --------------------------------------------
__global__ __launch_bounds__(64) void scanC_k(const float* __restrict__ bc,
                                              const float* __restrict__ hstart,
                                              const float* __restrict__ cum,
                                              float* __restrict__ y)
{
    __shared__ float sC[LC][16];
    __shared__ float scm[LC];
    int h = blockIdx.x, b = blockIdx.y, c = blockIdx.z + 1;
    int d = threadIdx.x;
    int t0 = c * LC;
    size_t rowbase = (size_t)(b * TT + t0);
    size_t base = (size_t)(b * NHH + h);

    for (int i = d; i < LC * 16; i += 64) {
        int t = i >> 4, j = i & 15;
        sC[t][j] = bc[(rowbase + t) * 32 + 16 + j];
    }
    for (int i = d; i < LC; i += 64) scm[i] = cum[base * TT + t0 + i];

    float hs[DS];
    const float* hsp = hstart + (base * NC + c) * (DS * HD);
#pragma unroll
    for (int s = 0; s < DS; s++) hs[s] = hsp[s * HD + d];
    __syncthreads();

    float* yp = y + rowbase * DI + h * HD + d;
    for (int t = 0; t < LC; t++) {
        float Cv[16];
        *(float4*)&Cv[0]  = *(const float4*)&sC[t][0];
        *(float4*)&Cv[4]  = *(const float4*)&sC[t][4];
        *(float4*)&Cv[8]  = *(const float4*)&sC[t][8];
        *(float4*)&Cv[12] = *(const float4*)&sC[t][12];
        float acc = 0.f;
#pragma unroll
        for (int s = 0; s < DS; s++) acc = fmaf(hs[s], Cv[s], acc);
        yp[(size_t)t * DI] += acc * scm[t];
    }
}

// ---------------- 5) gate + rmsnorm -> fp16 (warp per row) ------------------
__global__ void gatenorm_cvt_k(const float* __restrict__ y, const __half* __restrict__ zx,
                               const float* __restrict__ gw,
                               __half* __restrict__ oh) {
    int r = blockIdx.x * 4 + (threadIdx.x >> 5);
    int lane = threadIdx.x & 31;
    const float4* yr = (const float4*)(y + (size_t)r * DI);
    const __half* zr = zx + (size_t)r * PROJ;
    float4 g[4];
    float ss = 0.f;
#pragma unroll
    for (int k = 0; k < 4; k++) {
        float4 yv = yr[lane + 32 * k];
        uint2 zu = *(const uint2*)(zr + (lane + 32 * k) * 4);
        __half2 za = *(__half2*)&zu.x, zb = *(__half2*)&zu.y;
        float z0 = __half2float(za.x), z1 = __half2float(za.y);
        float z2 = __half2float(zb.x), z3 = __half2float(zb.y);
        g[k].x = yv.x * siluf(z0); g[k].y = yv.y * siluf(z1);
        g[k].z = yv.z * siluf(z2); g[k].w = yv.w * siluf(z3);
        ss += g[k].x*g[k].x + g[k].y*g[k].y + g[k].z*g[k].z + g[k].w*g[k].w;
    }
    ss = warpSum(ss);
    float sc = rsqrtf(ss / DI + 1e-5f);
    const float4* wr = (const float4*)gw;
    size_t base = (size_t)r * DI;
#pragma unroll
    for (int k = 0; k < 4; k++) {
        float4 wv = wr[lane + 32 * k];
        __half hh[4] = {__float2half_rn(g[k].x*sc*wv.x), __float2half_rn(g[k].y*sc*wv.y),
                        __float2half_rn(g[k].z*sc*wv.z), __float2half_rn(g[k].w*sc*wv.w)};
        *(uint2*)(oh + base + (lane + 32 * k) * 4) = *(uint2*)hh;
    }
}

// ---------------- 7b) Kalman finish (parallel m_t) ---------------------------
__global__ __launch_bounds__(64) void kalman_fin_k(
    const float* __restrict__ AP, const float* __restrict__ z_t,
    const float* __restrict__ kg_w1,
    const float* __restrict__ kp_w2, const float* __restrict__ kp_b2,
    const float* __restrict__ km_w1, const float* __restrict__ km_b1,
    const float* __restrict__ km_w2, const float* __restrict__ km_b2,
    const float* __restrict__ kg_w2, const float* __restrict__ kg_b2,
    const float* __restrict__ kW, float* __restrict__ out)
{
    __shared__ float redv[2], redg[2], redm;
    int r = blockIdx.x;
    int tid = threadIdx.x;
    float z = z_t[r];
    float ap = AP[(size_t)r * 128 + tid];
    float ag = AP[(size_t)r * 128 + 64 + tid];
    ag = fmaf(z, kg_w1[HID * 64 + tid], ag);
    float vp = siluf(ap) * kp_w2[tid];
    float gp = siluf(ag) * kg_w2[tid];
    float mp = 0.f;
    if (tid < 32)
        mp = siluf(fmaf(z, km_w1[tid], km_b1[tid])) * km_w2[tid];
    vp = warpSum(vp);
    gp = warpSum(gp);
    mp = warpSum(mp);
    if ((tid & 31) == 0) { redv[tid >> 5] = vp; redg[tid >> 5] = gp; }
    if (tid == 0) redm = mp;
    __syncthreads();
    if (tid == 0) {
        float v_prior = softplusf(redv[0] + redv[1] + kp_b2[0]);
        float Kt = sigmoidf_(redg[0] + redg[1] + kg_b2[0]);
        float m_t = softplusf(redm + km_b2[0]);
        float vpost = v_prior + Kt * (m_t - kW[0] * v_prior);
        vpost = fminf(fmaxf(vpost, 1e-6f), 10.f);
        out[r] = vpost;
    }
}

// ---------------- 8) per-batch softmax reductions ---------------------------
__global__ void reduce_k(float* __restrict__ out) {
    __shared__ float sa[256], sb[256];
    int b = blockIdx.x;
    int tid = threadIdx.x;
    const float* v = out + (size_t)b * TT;
    float v0 = v[tid], v1 = v[tid + 256];

    sa[tid] = fmaxf(v0, v1);
    sb[tid] = fminf(v0, v1);
    __syncthreads();
    for (int s = 128; s > 0; s >>= 1) {
        if (tid < s) {
            sa[tid] = fmaxf(sa[tid], sa[tid + s]);
            sb[tid] = fminf(sb[tid], sb[tid + s]);
        }
        __syncthreads();
    }
    float mx = sa[0], mn = sb[0];
    __syncthreads();

    float e0 = __expf(v0 - mx), e1 = __expf(v1 - mx);
    sa[tid] = e0 + e1;
    sb[tid] = e0 * v0 + e1 * v1;
    __syncthreads();
    for (int s = 128; s > 0; s >>= 1) {
        if (tid < s) { sa[tid] += sa[tid + s]; sb[tid] += sb[tid + s]; }
        __syncthreads();
    }
    float spden = sa[0], spnum = sb[0];
    __syncthreads();

    float f0 = __expf(mn - v0), f1 = __expf(mn - v1);
    sa[tid] = f0 + f1;
    sb[tid] = f0 * v0 + f1 * v1;
    __syncthreads();
    for (int s = 128; s > 0; s >>= 1) {
        if (tid < s) { sa[tid] += sa[tid + s]; sb[tid] += sb[tid + s]; }
        __syncthreads();
    }
    if (tid == 0) {
        out[ROWS + b] = spnum / spden;
        out[ROWS + BB + b] = sb[0] / sa[0];
    }
}

// ---------------- launcher ---------------------------------------------------
extern "C" void kernel_launch(void* const* d_in, const int* in_sizes, int n_in,
                              void* d_out, int out_size) {
    const float* tokens   = (const float*)d_in[0];
    const float* z_t      = (const float*)d_in[1];
    const float* norm_w   = (const float*)d_in[2];
    const float* in_w     = (const float*)d_in[3];
    const float* in_b     = (const float*)d_in[4];
    const float* conv_w   = (const float*)d_in[5];
    const float* conv_b   = (const float*)d_in[6];
    const float* dt_bias  = (const float*)d_in[7];
    const float* A_log    = (const float*)d_in[8];
    const float* Dp       = (const float*)d_in[9];
    const float* gnorm_w  = (const float*)d_in[10];
    const float* out_w    = (const float*)d_in[11];
    const float* out_b    = (const float*)d_in[12];
    const float* kp_w1    = (const float*)d_in[13];
    const float* kp_b1    = (const float*)d_in[14];
    const float* kp_w2    = (const float*)d_in[15];
    const float* kp_b2    = (const float*)d_in[16];
    const float* km_w1    = (const float*)d_in[17];
    const float* km_b1    = (const float*)d_in[18];
    const float* km_w2    = (const float*)d_in[19];
    const float* km_b2    = (const float*)d_in[20];
    const float* kg_w1    = (const float*)d_in[21];
    const float* kg_b1    = (const float*)d_in[22];
    const float* kg_w2    = (const float*)d_in[23];
    const float* kg_b2    = (const float*)d_in[24];
    const float* kW       = (const float*)d_in[25];
    const float* init_st  = (const float*)d_in[26];
    float* out = (float*)d_out;

    float *y, *bc, *hloc, *hstart, *cum, *ap, *kb;
    __half *zx, *xh, *yh, *ph, *wt1, *wt2, *wk;
    cudaGetSymbolAddress((void**)&zx,     g_zx);
    cudaGetSymbolAddress((void**)&y,      g_y);
    cudaGetSymbolAddress((void**)&bc,     g_bc);
    cudaGetSymbolAddress((void**)&hloc,   g_hloc);
    cudaGetSymbolAddress((void**)&hstart, g_hstart);
    cudaGetSymbolAddress((void**)&cum,    g_cum);
    cudaGetSymbolAddress((void**)&ap,     g_ap);
    cudaGetSymbolAddress((void**)&kb,     g_kb);
    cudaGetSymbolAddress((void**)&xh,     g_xh);
    cudaGetSymbolAddress((void**)&yh,     g_yh);
    cudaGetSymbolAddress((void**)&ph,     g_ph);
    cudaGetSymbolAddress((void**)&wt1,    g_wt1);
    cudaGetSymbolAddress((void**)&wt2,    g_wt2);
    cudaGetSymbolAddress((void**)&wk,     g_wk);

    cudaFuncSetAttribute(gemm_mma, cudaFuncAttributeMaxDynamicSharedMemorySize,
                         2 * GSM_STAGE);

    // weight prep (merged, single fp16) + t=0 Kalman rows
    prep_k<<<(W1SZ + W2SZ + WKSZ + 255) / 256, 256>>>(
        in_w, out_w, kp_w1, kg_w1, kp_b1, kg_b1, wt1, wt2, wk, kb);
    initrow_k<<<BB, 64>>>(init_st, ph);

    // 1) rmsnorm -> fp16 (warp per row)
    rmsnorm_cvt_k<<<ROWS / 4, 128>>>(tokens, norm_w, xh);
    // 2) in-proj GEMM -> fp16 zx
    gemm_mma<<<dim3(NT1 / 128, ROWS / 128), 256, 2 * GSM_STAGE>>>(
        xh, wt1, in_b, nullptr, nullptr, zx, nullptr, HID, PROJ);
    // 3+4) fused conv + chunked scan
    scanA_k<<<dim3(NHH, BB, NC), 64>>>(zx, conv_w, conv_b, dt_bias, A_log, Dp,
                                       y, hloc, cum, bc);
    scanB_k<<<dim3(NHH, BB), 64>>>(hloc, cum, hstart);
    scanC_k<<<dim3(NHH, BB, NC - 1), 64>>>(bc, hstart, cum, y);
    // 5) gate + rmsnorm (warp per row)
    gatenorm_cvt_k<<<ROWS / 4, 128>>>(y, zx, gnorm_w, yh);
    // 6) out-proj GEMM + residual, fused shift+cvt into ph
    gemm_mma<<<dim3(HID / 128, ROWS / 128), 256, 2 * GSM_STAGE>>>(
        yh, wt2, out_b, tokens, nullptr, nullptr, ph, DI, HID);
    // 7) Kalman GEMM -> finish
    gemm_mma<<<dim3(1, ROWS / 128), 256, 2 * GSM_STAGE>>>(
        ph, wk, kb, nullptr, ap, nullptr, nullptr, HID, 128);
    kalman_fin_k<<<ROWS, 64>>>(ap, z_t, kg_w1,
                               kp_w2, kp_b2, km_w1, km_b1, km_w2, km_b2,
                               kg_w2, kg_b2, kW, out);
    // 8) per-batch reductions
    reduce_k<<<BB, 256>>>(out);
}

// round 15
// speedup vs baseline: 1.6309x; 1.0485x over previous
#include <cuda_runtime.h>
#include <cuda_fp16.h>
#include <cstdint>

#define BB    64
#define TT    512
#define HID   256
#define DI    512
#define DS    16
#define NHH   8
#define HD    64
#define DCONV 4
#define CCH   544    // DI + 2*DS
#define PROJ  1064   // 2*DI + 2*DS + NH
#define ROWS  (BB*TT) // 32768
#define NC    16
#define LC    32     // TT/NC
#define NT1   1152   // PROJ padded to 9*128

// ---------------- scratch (device globals; no allocation allowed) ----------
__device__ __align__(16) __half g_zx[ROWS * PROJ];
__device__ __align__(16) __half g_y[ROWS * DI];
__device__ __align__(16) float g_bc[ROWS * 32];
__device__ __align__(16) float g_hloc[BB * NHH * NC * HD * DS];
__device__ __align__(16) float g_hstart[BB * NHH * NC * HD * DS];
__device__ __align__(16) float g_cum[BB * NHH * TT];
__device__ __align__(16) __half g_xh[ROWS * HID];
__device__ __align__(16) __half g_yh[ROWS * DI];
__device__ __align__(16) __half g_ph[ROWS * HID];
__device__ __align__(16) float g_ap[ROWS * 128];
__device__ __align__(16) __half g_wt1[NT1 * HID];
__device__ __align__(16) __half g_wt2[HID * DI];
__device__ __align__(16) __half g_wk[128 * HID];
__device__ __align__(16) float g_kb[128];

// ---------------- helpers ---------------------------------------------------
__device__ __forceinline__ float siluf(float x) { return x / (1.f + __expf(-x)); }
__device__ __forceinline__ float softplusf(float x) {
    return (x > 20.f) ? x : log1pf(__expf(x));
}
__device__ __forceinline__ float sigmoidf_(float x) { return 1.f / (1.f + __expf(-x)); }
__device__ __forceinline__ float warpSum(float v) {
#pragma unroll
    for (int o = 16; o; o >>= 1) v += __shfl_xor_sync(0xffffffffu, v, o);
    return v;
}
__device__ __forceinline__ uint32_t smem_u32(const void* p) {
    uint32_t a;
    asm("{ .reg .u64 t; cvta.to.shared.u64 t, %1; cvt.u32.u64 %0, t; }"
        : "=r"(a) : "l"(p));
    return a;
}
#define SWZ(b) ((b) ^ (((b) >> 3) & 0x70))

__device__ __forceinline__ void ldsm_x4(uint32_t* r, uint32_t addr) {
    asm volatile("ldmatrix.sync.aligned.m8n8.x4.shared.b16 {%0,%1,%2,%3}, [%4];"
                 : "=r"(r[0]), "=r"(r[1]), "=r"(r[2]), "=r"(r[3]) : "r"(addr));
}
__device__ __forceinline__ void mma16816(float* c, const uint32_t* a, const uint32_t* b) {
    asm volatile("mma.sync.aligned.m16n8k16.row.col.f32.f16.f16.f32 "
                 "{%0,%1,%2,%3}, {%4,%5,%6,%7}, {%8,%9}, {%0,%1,%2,%3};"
                 : "+f"(c[0]), "+f"(c[1]), "+f"(c[2]), "+f"(c[3])
                 : "r"(a[0]), "r"(a[1]), "r"(a[2]), "r"(a[3]), "r"(b[0]), "r"(b[1]));
}
#define CP16(sa, gp) \
    asm volatile("cp.async.cg.shared.global [%0], [%1], 16;" :: "r"(sa), "l"(gp))
#define CP_COMMIT() asm volatile("cp.async.commit_group;" ::: "memory")
#define CP_WAIT1() asm volatile("cp.async.wait_group 1;" ::: "memory")
#define CP_WAIT0() asm volatile("cp.async.wait_group 0;" ::: "memory")

// ---------------- fp16 GEMM via mma.sync, cp.async 2-stage ------------------
// A: [M,K] fp16 row-major. B: [NT,K] fp16 row-major (W^T, zero-padded). K%64==0.
// CTA tile 128x128, BK=64, 8 warps (2x4), warp tile 64x32.
// Output options: C (fp32 full), ch (fp16 full), oh (fp16 shifted to row m+1,
// skipping (m+1)%TT==0; requires N==HID).
#define TILE_B 16384
#define GSM_STAGE (2 * TILE_B)
__global__ __launch_bounds__(256, 2) void gemm_mma(
    const __half* __restrict__ A, const __half* __restrict__ B,
    const float* __restrict__ bias, const float* __restrict__ res,
    float* __restrict__ C, __half* __restrict__ ch, __half* __restrict__ oh,
    int K, int N)
{
    extern __shared__ __align__(16) uint8_t dsm[];
    uint32_t sbase = smem_u32(dsm);

    int tid = threadIdx.x;
    int wid = tid >> 5, lane = tid & 31;
    int bm = blockIdx.y * 128, bn = blockIdx.x * 128;
    int wm = (wid >> 2) * 64;
    int wn = (wid & 3) * 32;

    int lrow = tid >> 1;
    int lhe  = (tid & 1) * 32;
    const __half* pA = A + (size_t)(bm + lrow) * K + lhe;
    const __half* pB = B + (size_t)(bn + lrow) * K + lhe;
    uint32_t so[4];
#pragma unroll
    for (int i = 0; i < 4; i++)
        so[i] = SWZ((uint32_t)(lrow * 128 + (tid & 1) * 64 + i * 16));

    float acc[4][4][4];
#pragma unroll
    for (int i = 0; i < 4; i++)
#pragma unroll
        for (int j = 0; j < 4; j++)
#pragma unroll
            for (int q = 0; q < 4; q++) acc[i][j][q] = 0.f;

    int aRow = lane & 15;
    int aKb  = (lane >> 4) << 4;
    int bRow = ((lane >> 4) << 3) + (lane & 7);
    int bKb  = ((lane >> 3) & 1) << 4;

    const int KC = K >> 6;

    {
        uint32_t st = sbase;
#pragma unroll
        for (int i = 0; i < 4; i++) {
            CP16(st + so[i],          pA + i * 8);
            CP16(st + TILE_B + so[i], pB + i * 8);
        }
        CP_COMMIT();
    }

    for (int c = 0; c < KC; c++) {
        if (c + 1 < KC) {
            int e = (c + 1) * 64;
            uint32_t st = sbase + ((c + 1) & 1) * GSM_STAGE;
#pragma unroll
            for (int i = 0; i < 4; i++) {
                CP16(st + so[i],          pA + e + i * 8);
                CP16(st + TILE_B + so[i], pB + e + i * 8);
            }
            CP_COMMIT();
            CP_WAIT1();
        } else {
            CP_WAIT0();
        }
        __syncthreads();

        uint32_t st = sbase + (c & 1) * GSM_STAGE;
        uint32_t sA = st, sB = st + TILE_B;

#pragma unroll
        for (int ks = 0; ks < 4; ks++) {
            int kb2 = ks * 32;
            uint32_t ah[4][4], bh[2][4];
#pragma unroll
            for (int mt = 0; mt < 4; mt++) {
                uint32_t off = SWZ((uint32_t)(wm + mt * 16 + aRow) * 128 + kb2 + aKb);
                ldsm_x4(ah[mt], sA + off);
            }
#pragma unroll
            for (int np = 0; np < 2; np++) {
                uint32_t off = SWZ((uint32_t)(wn + np * 16 + bRow) * 128 + kb2 + bKb);
                ldsm_x4(bh[np], sB + off);
            }
#pragma unroll
            for (int mt = 0; mt < 4; mt++) {
#pragma unroll
                for (int nt = 0; nt < 4; nt++) {
                    const uint32_t* pbh = &bh[nt >> 1][(nt & 1) * 2];
                    mma16816(acc[mt][nt], ah[mt], pbh);
                }
            }
        }
        __syncthreads();
    }

    // epilogue
    int mrow0 = bm + wm + (lane >> 2);
    int ncol0 = bn + wn + (lane & 3) * 2;
#pragma unroll
    for (int mt = 0; mt < 4; mt++) {
#pragma unroll
        for (int half = 0; half < 2; half++) {
            int m = mrow0 + mt * 16 + half * 8;
            float* crow = C ? C + (size_t)m * N : nullptr;
            __half* chrow = ch ? ch + (size_t)m * N : nullptr;
            const float* rrow = res ? res + (size_t)m * N : nullptr;
            int mp = m + 1;
            bool doshift = (oh != nullptr) && ((mp & (TT - 1)) != 0);
#pragma unroll
            for (int nt = 0; nt < 4; nt++) {
                int n = ncol0 + nt * 8;
                if (n + 1 < N) {
                    float v0 = acc[mt][nt][half * 2 + 0] + bias[n];
                    float v1 = acc[mt][nt][half * 2 + 1] + bias[n + 1];
                    if (res) { v0 += rrow[n]; v1 += rrow[n + 1]; }
                    if (crow) { crow[n] = v0; crow[n + 1] = v1; }
                    if (chrow) {
                        __half2 hp;
                        hp.x = __float2half_rn(v0);
                        hp.y = __float2half_rn(v1);
                        *(__half2*)(chrow + n) = hp;
                    }
                    if (doshift) {
                        __half2 hp;
                        hp.x = __float2half_rn(v0);
                        hp.y = __float2half_rn(v1);
                        *(__half2*)(oh + (size_t)mp * N + n) = hp;
                    }
                } else if (n < N) {
                    float v0 = acc[mt][nt][half * 2 + 0] + bias[n];
                    if (res) v0 += rrow[n];
                    if (crow) crow[n] = v0;
                    if (chrow) chrow[n] = __float2half_rn(v0);
                }
            }
        }
    }
}

// ---------------- merged weight prep + t=0 Kalman rows ----------------------
#define W1SZ (NT1 * HID)
#define W2SZ (HID * DI)
#define WKSZ (128 * HID)
#define IRSZ (BB * 64)
__global__ void prep_k(const float* __restrict__ in_w, const float* __restrict__ out_w,
                       const float* __restrict__ kp_w1, const float* __restrict__ kg_w1,
                       const float* __restrict__ kp_b1, const float* __restrict__ kg_b1,
                       const float* __restrict__ init_state,
                       __half* __restrict__ w1, __half* __restrict__ w2,
                       __half* __restrict__ wk, float* __restrict__ kb,
                       __half* __restrict__ ph) {
    int idx = blockIdx.x * blockDim.x + threadIdx.x;
    if (idx < W1SZ) {
        int n = idx / HID, k = idx % HID;
        float v = (n < PROJ) ? in_w[(size_t)k * PROJ + n] : 0.f;
        w1[idx] = __float2half_rn(v);
    } else if (idx < W1SZ + W2SZ) {
        int i = idx - W1SZ;
        int n = i / DI, k = i % DI;
        w2[i] = __float2half_rn(out_w[(size_t)k * HID + n]);
    } else if (idx < W1SZ + W2SZ + WKSZ) {
        int i = idx - W1SZ - W2SZ;
        int n = i / HID, k = i % HID;
        float v = (n < 64) ? kp_w1[(size_t)k * 64 + n] : kg_w1[(size_t)k * 64 + (n - 64)];
        wk[i] = __float2half_rn(v);
        if (i < 128) kb[i] = (i < 64) ? kp_b1[i] : kg_b1[i - 64];
    } else if (idx < W1SZ + W2SZ + WKSZ + IRSZ) {
        int i = idx - W1SZ - W2SZ - WKSZ;
        int b = i >> 6, t4 = i & 63;
        float4 v = ((const float4*)init_state)[t4];
        __half hh[4] = {__float2half_rn(v.x), __float2half_rn(v.y),
                        __float2half_rn(v.z), __float2half_rn(v.w)};
        size_t base = (size_t)(b * TT) * HID + t4 * 4;
        *(uint2*)(ph + base) = *(uint2*)hh;
    }
}

// ---------------- 1) rmsnorm -> fp16 (warp per row) -------------------------
__global__ void rmsnorm_cvt_k(const float* __restrict__ x, const float* __restrict__ w,
                              __half* __restrict__ oh) {
    int r = blockIdx.x * 4 + (threadIdx.x >> 5);
    int lane = threadIdx.x & 31;
    const float4* xr = (const float4*)(x + (size_t)r * HID);
    float4 v0 = xr[lane], v1 = xr[lane + 32];
    float ss = v0.x*v0.x + v0.y*v0.y + v0.z*v0.z + v0.w*v0.w
             + v1.x*v1.x + v1.y*v1.y + v1.z*v1.z + v1.w*v1.w;
    ss = warpSum(ss);
    float sc = rsqrtf(ss / HID + 1e-5f);
    const float4* wr = (const float4*)w;
    float4 w0 = wr[lane], w1 = wr[lane + 32];
    __half h0[4] = {__float2half_rn(v0.x*sc*w0.x), __float2half_rn(v0.y*sc*w0.y),
                    __float2half_rn(v0.z*sc*w0.z), __float2half_rn(v0.w*sc*w0.w)};
    __half h1[4] = {__float2half_rn(v1.x*sc*w1.x), __float2half_rn(v1.y*sc*w1.y),
                    __float2half_rn(v1.z*sc*w1.z), __float2half_rn(v1.w*sc*w1.w)};
    size_t base = (size_t)r * HID;
    *(uint2*)(oh + base + lane * 4) = *(uint2*)h0;
    *(uint2*)(oh + base + (lane + 32) * 4) = *(uint2*)h1;
}

// ---------------- 4a) fused conv+silu + chunked scan local pass -------------
__global__ __launch_bounds__(64) void scanA_k(
    const __half* __restrict__ zx, const float* __restrict__ cw,
    const float* __restrict__ cbv,
    const float* __restrict__ dt_bias, const float* __restrict__ A_log,
    const float* __restrict__ Dp, __half* __restrict__ y,
    float* __restrict__ hloc, float* __restrict__ cum, float* __restrict__ bc)
{
    __shared__ float sBC[LC][32];
    __shared__ float sdt[LC];
    int h = blockIdx.x, b = blockIdx.y, c = blockIdx.z;
    int d = threadIdx.x;
    int t0 = c * LC;
    size_t rowbase = (size_t)(b * TT + t0);

    for (int i = d; i < LC * 32; i += 64) {
        int t = i >> 5, j = i & 31;
        int ch = 512 + j;
        float acc = cbv[ch];
#pragma unroll
        for (int k = 0; k < DCONV; k++) {
            int tt = t0 + t - (DCONV - 1) + k;
            if (tt >= 0)
                acc = fmaf(__half2float(zx[((size_t)(b * TT + tt)) * PROJ + DI + ch]),
                           cw[k * CCH + ch], acc);
        }
        float v = siluf(acc);
        sBC[t][j] = v;
        if (h == 0) bc[(rowbase + t) * 32 + j] = v;
    }
    float dtb = dt_bias[h];
    for (int i = d; i < LC; i += 64)
        sdt[i] = softplusf(__half2float(zx[(rowbase + i) * PROJ + 2 * DI + 2 * DS + h]) + dtb);
    __syncthreads();

    int ch = h * HD + d;
    float w0 = cw[0 * CCH + ch], w1 = cw[1 * CCH + ch];
    float w2 = cw[2 * CCH + ch], w3 = cw[3 * CCH + ch];
    float cb0 = cbv[ch];
    const __half* xcol = zx + DI + ch;
    float r0 = 0.f, r1 = 0.f, r2 = 0.f;
    {
        int tb = t0 - 3;
        if (tb >= 0)     r0 = __half2float(xcol[(size_t)(b * TT + tb) * PROJ]);
        if (tb + 1 >= 0) r1 = __half2float(xcol[(size_t)(b * TT + tb + 1) * PROJ]);
        if (tb + 2 >= 0) r2 = __half2float(xcol[(size_t)(b * TT + tb + 2) * PROJ]);
    }

    float A = -__expf(A_log[h]);
    float Dh = Dp[h];
    float hr[DS];
#pragma unroll
    for (int s = 0; s < DS; s++) hr[s] = 0.f;
    float cm = 1.f;

    __half* yp = y + rowbase * DI + h * HD + d;
    float* cmp = cum + ((size_t)(b * NHH + h)) * TT + t0;

    for (int t = 0; t < LC; t++) {
        float raw = __half2float(xcol[(rowbase + t) * PROJ]);
        float x = siluf(fmaf(raw, w3, fmaf(r2, w2, fmaf(r1, w1, fmaf(r0, w0, cb0)))));
        r0 = r1; r1 = r2; r2 = raw;

        float dtsp = sdt[t];
        float dA = __expf(dtsp * A);
        cm *= dA;
        if (d == 0) cmp[t] = cm;
        float dtx = dtsp * x;
        float yvp[4] = {Dh * x, 0.f, 0.f, 0.f};
        float Bv[16], Cv[16];
        *(float4*)&Bv[0]  = *(const float4*)&sBC[t][0];
        *(float4*)&Bv[4]  = *(const float4*)&sBC[t][4];
        *(float4*)&Bv[8]  = *(const float4*)&sBC[t][8];
        *(float4*)&Bv[12] = *(const float4*)&sBC[t][12];
        *(float4*)&Cv[0]  = *(const float4*)&sBC[t][16];
        *(float4*)&Cv[4]  = *(const float4*)&sBC[t][20];
        *(float4*)&Cv[8]  = *(const float4*)&sBC[t][24];
        *(float4*)&Cv[12] = *(const float4*)&sBC[t][28];
#pragma unroll
        for (int s = 0; s < DS; s++) {
            hr[s] = fmaf(hr[s], dA, dtx * Bv[s]);
            yvp[s & 3] = fmaf(hr[s], Cv[s], yvp[s & 3]);
        }
        yp[(size_t)t * DI] = __float2half_rn((yvp[0] + yvp[1]) + (yvp[2] + yvp[3]));
    }

    float* hl = hloc + ((size_t)((b * NHH + h) * NC + c)) * (DS * HD);
#pragma unroll
    for (int s = 0; s < DS; s++) hl[s * HD + d] = hr[s];
}

// ---------------- 4b) chain chunk states ------------------------------------
__global__ __launch_bounds__(64) void scanB_k(const float* __restrict__ hloc,
                                              const float* __restrict__ cum,
                                              float* __restrict__ hstart)
{
    int h = blockIdx.x, b = blockIdx.y, d = threadIdx.x;
    size_t base = (size_t)(b * NHH + h);
    float hs[DS];
#pragma unroll
    for (int s = 0; s < DS; s++) hs[s] = 0.f;
    for (int c = 0; c < NC; c++) {
        float* hsp = hstart + (base * NC + c) * (DS * HD);
#pragma unroll
        for (int s = 0; s < DS; s++) hsp[s * HD + d] = hs[s];
        float P = cum[base * TT + c * LC + LC - 1];
        const float* hl = hloc + (base * NC + c) * (DS * HD);
#pragma unroll
        for (int s = 0; s < DS; s++) hs[s] = fmaf(hs[s], P, hl[s * HD + d]);
    }
}

// ---------------- 4c) correction (fp16 RMW on y) -----------------------------
__global__ __launch_bounds__(64) void scanC_k(const float* __restrict__ bc,
                                              const float* __restrict__ hstart,
                                              const float* __restrict__ cum,
                                              __half* __restrict__ y)
{
    __shared__ float sC[LC][16];
    __shared__ float scm[LC];
    int h = blockIdx.x, b = blockIdx.y, c = blockIdx.z + 1;
    int d = threadIdx.x;
    int t0 = c * LC;
    size_t rowbase = (size_t)(b * TT + t0);
    size_t base = (size_t)(b * NHH + h);

    for (int i = d; i < LC * 16; i += 64) {
        int t = i >> 4, j = i & 15;
        sC[t][j] = bc[(rowbase + t) * 32 + 16 + j];
    }
    for (int i = d; i < LC; i += 64) scm[i] = cum[base * TT + t0 + i];

    float hs[DS];
    const float* hsp = hstart + (base * NC + c) * (DS * HD);
#pragma unroll
    for (int s = 0; s < DS; s++) hs[s] = hsp[s * HD + d];
    __syncthreads();

    __half* yp = y + rowbase * DI + h * HD + d;
    for (int t = 0; t < LC; t++) {
        float Cv[16];
        *(float4*)&Cv[0]  = *(const float4*)&sC[t][0];
        *(float4*)&Cv[4]  = *(const float4*)&sC[t][4];
        *(float4*)&Cv[8]  = *(const float4*)&sC[t][8];
        *(float4*)&Cv[12] = *(const float4*)&sC[t][12];
        float acc = 0.f;
#pragma unroll
        for (int s = 0; s < DS; s++) acc = fmaf(hs[s], Cv[s], acc);
        float v = __half2float(yp[(size_t)t * DI]) + acc * scm[t];
        yp[(size_t)t * DI] = __float2half_rn(v);
    }
}

// ---------------- 5) gate + rmsnorm -> fp16 (warp per row) ------------------
__global__ void gatenorm_cvt_k(const __half* __restrict__ y, const __half* __restrict__ zx,
                               const float* __restrict__ gw,
                               __half* __restrict__ oh) {
    int r = blockIdx.x * 4 + (threadIdx.x >> 5);
    int lane = threadIdx.x & 31;
    const __half* yr = y + (size_t)r * DI;
    const __half* zr = zx + (size_t)r * PROJ;
    float4 g[4];
    float ss = 0.f;
#pragma unroll
    for (int k = 0; k < 4; k++) {
        uint2 yu = *(const uint2*)(yr + (lane + 32 * k) * 4);
        __half2 ya = *(__half2*)&yu.x, yb = *(__half2*)&yu.y;
        uint2 zu = *(const uint2*)(zr + (lane + 32 * k) * 4);
        __half2 za = *(__half2*)&zu.x, zb = *(__half2*)&zu.y;
        g[k].x = __half2float(ya.x) * siluf(__half2float(za.x));
        g[k].y = __half2float(ya.y) * siluf(__half2float(za.y));
        g[k].z = __half2float(yb.x) * siluf(__half2float(zb.x));
        g[k].w = __half2float(yb.y) * siluf(__half2float(zb.y));
        ss += g[k].x*g[k].x + g[k].y*g[k].y + g[k].z*g[k].z + g[k].w*g[k].w;
    }
    ss = warpSum(ss);
    float sc = rsqrtf(ss / DI + 1e-5f);
    const float4* wr = (const float4*)gw;
    size_t base = (size_t)r * DI;
#pragma unroll
    for (int k = 0; k < 4; k++) {
        float4 wv = wr[lane + 32 * k];
        __half hh[4] = {__float2half_rn(g[k].x*sc*wv.x), __float2half_rn(g[k].y*sc*wv.y),
                        __float2half_rn(g[k].z*sc*wv.z), __float2half_rn(g[k].w*sc*wv.w)};
        *(uint2*)(oh + base + (lane + 32 * k) * 4) = *(uint2*)hh;
    }
}

// ---------------- 7b) Kalman finish (warp per row) ---------------------------
__global__ __launch_bounds__(256) void kalman_fin_k(
    const float* __restrict__ AP, const float* __restrict__ z_t,
    const float* __restrict__ kg_w1,
    const float* __restrict__ kp_w2, const float* __restrict__ kp_b2,
    const float* __restrict__ km_w1, const float* __restrict__ km_b1,
    const float* __restrict__ km_w2, const float* __restrict__ km_b2,
    const float* __restrict__ kg_w2, const float* __restrict__ kg_b2,
    const float* __restrict__ kW, float* __restrict__ out)
{
    int r = blockIdx.x * 8 + (threadIdx.x >> 5);
    int lane = threadIdx.x & 31;
    float z = z_t[r];
    const float* aprow = AP + (size_t)r * 128;

    float ap0 = aprow[lane], ap1 = aprow[lane + 32];
    float ag0 = fmaf(z, kg_w1[HID * 64 + lane],      aprow[64 + lane]);
    float ag1 = fmaf(z, kg_w1[HID * 64 + lane + 32], aprow[96 + lane]);
    float vp = siluf(ap0) * kp_w2[lane] + siluf(ap1) * kp_w2[lane + 32];
    float gp = siluf(ag0) * kg_w2[lane] + siluf(ag1) * kg_w2[lane + 32];
    float mp = siluf(fmaf(z, km_w1[lane], km_b1[lane])) * km_w2[lane];
    vp = warpSum(vp);
    gp = warpSum(gp);
    mp = warpSum(mp);
    if (lane == 0) {
        float v_prior = softplusf(vp + kp_b2[0]);
        float Kt = sigmoidf_(gp + kg_b2[0]);
        float m_t = softplusf(mp + km_b2[0]);
        float vpost = v_prior + Kt * (m_t - kW[0] * v_prior);
        vpost = fminf(fmaxf(vpost, 1e-6f), 10.f);
        out[r] = vpost;
    }
}

// ---------------- 8) per-batch softmax reductions ---------------------------
__global__ void reduce_k(float* __restrict__ out) {
    __shared__ float sa[256], sb[256];
    int b = blockIdx.x;
    int tid = threadIdx.x;
    const float* v = out + (size_t)b * TT;
    float v0 = v[tid], v1 = v[tid + 256];

    sa[tid] = fmaxf(v0, v1);
    sb[tid] = fminf(v0, v1);
    __syncthreads();
    for (int s = 128; s > 0; s >>= 1) {
        if (tid < s) {
            sa[tid] = fmaxf(sa[tid], sa[tid + s]);
            sb[tid] = fminf(sb[tid], sb[tid + s]);
        }
        __syncthreads();
    }
    float mx = sa[0], mn = sb[0];
    __syncthreads();

    float e0 = __expf(v0 - mx), e1 = __expf(v1 - mx);
    sa[tid] = e0 + e1;
    sb[tid] = e0 * v0 + e1 * v1;
    __syncthreads();
    for (int s = 128; s > 0; s >>= 1) {
        if (tid < s) { sa[tid] += sa[tid + s]; sb[tid] += sb[tid + s]; }
        __syncthreads();
    }
    float spden = sa[0], spnum = sb[0];
    __syncthreads();

    float f0 = __expf(mn - v0), f1 = __expf(mn - v1);
    sa[tid] = f0 + f1;
    sb[tid] = f0 * v0 + f1 * v1;
    __syncthreads();
    for (int s = 128; s > 0; s >>= 1) {
        if (tid < s) { sa[tid] += sa[tid + s]; sb[tid] += sb[tid + s]; }
        __syncthreads();
    }
    if (tid == 0) {
        out[ROWS + b] = spnum / spden;
        out[ROWS + BB + b] = sb[0] / sa[0];
    }
}

// ---------------- launcher ---------------------------------------------------
extern "C" void kernel_launch(void* const* d_in, const int* in_sizes, int n_in,
                              void* d_out, int out_size) {
    const float* tokens   = (const float*)d_in[0];
    const float* z_t      = (const float*)d_in[1];
    const float* norm_w   = (const float*)d_in[2];
    const float* in_w     = (const float*)d_in[3];
    const float* in_b     = (const float*)d_in[4];
    const float* conv_w   = (const float*)d_in[5];
    const float* conv_b   = (const float*)d_in[6];
    const float* dt_bias  = (const float*)d_in[7];
    const float* A_log    = (const float*)d_in[8];
    const float* Dp       = (const float*)d_in[9];
    const float* gnorm_w  = (const float*)d_in[10];
    const float* out_w    = (const float*)d_in[11];
    const float* out_b    = (const float*)d_in[12];
    const float* kp_w1    = (const float*)d_in[13];
    const float* kp_b1    = (const float*)d_in[14];
    const float* kp_w2    = (const float*)d_in[15];
    const float* kp_b2    = (const float*)d_in[16];
    const float* km_w1    = (const float*)d_in[17];
    const float* km_b1    = (const float*)d_in[18];
    const float* km_w2    = (const float*)d_in[19];
    const float* km_b2    = (const float*)d_in[20];
    const float* kg_w1    = (const float*)d_in[21];
    const float* kg_b1    = (const float*)d_in[22];
    const float* kg_w2    = (const float*)d_in[23];
    const float* kg_b2    = (const float*)d_in[24];
    const float* kW       = (const float*)d_in[25];
    const float* init_st  = (const float*)d_in[26];
    float* out = (float*)d_out;

    float *bc, *hloc, *hstart, *cum, *ap, *kb;
    __half *zx, *y, *xh, *yh, *ph, *wt1, *wt2, *wk;
    cudaGetSymbolAddress((void**)&zx,     g_zx);
    cudaGetSymbolAddress((void**)&y,      g_y);
    cudaGetSymbolAddress((void**)&bc,     g_bc);
    cudaGetSymbolAddress((void**)&hloc,   g_hloc);
    cudaGetSymbolAddress((void**)&hstart, g_hstart);
    cudaGetSymbolAddress((void**)&cum,    g_cum);
    cudaGetSymbolAddress((void**)&ap,     g_ap);
    cudaGetSymbolAddress((void**)&kb,     g_kb);
    cudaGetSymbolAddress((void**)&xh,     g_xh);
    cudaGetSymbolAddress((void**)&yh,     g_yh);
    cudaGetSymbolAddress((void**)&ph,     g_ph);
    cudaGetSymbolAddress((void**)&wt1,    g_wt1);
    cudaGetSymbolAddress((void**)&wt2,    g_wt2);
    cudaGetSymbolAddress((void**)&wk,     g_wk);

    cudaFuncSetAttribute(gemm_mma, cudaFuncAttributeMaxDynamicSharedMemorySize,
                         2 * GSM_STAGE);

    // weight prep (merged, single fp16) + t=0 Kalman rows
    prep_k<<<(W1SZ + W2SZ + WKSZ + IRSZ + 255) / 256, 256>>>(
        in_w, out_w, kp_w1, kg_w1, kp_b1, kg_b1, init_st,
        wt1, wt2, wk, kb, ph);

    // 1) rmsnorm -> fp16 (warp per row)
    rmsnorm_cvt_k<<<ROWS / 4, 128>>>(tokens, norm_w, xh);
    // 2) in-proj GEMM -> fp16 zx
    gemm_mma<<<dim3(NT1 / 128, ROWS / 128), 256, 2 * GSM_STAGE>>>(
        xh, wt1, in_b, nullptr, nullptr, zx, nullptr, HID, PROJ);
    // 3+4) fused conv + chunked scan (y in fp16)
    scanA_k<<<dim3(NHH, BB, NC), 64>>>(zx, conv_w, conv_b, dt_bias, A_log, Dp,
                                       y, hloc, cum, bc);
    scanB_k<<<dim3(NHH, BB), 64>>>(hloc, cum, hstart);
    scanC_k<<<dim3(NHH, BB, NC - 1), 64>>>(bc, hstart, cum, y);
    // 5) gate + rmsnorm (warp per row)
    gatenorm_cvt_k<<<ROWS / 4, 128>>>(y, zx, gnorm_w, yh);
    // 6) out-proj GEMM + residual, fused shift+cvt into ph
    gemm_mma<<<dim3(HID / 128, ROWS / 128), 256, 2 * GSM_STAGE>>>(
        yh, wt2, out_b, tokens, nullptr, nullptr, ph, DI, HID);
    // 7) Kalman GEMM -> finish (warp per row)
    gemm_mma<<<dim3(1, ROWS / 128), 256, 2 * GSM_STAGE>>>(
        ph, wk, kb, nullptr, ap, nullptr, nullptr, HID, 128);
    kalman_fin_k<<<ROWS / 8, 256>>>(ap, z_t, kg_w1,
                                    kp_w2, kp_b2, km_w1, km_b1, km_w2, km_b2,
                                    kg_w2, kg_b2, kW, out);
    // 8) per-batch reductions
    reduce_k<<<BB, 256>>>(out);
}

// round 16
// speedup vs baseline: 1.6884x; 1.0353x over previous
#include <cuda_runtime.h>
#include <cuda_fp16.h>
#include <cstdint>

#define BB    64
#define TT    512
#define HID   256
#define DI    512
#define DS    16
#define NHH   8
#define HD    64
#define DCONV 4
#define CCH   544    // DI + 2*DS
#define PROJ  1064   // 2*DI + 2*DS + NH
#define ROWS  (BB*TT) // 32768
#define NC    16
#define LC    32     // TT/NC
#define NT1   1152   // PROJ padded to 9*128

// ---------------- scratch (device globals; no allocation allowed) ----------
__device__ __align__(16) __half g_zx[ROWS * PROJ];
__device__ __align__(16) __half g_y[ROWS * DI];
__device__ __align__(16) float g_bc[ROWS * 32];
__device__ __align__(16) float g_hloc[BB * NHH * NC * HD * DS];
__device__ __align__(16) float g_hstart[BB * NHH * NC * HD * DS];
__device__ __align__(16) float g_cum[BB * NHH * TT];
__device__ __align__(16) __half g_xh[ROWS * HID];
__device__ __align__(16) __half g_yh[ROWS * DI];
__device__ __align__(16) __half g_ph[ROWS * HID];
__device__ __align__(16) float g_ap[ROWS * 128];
__device__ __align__(16) __half g_wt1[NT1 * HID];
__device__ __align__(16) __half g_wt2[HID * DI];
__device__ __align__(16) __half g_wk[128 * HID];
__device__ __align__(16) float g_kb[128];

// ---------------- helpers ---------------------------------------------------
__device__ __forceinline__ float siluf(float x) { return x / (1.f + __expf(-x)); }
__device__ __forceinline__ float softplusf(float x) {
    return (x > 20.f) ? x : log1pf(__expf(x));
}
__device__ __forceinline__ float sigmoidf_(float x) { return 1.f / (1.f + __expf(-x)); }
__device__ __forceinline__ float warpSum(float v) {
#pragma unroll
    for (int o = 16; o; o >>= 1) v += __shfl_xor_sync(0xffffffffu, v, o);
    return v;
}
__device__ __forceinline__ uint32_t smem_u32(const void* p) {
    uint32_t a;
    asm("{ .reg .u64 t; cvta.to.shared.u64 t, %1; cvt.u32.u64 %0, t; }"
        : "=r"(a) : "l"(p));
    return a;
}
#define SWZ(b) ((b) ^ (((b) >> 3) & 0x70))

__device__ __forceinline__ void ldsm_x4(uint32_t* r, uint32_t addr) {
    asm volatile("ldmatrix.sync.aligned.m8n8.x4.shared.b16 {%0,%1,%2,%3}, [%4];"
                 : "=r"(r[0]), "=r"(r[1]), "=r"(r[2]), "=r"(r[3]) : "r"(addr));
}
__device__ __forceinline__ void mma16816(float* c, const uint32_t* a, const uint32_t* b) {
    asm volatile("mma.sync.aligned.m16n8k16.row.col.f32.f16.f16.f32 "
                 "{%0,%1,%2,%3}, {%4,%5,%6,%7}, {%8,%9}, {%0,%1,%2,%3};"
                 : "+f"(c[0]), "+f"(c[1]), "+f"(c[2]), "+f"(c[3])
                 : "r"(a[0]), "r"(a[1]), "r"(a[2]), "r"(a[3]), "r"(b[0]), "r"(b[1]));
}
#define CP16(sa, gp) \
    asm volatile("cp.async.cg.shared.global [%0], [%1], 16;" :: "r"(sa), "l"(gp))
#define CP_COMMIT() asm volatile("cp.async.commit_group;" ::: "memory")
#define CP_WAIT1() asm volatile("cp.async.wait_group 1;" ::: "memory")
#define CP_WAIT0() asm volatile("cp.async.wait_group 0;" ::: "memory")

// ---------------- fp16 GEMM via mma.sync, cp.async 2-stage ------------------
#define TILE_B 16384
#define GSM_STAGE (2 * TILE_B)
__global__ __launch_bounds__(256, 2) void gemm_mma(
    const __half* __restrict__ A, const __half* __restrict__ B,
    const float* __restrict__ bias, const float* __restrict__ res,
    float* __restrict__ C, __half* __restrict__ ch, __half* __restrict__ oh,
    int K, int N)
{
    extern __shared__ __align__(16) uint8_t dsm[];
    uint32_t sbase = smem_u32(dsm);

    int tid = threadIdx.x;
    int wid = tid >> 5, lane = tid & 31;
    int bm = blockIdx.y * 128, bn = blockIdx.x * 128;
    int wm = (wid >> 2) * 64;
    int wn = (wid & 3) * 32;

    int lrow = tid >> 1;
    int lhe  = (tid & 1) * 32;
    const __half* pA = A + (size_t)(bm + lrow) * K + lhe;
    const __half* pB = B + (size_t)(bn + lrow) * K + lhe;
    uint32_t so[4];
#pragma unroll
    for (int i = 0; i < 4; i++)
        so[i] = SWZ((uint32_t)(lrow * 128 + (tid & 1) * 64 + i * 16));

    float acc[4][4][4];
#pragma unroll
    for (int i = 0; i < 4; i++)
#pragma unroll
        for (int j = 0; j < 4; j++)
#pragma unroll
            for (int q = 0; q < 4; q++) acc[i][j][q] = 0.f;

    int aRow = lane & 15;
    int aKb  = (lane >> 4) << 4;
    int bRow = ((lane >> 4) << 3) + (lane & 7);
    int bKb  = ((lane >> 3) & 1) << 4;

    const int KC = K >> 6;

    {
        uint32_t st = sbase;
#pragma unroll
        for (int i = 0; i < 4; i++) {
            CP16(st + so[i],          pA + i * 8);
            CP16(st + TILE_B + so[i], pB + i * 8);
        }
        CP_COMMIT();
    }

    for (int c = 0; c < KC; c++) {
        if (c + 1 < KC) {
            int e = (c + 1) * 64;
            uint32_t st = sbase + ((c + 1) & 1) * GSM_STAGE;
#pragma unroll
            for (int i = 0; i < 4; i++) {
                CP16(st + so[i],          pA + e + i * 8);
                CP16(st + TILE_B + so[i], pB + e + i * 8);
            }
            CP_COMMIT();
            CP_WAIT1();
        } else {
            CP_WAIT0();
        }
        __syncthreads();

        uint32_t st = sbase + (c & 1) * GSM_STAGE;
        uint32_t sA = st, sB = st + TILE_B;

#pragma unroll
        for (int ks = 0; ks < 4; ks++) {
            int kb2 = ks * 32;
            uint32_t ah[4][4], bh[2][4];
#pragma unroll
            for (int mt = 0; mt < 4; mt++) {
                uint32_t off = SWZ((uint32_t)(wm + mt * 16 + aRow) * 128 + kb2 + aKb);
                ldsm_x4(ah[mt], sA + off);
            }
#pragma unroll
            for (int np = 0; np < 2; np++) {
                uint32_t off = SWZ((uint32_t)(wn + np * 16 + bRow) * 128 + kb2 + bKb);
                ldsm_x4(bh[np], sB + off);
            }
#pragma unroll
            for (int mt = 0; mt < 4; mt++) {
#pragma unroll
                for (int nt = 0; nt < 4; nt++) {
                    const uint32_t* pbh = &bh[nt >> 1][(nt & 1) * 2];
                    mma16816(acc[mt][nt], ah[mt], pbh);
                }
            }
        }
        __syncthreads();
    }

    int mrow0 = bm + wm + (lane >> 2);
    int ncol0 = bn + wn + (lane & 3) * 2;
#pragma unroll
    for (int mt = 0; mt < 4; mt++) {
#pragma unroll
        for (int half = 0; half < 2; half++) {
            int m = mrow0 + mt * 16 + half * 8;
            float* crow = C ? C + (size_t)m * N : nullptr;
            __half* chrow = ch ? ch + (size_t)m * N : nullptr;
            const float* rrow = res ? res + (size_t)m * N : nullptr;
            int mp = m + 1;
            bool doshift = (oh != nullptr) && ((mp & (TT - 1)) != 0);
#pragma unroll
            for (int nt = 0; nt < 4; nt++) {
                int n = ncol0 + nt * 8;
                if (n + 1 < N) {
                    float v0 = acc[mt][nt][half * 2 + 0] + bias[n];
                    float v1 = acc[mt][nt][half * 2 + 1] + bias[n + 1];
                    if (res) { v0 += rrow[n]; v1 += rrow[n + 1]; }
                    if (crow) { crow[n] = v0; crow[n + 1] = v1; }
                    if (chrow) {
                        __half2 hp;
                        hp.x = __float2half_rn(v0);
                        hp.y = __float2half_rn(v1);
                        *(__half2*)(chrow + n) = hp;
                    }
                    if (doshift) {
                        __half2 hp;
                        hp.x = __float2half_rn(v0);
                        hp.y = __float2half_rn(v1);
                        *(__half2*)(oh + (size_t)mp * N + n) = hp;
                    }
                } else if (n < N) {
                    float v0 = acc[mt][nt][half * 2 + 0] + bias[n];
                    if (res) v0 += rrow[n];
                    if (crow) crow[n] = v0;
                    if (chrow) chrow[n] = __float2half_rn(v0);
                }
            }
        }
    }
}

// ---------------- merged weight prep + t=0 Kalman rows ----------------------
#define W1SZ (NT1 * HID)
#define W2SZ (HID * DI)
#define WKSZ (128 * HID)
#define IRSZ (BB * 64)
__global__ void prep_k(const float* __restrict__ in_w, const float* __restrict__ out_w,
                       const float* __restrict__ kp_w1, const float* __restrict__ kg_w1,
                       const float* __restrict__ kp_b1, const float* __restrict__ kg_b1,
                       const float* __restrict__ init_state,
                       __half* __restrict__ w1, __half* __restrict__ w2,
                       __half* __restrict__ wk, float* __restrict__ kb,
                       __half* __restrict__ ph) {
    int idx = blockIdx.x * blockDim.x + threadIdx.x;
    if (idx < W1SZ) {
        int n = idx / HID, k = idx % HID;
        float v = (n < PROJ) ? in_w[(size_t)k * PROJ + n] : 0.f;
        w1[idx] = __float2half_rn(v);
    } else if (idx < W1SZ + W2SZ) {
        int i = idx - W1SZ;
        int n = i / DI, k = i % DI;
        w2[i] = __float2half_rn(out_w[(size_t)k * HID + n]);
    } else if (idx < W1SZ + W2SZ + WKSZ) {
        int i = idx - W1SZ - W2SZ;
        int n = i / HID, k = i % HID;
        float v = (n < 64) ? kp_w1[(size_t)k * 64 + n] : kg_w1[(size_t)k * 64 + (n - 64)];
        wk[i] = __float2half_rn(v);
        if (i < 128) kb[i] = (i < 64) ? kp_b1[i] : kg_b1[i - 64];
    } else if (idx < W1SZ + W2SZ + WKSZ + IRSZ) {
        int i = idx - W1SZ - W2SZ - WKSZ;
        int b = i >> 6, t4 = i & 63;
        float4 v = ((const float4*)init_state)[t4];
        __half hh[4] = {__float2half_rn(v.x), __float2half_rn(v.y),
                        __float2half_rn(v.z), __float2half_rn(v.w)};
        size_t base = (size_t)(b * TT) * HID + t4 * 4;
        *(uint2*)(ph + base) = *(uint2*)hh;
    }
}

// ---------------- 1) rmsnorm -> fp16 (warp per row) -------------------------
__global__ void rmsnorm_cvt_k(const float* __restrict__ x, const float* __restrict__ w,
                              __half* __restrict__ oh) {
    int r = blockIdx.x * 4 + (threadIdx.x >> 5);
    int lane = threadIdx.x & 31;
    const float4* xr = (const float4*)(x + (size_t)r * HID);
    float4 v0 = xr[lane], v1 = xr[lane + 32];
    float ss = v0.x*v0.x + v0.y*v0.y + v0.z*v0.z + v0.w*v0.w
             + v1.x*v1.x + v1.y*v1.y + v1.z*v1.z + v1.w*v1.w;
    ss = warpSum(ss);
    float sc = rsqrtf(ss / HID + 1e-5f);
    const float4* wr = (const float4*)w;
    float4 w0 = wr[lane], w1 = wr[lane + 32];
    __half h0[4] = {__float2half_rn(v0.x*sc*w0.x), __float2half_rn(v0.y*sc*w0.y),
                    __float2half_rn(v0.z*sc*w0.z), __float2half_rn(v0.w*sc*w0.w)};
    __half h1[4] = {__float2half_rn(v1.x*sc*w1.x), __float2half_rn(v1.y*sc*w1.y),
                    __float2half_rn(v1.z*sc*w1.z), __float2half_rn(v1.w*sc*w1.w)};
    size_t base = (size_t)r * HID;
    *(uint2*)(oh + base + lane * 4) = *(uint2*)h0;
    *(uint2*)(oh + base + (lane + 32) * 4) = *(uint2*)h1;
}

// ---------------- 4a) fused conv+silu + chunked scan local pass --------------
// One block per (b, chunk): 512 threads = 8 heads x 64 dims. B/C conv computed
// once per block (was 8x redundant).
__global__ __launch_bounds__(512) void scanA_k(
    const __half* __restrict__ zx, const float* __restrict__ cw,
    const float* __restrict__ cbv,
    const float* __restrict__ dt_bias, const float* __restrict__ A_log,
    const float* __restrict__ Dp, __half* __restrict__ y,
    float* __restrict__ hloc, float* __restrict__ cum, float* __restrict__ bc)
{
    __shared__ float sBC[LC][32];
    __shared__ float sdt[NHH][LC];
    int b = blockIdx.x, c = blockIdx.y;
    int tid = threadIdx.x;
    int h = tid >> 6, d = tid & 63;
    int t0 = c * LC;
    size_t rowbase = (size_t)(b * TT + t0);

    // B/C with inline conv (channels 512..543) — once per (b,c)
    for (int i = tid; i < LC * 32; i += 512) {
        int t = i >> 5, j = i & 31;
        int ch = 512 + j;
        float acc = cbv[ch];
#pragma unroll
        for (int k = 0; k < DCONV; k++) {
            int tt = t0 + t - (DCONV - 1) + k;
            if (tt >= 0)
                acc = fmaf(__half2float(zx[((size_t)(b * TT + tt)) * PROJ + DI + ch]),
                           cw[k * CCH + ch], acc);
        }
        float v = siluf(acc);
        sBC[t][j] = v;
        bc[(rowbase + t) * 32 + j] = v;
    }
    // per-head dt: NHH*LC = 256 elements
    for (int i = tid; i < NHH * LC; i += 512) {
        int hh = i >> 5, t = i & 31;
        sdt[hh][t] = softplusf(
            __half2float(zx[(rowbase + t) * PROJ + 2 * DI + 2 * DS + hh]) + dt_bias[hh]);
    }
    __syncthreads();

    int ch = h * HD + d;
    float w0 = cw[0 * CCH + ch], w1 = cw[1 * CCH + ch];
    float w2 = cw[2 * CCH + ch], w3 = cw[3 * CCH + ch];
    float cb0 = cbv[ch];
    const __half* xcol = zx + DI + ch;
    float r0 = 0.f, r1 = 0.f, r2 = 0.f;
    {
        int tb = t0 - 3;
        if (tb >= 0)     r0 = __half2float(xcol[(size_t)(b * TT + tb) * PROJ]);
        if (tb + 1 >= 0) r1 = __half2float(xcol[(size_t)(b * TT + tb + 1) * PROJ]);
        if (tb + 2 >= 0) r2 = __half2float(xcol[(size_t)(b * TT + tb + 2) * PROJ]);
    }

    float A = -__expf(A_log[h]);
    float Dh = Dp[h];
    float hr[DS];
#pragma unroll
    for (int s = 0; s < DS; s++) hr[s] = 0.f;
    float cm = 1.f;

    __half* yp = y + rowbase * DI + h * HD + d;
    float* cmp = cum + ((size_t)(b * NHH + h)) * TT + t0;

    for (int t = 0; t < LC; t++) {
        float raw = __half2float(xcol[(rowbase + t) * PROJ]);
        float x = siluf(fmaf(raw, w3, fmaf(r2, w2, fmaf(r1, w1, fmaf(r0, w0, cb0)))));
        r0 = r1; r1 = r2; r2 = raw;

        float dtsp = sdt[h][t];
        float dA = __expf(dtsp * A);
        cm *= dA;
        if (d == 0) cmp[t] = cm;
        float dtx = dtsp * x;
        float yvp[4] = {Dh * x, 0.f, 0.f, 0.f};
        float Bv[16], Cv[16];
        *(float4*)&Bv[0]  = *(const float4*)&sBC[t][0];
        *(float4*)&Bv[4]  = *(const float4*)&sBC[t][4];
        *(float4*)&Bv[8]  = *(const float4*)&sBC[t][8];
        *(float4*)&Bv[12] = *(const float4*)&sBC[t][12];
        *(float4*)&Cv[0]  = *(const float4*)&sBC[t][16];
        *(float4*)&Cv[4]  = *(const float4*)&sBC[t][20];
        *(float4*)&Cv[8]  = *(const float4*)&sBC[t][24];
        *(float4*)&Cv[12] = *(const float4*)&sBC[t][28];
#pragma unroll
        for (int s = 0; s < DS; s++) {
            hr[s] = fmaf(hr[s], dA, dtx * Bv[s]);
            yvp[s & 3] = fmaf(hr[s], Cv[s], yvp[s & 3]);
        }
        yp[(size_t)t * DI] = __float2half_rn((yvp[0] + yvp[1]) + (yvp[2] + yvp[3]));
    }

    float* hl = hloc + ((size_t)((b * NHH + h) * NC + c)) * (DS * HD);
#pragma unroll
    for (int s = 0; s < DS; s++) hl[s * HD + d] = hr[s];
}

// ---------------- 4b) chain chunk states ------------------------------------
__global__ __launch_bounds__(64) void scanB_k(const float* __restrict__ hloc,
                                              const float* __restrict__ cum,
                                              float* __restrict__ hstart)
{
    int h = blockIdx.x, b = blockIdx.y, d = threadIdx.x;
    size_t base = (size_t)(b * NHH + h);
    float hs[DS];
#pragma unroll
    for (int s = 0; s < DS; s++) hs[s] = 0.f;
    for (int c = 0; c < NC; c++) {
        float* hsp = hstart + (base * NC + c) * (DS * HD);
#pragma unroll
        for (int s = 0; s < DS; s++) hsp[s * HD + d] = hs[s];
        float P = cum[base * TT + c * LC + LC - 1];
        const float* hl = hloc + (base * NC + c) * (DS * HD);
#pragma unroll
        for (int s = 0; s < DS; s++) hs[s] = fmaf(hs[s], P, hl[s * HD + d]);
    }
}

// ---------------- 4c) correction (fp16 RMW on y) -----------------------------
__global__ __launch_bounds__(64) void scanC_k(const float* __restrict__ bc,
                                              const float* __restrict__ hstart,
                                              const float* __restrict__ cum,
                                              __half* __restrict__ y)
{
    __shared__ float sC[LC][16];
    __shared__ float scm[LC];
    int h = blockIdx.x, b = blockIdx.y, c = blockIdx.z + 1;
    int d = threadIdx.x;
    int t0 = c * LC;
    size_t rowbase = (size_t)(b * TT + t0);
    size_t base = (size_t)(b * NHH + h);

    for (int i = d; i < LC * 16; i += 64) {
        int t = i >> 4, j = i & 15;
        sC[t][j] = bc[(rowbase + t) * 32 + 16 + j];
    }
    for (int i = d; i < LC; i += 64) scm[i] = cum[base * TT + t0 + i];

    float hs[DS];
    const float* hsp = hstart + (base * NC + c) * (DS * HD);
#pragma unroll
    for (int s = 0; s < DS; s++) hs[s] = hsp[s * HD + d];
    __syncthreads();

    __half* yp = y + rowbase * DI + h * HD + d;
    for (int t = 0; t < LC; t++) {
        float Cv[16];
        *(float4*)&Cv[0]  = *(const float4*)&sC[t][0];
        *(float4*)&Cv[4]  = *(const float4*)&sC[t][4];
        *(float4*)&Cv[8]  = *(const float4*)&sC[t][8];
        *(float4*)&Cv[12] = *(const float4*)&sC[t][12];
        float acc = 0.f;
#pragma unroll
        for (int s = 0; s < DS; s++) acc = fmaf(hs[s], Cv[s], acc);
        float v = __half2float(yp[(size_t)t * DI]) + acc * scm[t];
        yp[(size_t)t * DI] = __float2half_rn(v);
    }
}

// ---------------- 5) gate + rmsnorm -> fp16 (warp per row) ------------------
__global__ void gatenorm_cvt_k(const __half* __restrict__ y, const __half* __restrict__ zx,
                               const float* __restrict__ gw,
                               __half* __restrict__ oh) {
    int r = blockIdx.x * 4 + (threadIdx.x >> 5);
    int lane = threadIdx.x & 31;
    const __half* yr = y + (size_t)r * DI;
    const __half* zr = zx + (size_t)r * PROJ;
    float4 g[4];
    float ss = 0.f;
#pragma unroll
    for (int k = 0; k < 4; k++) {
        uint2 yu = *(const uint2*)(yr + (lane + 32 * k) * 4);
        __half2 ya = *(__half2*)&yu.x, yb = *(__half2*)&yu.y;
        uint2 zu = *(const uint2*)(zr + (lane + 32 * k) * 4);
        __half2 za = *(__half2*)&zu.x, zb = *(__half2*)&zu.y;
        g[k].x = __half2float(ya.x) * siluf(__half2float(za.x));
        g[k].y = __half2float(ya.y) * siluf(__half2float(za.y));
        g[k].z = __half2float(yb.x) * siluf(__half2float(zb.x));
        g[k].w = __half2float(yb.y) * siluf(__half2float(zb.y));
        ss += g[k].x*g[k].x + g[k].y*g[k].y + g[k].z*g[k].z + g[k].w*g[k].w;
    }
    ss = warpSum(ss);
    float sc = rsqrtf(ss / DI + 1e-5f);
    const float4* wr = (const float4*)gw;
    size_t base = (size_t)r * DI;
#pragma unroll
    for (int k = 0; k < 4; k++) {
        float4 wv = wr[lane + 32 * k];
        __half hh[4] = {__float2half_rn(g[k].x*sc*wv.x), __float2half_rn(g[k].y*sc*wv.y),
                        __float2half_rn(g[k].z*sc*wv.z), __float2half_rn(g[k].w*sc*wv.w)};
        *(uint2*)(oh + base + (lane + 32 * k) * 4) = *(uint2*)hh;
    }
}

// ---------------- 7b) Kalman finish (warp per row) ---------------------------
__global__ __launch_bounds__(256) void kalman_fin_k(
    const float* __restrict__ AP, const float* __restrict__ z_t,
    const float* __restrict__ kg_w1,
    const float* __restrict__ kp_w2, const float* __restrict__ kp_b2,
    const float* __restrict__ km_w1, const float* __restrict__ km_b1,
    const float* __restrict__ km_w2, const float* __restrict__ km_b2,
    const float* __restrict__ kg_w2, const float* __restrict__ kg_b2,
    const float* __restrict__ kW, float* __restrict__ out)
{
    int r = blockIdx.x * 8 + (threadIdx.x >> 5);
    int lane = threadIdx.x & 31;
    float z = z_t[r];
    const float* aprow = AP + (size_t)r * 128;

    float ap0 = aprow[lane], ap1 = aprow[lane + 32];
    float ag0 = fmaf(z, kg_w1[HID * 64 + lane],      aprow[64 + lane]);
    float ag1 = fmaf(z, kg_w1[HID * 64 + lane + 32], aprow[96 + lane]);
    float vp = siluf(ap0) * kp_w2[lane] + siluf(ap1) * kp_w2[lane + 32];
    float gp = siluf(ag0) * kg_w2[lane] + siluf(ag1) * kg_w2[lane + 32];
    float mp = siluf(fmaf(z, km_w1[lane], km_b1[lane])) * km_w2[lane];
    vp = warpSum(vp);
    gp = warpSum(gp);
    mp = warpSum(mp);
    if (lane == 0) {
        float v_prior = softplusf(vp + kp_b2[0]);
        float Kt = sigmoidf_(gp + kg_b2[0]);
        float m_t = softplusf(mp + km_b2[0]);
        float vpost = v_prior + Kt * (m_t - kW[0] * v_prior);
        vpost = fminf(fmaxf(vpost, 1e-6f), 10.f);
        out[r] = vpost;
    }
}

// ---------------- 8) per-batch softmax reductions ---------------------------
__global__ void reduce_k(float* __restrict__ out) {
    __shared__ float sa[256], sb[256];
    int b = blockIdx.x;
    int tid = threadIdx.x;
    const float* v = out + (size_t)b * TT;
    float v0 = v[tid], v1 = v[tid + 256];

    sa[tid] = fmaxf(v0, v1);
    sb[tid] = fminf(v0, v1);
    __syncthreads();
    for (int s = 128; s > 0; s >>= 1) {
        if (tid < s) {
            sa[tid] = fmaxf(sa[tid], sa[tid + s]);
            sb[tid] = fminf(sb[tid], sb[tid + s]);
        }
        __syncthreads();
    }
    float mx = sa[0], mn = sb[0];
    __syncthreads();

    float e0 = __expf(v0 - mx), e1 = __expf(v1 - mx);
    sa[tid] = e0 + e1;
    sb[tid] = e0 * v0 + e1 * v1;
    __syncthreads();
    for (int s = 128; s > 0; s >>= 1) {
        if (tid < s) { sa[tid] += sa[tid + s]; sb[tid] += sb[tid + s]; }
        __syncthreads();
    }
    float spden = sa[0], spnum = sb[0];
    __syncthreads();

    float f0 = __expf(mn - v0), f1 = __expf(mn - v1);
    sa[tid] = f0 + f1;
    sb[tid] = f0 * v0 + f1 * v1;
    __syncthreads();
    for (int s = 128; s > 0; s >>= 1) {
        if (tid < s) { sa[tid] += sa[tid + s]; sb[tid] += sb[tid + s]; }
        __syncthreads();
    }
    if (tid == 0) {
        out[ROWS + b] = spnum / spden;
        out[ROWS + BB + b] = sb[0] / sa[0];
    }
}

// ---------------- launcher ---------------------------------------------------
extern "C" void kernel_launch(void* const* d_in, const int* in_sizes, int n_in,
                              void* d_out, int out_size) {
    const float* tokens   = (const float*)d_in[0];
    const float* z_t      = (const float*)d_in[1];
    const float* norm_w   = (const float*)d_in[2];
    const float* in_w     = (const float*)d_in[3];
    const float* in_b     = (const float*)d_in[4];
    const float* conv_w   = (const float*)d_in[5];
    const float* conv_b   = (const float*)d_in[6];
    const float* dt_bias  = (const float*)d_in[7];
    const float* A_log    = (const float*)d_in[8];
    const float* Dp       = (const float*)d_in[9];
    const float* gnorm_w  = (const float*)d_in[10];
    const float* out_w    = (const float*)d_in[11];
    const float* out_b    = (const float*)d_in[12];
    const float* kp_w1    = (const float*)d_in[13];
    const float* kp_b1    = (const float*)d_in[14];
    const float* kp_w2    = (const float*)d_in[15];
    const float* kp_b2    = (const float*)d_in[16];
    const float* km_w1    = (const float*)d_in[17];
    const float* km_b1    = (const float*)d_in[18];
    const float* km_w2    = (const float*)d_in[19];
    const float* km_b2    = (const float*)d_in[20];
    const float* kg_w1    = (const float*)d_in[21];
    const float* kg_b1    = (const float*)d_in[22];
    const float* kg_w2    = (const float*)d_in[23];
    const float* kg_b2    = (const float*)d_in[24];
    const float* kW       = (const float*)d_in[25];
    const float* init_st  = (const float*)d_in[26];
    float* out = (float*)d_out;

    float *bc, *hloc, *hstart, *cum, *ap, *kb;
    __half *zx, *y, *xh, *yh, *ph, *wt1, *wt2, *wk;
    cudaGetSymbolAddress((void**)&zx,     g_zx);
    cudaGetSymbolAddress((void**)&y,      g_y);
    cudaGetSymbolAddress((void**)&bc,     g_bc);
    cudaGetSymbolAddress((void**)&hloc,   g_hloc);
    cudaGetSymbolAddress((void**)&hstart, g_hstart);
    cudaGetSymbolAddress((void**)&cum,    g_cum);
    cudaGetSymbolAddress((void**)&ap,     g_ap);
    cudaGetSymbolAddress((void**)&kb,     g_kb);
    cudaGetSymbolAddress((void**)&xh,     g_xh);
    cudaGetSymbolAddress((void**)&yh,     g_yh);
    cudaGetSymbolAddress((void**)&ph,     g_ph);
    cudaGetSymbolAddress((void**)&wt1,    g_wt1);
    cudaGetSymbolAddress((void**)&wt2,    g_wt2);
    cudaGetSymbolAddress((void**)&wk,     g_wk);

    cudaFuncSetAttribute(gemm_mma, cudaFuncAttributeMaxDynamicSharedMemorySize,
                         2 * GSM_STAGE);

    // weight prep (merged, single fp16) + t=0 Kalman rows
    prep_k<<<(W1SZ + W2SZ + WKSZ + IRSZ + 255) / 256, 256>>>(
        in_w, out_w, kp_w1, kg_w1, kp_b1, kg_b1, init_st,
        wt1, wt2, wk, kb, ph);

    // 1) rmsnorm -> fp16 (warp per row)
    rmsnorm_cvt_k<<<ROWS / 4, 128>>>(tokens, norm_w, xh);
    // 2) in-proj GEMM -> fp16 zx
    gemm_mma<<<dim3(NT1 / 128, ROWS / 128), 256, 2 * GSM_STAGE>>>(
        xh, wt1, in_b, nullptr, nullptr, zx, nullptr, HID, PROJ);
    // 3+4) fused conv + chunked scan (one block per (b,c), 8 heads/block)
    scanA_k<<<dim3(BB, NC), 512>>>(zx, conv_w, conv_b, dt_bias, A_log, Dp,
                                   y, hloc, cum, bc);
    scanB_k<<<dim3(NHH, BB), 64>>>(hloc, cum, hstart);
    scanC_k<<<dim3(NHH, BB, NC - 1), 64>>>(bc, hstart, cum, y);
    // 5) gate + rmsnorm (warp per row)
    gatenorm_cvt_k<<<ROWS / 4, 128>>>(y, zx, gnorm_w, yh);
    // 6) out-proj GEMM + residual, fused shift+cvt into ph
    gemm_mma<<<dim3(HID / 128, ROWS / 128), 256, 2 * GSM_STAGE>>>(
        yh, wt2, out_b, tokens, nullptr, nullptr, ph, DI, HID);
    // 7) Kalman GEMM -> finish (warp per row)
    gemm_mma<<<dim3(1, ROWS / 128), 256, 2 * GSM_STAGE>>>(
        ph, wk, kb, nullptr, ap, nullptr, nullptr, HID, 128);
    kalman_fin_k<<<ROWS / 8, 256>>>(ap, z_t, kg_w1,
                                    kp_w2, kp_b2, km_w1, km_b1, km_w2, km_b2,
                                    kg_w2, kg_b2, kW, out);
    // 8) per-batch reductions
    reduce_k<<<BB, 256>>>(out);
}

// round 17
// speedup vs baseline: 1.7144x; 1.0154x over previous
#include <cuda_runtime.h>
#include <cuda_fp16.h>
#include <cstdint>

#define BB    64
#define TT    512
#define HID   256
#define DI    512
#define DS    16
#define NHH   8
#define HD    64
#define DCONV 4
#define CCH   544    // DI + 2*DS
#define PROJ  1064   // 2*DI + 2*DS + NH
#define ROWS  (BB*TT) // 32768
#define NC    16
#define LC    32     // TT/NC
#define NT1   1152   // PROJ padded to 9*128

// ---------------- scratch (device globals; no allocation allowed) ----------
__device__ __align__(16) __half g_zx[ROWS * PROJ];
__device__ __align__(16) __half g_y[ROWS * DI];
__device__ __align__(16) float g_bc[ROWS * 32];
__device__ __align__(16) float g_hloc[BB * NHH * NC * HD * DS];
__device__ __align__(16) float g_hstart[BB * NHH * NC * HD * DS];
__device__ __align__(16) float g_cum[BB * NHH * TT];
__device__ __align__(16) __half g_xh[ROWS * HID];
__device__ __align__(16) __half g_yh[ROWS * DI];
__device__ __align__(16) __half g_ph[ROWS * HID];
__device__ __align__(16) float g_ap[ROWS * 128];
__device__ __align__(16) __half g_wt1[NT1 * HID];
__device__ __align__(16) __half g_wt2[HID * DI];
__device__ __align__(16) __half g_wk[128 * HID];
__device__ __align__(16) float g_kb[128];

// ---------------- helpers ---------------------------------------------------
__device__ __forceinline__ float siluf(float x) { return x / (1.f + __expf(-x)); }
__device__ __forceinline__ float softplusf(float x) {
    return (x > 20.f) ? x : log1pf(__expf(x));
}
__device__ __forceinline__ float sigmoidf_(float x) { return 1.f / (1.f + __expf(-x)); }
__device__ __forceinline__ float warpSum(float v) {
#pragma unroll
    for (int o = 16; o; o >>= 1) v += __shfl_xor_sync(0xffffffffu, v, o);
    return v;
}
__device__ __forceinline__ uint32_t smem_u32(const void* p) {
    uint32_t a;
    asm("{ .reg .u64 t; cvta.to.shared.u64 t, %1; cvt.u32.u64 %0, t; }"
        : "=r"(a) : "l"(p));
    return a;
}
#define SWZ(b) ((b) ^ (((b) >> 3) & 0x70))

__device__ __forceinline__ void ldsm_x4(uint32_t* r, uint32_t addr) {
    asm volatile("ldmatrix.sync.aligned.m8n8.x4.shared.b16 {%0,%1,%2,%3}, [%4];"
                 : "=r"(r[0]), "=r"(r[1]), "=r"(r[2]), "=r"(r[3]) : "r"(addr));
}
__device__ __forceinline__ void mma16816(float* c, const uint32_t* a, const uint32_t* b) {
    asm volatile("mma.sync.aligned.m16n8k16.row.col.f32.f16.f16.f32 "
                 "{%0,%1,%2,%3}, {%4,%5,%6,%7}, {%8,%9}, {%0,%1,%2,%3};"
                 : "+f"(c[0]), "+f"(c[1]), "+f"(c[2]), "+f"(c[3])
                 : "r"(a[0]), "r"(a[1]), "r"(a[2]), "r"(a[3]), "r"(b[0]), "r"(b[1]));
}
#define CP16(sa, gp) \
    asm volatile("cp.async.cg.shared.global [%0], [%1], 16;" :: "r"(sa), "l"(gp))
#define CP_COMMIT() asm volatile("cp.async.commit_group;" ::: "memory")
#define CP_WAIT1() asm volatile("cp.async.wait_group 1;" ::: "memory")
#define CP_WAIT0() asm volatile("cp.async.wait_group 0;" ::: "memory")

// ---------------- fp16 GEMM via mma.sync, cp.async 2-stage ------------------
#define TILE_B 16384
#define GSM_STAGE (2 * TILE_B)
__global__ __launch_bounds__(256, 2) void gemm_mma(
    const __half* __restrict__ A, const __half* __restrict__ B,
    const float* __restrict__ bias, const float* __restrict__ res,
    float* __restrict__ C, __half* __restrict__ ch, __half* __restrict__ oh,
    int K, int N)
{
    extern __shared__ __align__(16) uint8_t dsm[];
    uint32_t sbase = smem_u32(dsm);

    int tid = threadIdx.x;
    int wid = tid >> 5, lane = tid & 31;
    int bm = blockIdx.y * 128, bn = blockIdx.x * 128;
    int wm = (wid >> 2) * 64;
    int wn = (wid & 3) * 32;

    int lrow = tid >> 1;
    int lhe  = (tid & 1) * 32;
    const __half* pA = A + (size_t)(bm + lrow) * K + lhe;
    const __half* pB = B + (size_t)(bn + lrow) * K + lhe;
    uint32_t so[4];
#pragma unroll
    for (int i = 0; i < 4; i++)
        so[i] = SWZ((uint32_t)(lrow * 128 + (tid & 1) * 64 + i * 16));

    float acc[4][4][4];
#pragma unroll
    for (int i = 0; i < 4; i++)
#pragma unroll
        for (int j = 0; j < 4; j++)
#pragma unroll
            for (int q = 0; q < 4; q++) acc[i][j][q] = 0.f;

    int aRow = lane & 15;
    int aKb  = (lane >> 4) << 4;
    int bRow = ((lane >> 4) << 3) + (lane & 7);
    int bKb  = ((lane >> 3) & 1) << 4;

    const int KC = K >> 6;

    {
        uint32_t st = sbase;
#pragma unroll
        for (int i = 0; i < 4; i++) {
            CP16(st + so[i],          pA + i * 8);
            CP16(st + TILE_B + so[i], pB + i * 8);
        }
        CP_COMMIT();
    }

    for (int c = 0; c < KC; c++) {
        if (c + 1 < KC) {
            int e = (c + 1) * 64;
            uint32_t st = sbase + ((c + 1) & 1) * GSM_STAGE;
#pragma unroll
            for (int i = 0; i < 4; i++) {
                CP16(st + so[i],          pA + e + i * 8);
                CP16(st + TILE_B + so[i], pB + e + i * 8);
            }
            CP_COMMIT();
            CP_WAIT1();
        } else {
            CP_WAIT0();
        }
        __syncthreads();

        uint32_t st = sbase + (c & 1) * GSM_STAGE;
        uint32_t sA = st, sB = st + TILE_B;

#pragma unroll
        for (int ks = 0; ks < 4; ks++) {
            int kb2 = ks * 32;
            uint32_t ah[4][4], bh[2][4];
#pragma unroll
            for (int mt = 0; mt < 4; mt++) {
                uint32_t off = SWZ((uint32_t)(wm + mt * 16 + aRow) * 128 + kb2 + aKb);
                ldsm_x4(ah[mt], sA + off);
            }
#pragma unroll
            for (int np = 0; np < 2; np++) {
                uint32_t off = SWZ((uint32_t)(wn + np * 16 + bRow) * 128 + kb2 + bKb);
                ldsm_x4(bh[np], sB + off);
            }
#pragma unroll
            for (int mt = 0; mt < 4; mt++) {
#pragma unroll
                for (int nt = 0; nt < 4; nt++) {
                    const uint32_t* pbh = &bh[nt >> 1][(nt & 1) * 2];
                    mma16816(acc[mt][nt], ah[mt], pbh);
                }
            }
        }
        __syncthreads();
    }

    int mrow0 = bm + wm + (lane >> 2);
    int ncol0 = bn + wn + (lane & 3) * 2;
#pragma unroll
    for (int mt = 0; mt < 4; mt++) {
#pragma unroll
        for (int half = 0; half < 2; half++) {
            int m = mrow0 + mt * 16 + half * 8;
            float* crow = C ? C + (size_t)m * N : nullptr;
            __half* chrow = ch ? ch + (size_t)m * N : nullptr;
            const float* rrow = res ? res + (size_t)m * N : nullptr;
            int mp = m + 1;
            bool doshift = (oh != nullptr) && ((mp & (TT - 1)) != 0);
#pragma unroll
            for (int nt = 0; nt < 4; nt++) {
                int n = ncol0 + nt * 8;
                if (n + 1 < N) {
                    float v0 = acc[mt][nt][half * 2 + 0] + bias[n];
                    float v1 = acc[mt][nt][half * 2 + 1] + bias[n + 1];
                    if (res) { v0 += rrow[n]; v1 += rrow[n + 1]; }
                    if (crow) { crow[n] = v0; crow[n + 1] = v1; }
                    if (chrow) {
                        __half2 hp;
                        hp.x = __float2half_rn(v0);
                        hp.y = __float2half_rn(v1);
                        *(__half2*)(chrow + n) = hp;
                    }
                    if (doshift) {
                        __half2 hp;
                        hp.x = __float2half_rn(v0);
                        hp.y = __float2half_rn(v1);
                        *(__half2*)(oh + (size_t)mp * N + n) = hp;
                    }
                } else if (n < N) {
                    float v0 = acc[mt][nt][half * 2 + 0] + bias[n];
                    if (res) v0 += rrow[n];
                    if (crow) crow[n] = v0;
                    if (chrow) chrow[n] = __float2half_rn(v0);
                }
            }
        }
    }
}

// ---------------- merged weight prep + t=0 Kalman rows ----------------------
#define W1SZ (NT1 * HID)
#define W2SZ (HID * DI)
#define WKSZ (128 * HID)
#define IRSZ (BB * 64)
__global__ void prep_k(const float* __restrict__ in_w, const float* __restrict__ out_w,
                       const float* __restrict__ kp_w1, const float* __restrict__ kg_w1,
                       const float* __restrict__ kp_b1, const float* __restrict__ kg_b1,
                       const float* __restrict__ init_state,
                       __half* __restrict__ w1, __half* __restrict__ w2,
                       __half* __restrict__ wk, float* __restrict__ kb,
                       __half* __restrict__ ph) {
    int idx = blockIdx.x * blockDim.x + threadIdx.x;
    if (idx < W1SZ) {
        int n = idx / HID, k = idx % HID;
        float v = (n < PROJ) ? in_w[(size_t)k * PROJ + n] : 0.f;
        w1[idx] = __float2half_rn(v);
    } else if (idx < W1SZ + W2SZ) {
        int i = idx - W1SZ;
        int n = i / DI, k = i % DI;
        w2[i] = __float2half_rn(out_w[(size_t)k * HID + n]);
    } else if (idx < W1SZ + W2SZ + WKSZ) {
        int i = idx - W1SZ - W2SZ;
        int n = i / HID, k = i % HID;
        float v = (n < 64) ? kp_w1[(size_t)k * 64 + n] : kg_w1[(size_t)k * 64 + (n - 64)];
        wk[i] = __float2half_rn(v);
        if (i < 128) kb[i] = (i < 64) ? kp_b1[i] : kg_b1[i - 64];
    } else if (idx < W1SZ + W2SZ + WKSZ + IRSZ) {
        int i = idx - W1SZ - W2SZ - WKSZ;
        int b = i >> 6, t4 = i & 63;
        float4 v = ((const float4*)init_state)[t4];
        __half hh[4] = {__float2half_rn(v.x), __float2half_rn(v.y),
                        __float2half_rn(v.z), __float2half_rn(v.w)};
        size_t base = (size_t)(b * TT) * HID + t4 * 4;
        *(uint2*)(ph + base) = *(uint2*)hh;
    }
}

// ---------------- 1) rmsnorm -> fp16 (warp per row) -------------------------
__global__ void rmsnorm_cvt_k(const float* __restrict__ x, const float* __restrict__ w,
                              __half* __restrict__ oh) {
    int r = blockIdx.x * 4 + (threadIdx.x >> 5);
    int lane = threadIdx.x & 31;
    const float4* xr = (const float4*)(x + (size_t)r * HID);
    float4 v0 = xr[lane], v1 = xr[lane + 32];
    float ss = v0.x*v0.x + v0.y*v0.y + v0.z*v0.z + v0.w*v0.w
             + v1.x*v1.x + v1.y*v1.y + v1.z*v1.z + v1.w*v1.w;
    ss = warpSum(ss);
    float sc = rsqrtf(ss / HID + 1e-5f);
    const float4* wr = (const float4*)w;
    float4 w0 = wr[lane], w1 = wr[lane + 32];
    __half h0[4] = {__float2half_rn(v0.x*sc*w0.x), __float2half_rn(v0.y*sc*w0.y),
                    __float2half_rn(v0.z*sc*w0.z), __float2half_rn(v0.w*sc*w0.w)};
    __half h1[4] = {__float2half_rn(v1.x*sc*w1.x), __float2half_rn(v1.y*sc*w1.y),
                    __float2half_rn(v1.z*sc*w1.z), __float2half_rn(v1.w*sc*w1.w)};
    size_t base = (size_t)r * HID;
    *(uint2*)(oh + base + lane * 4) = *(uint2*)h0;
    *(uint2*)(oh + base + (lane + 32) * 4) = *(uint2*)h1;
}

// ---------------- 4a) fused conv+silu + chunked scan local pass --------------
// One block per (b, chunk): 512 threads = 8 heads x 64 dims. B/C conv + per-head
// dt/dA computed once per block.
__global__ __launch_bounds__(512) void scanA_k(
    const __half* __restrict__ zx, const float* __restrict__ cw,
    const float* __restrict__ cbv,
    const float* __restrict__ dt_bias, const float* __restrict__ A_log,
    const float* __restrict__ Dp, __half* __restrict__ y,
    float* __restrict__ hloc, float* __restrict__ cum, float* __restrict__ bc)
{
    __shared__ float sBC[LC][32];
    __shared__ float sdt[NHH][LC];
    __shared__ float sdA[NHH][LC];
    int b = blockIdx.x, c = blockIdx.y;
    int tid = threadIdx.x;
    int h = tid >> 6, d = tid & 63;
    int t0 = c * LC;
    size_t rowbase = (size_t)(b * TT + t0);

    // B/C with inline conv (channels 512..543) — once per (b,c)
    for (int i = tid; i < LC * 32; i += 512) {
        int t = i >> 5, j = i & 31;
        int ch = 512 + j;
        float acc = cbv[ch];
#pragma unroll
        for (int k = 0; k < DCONV; k++) {
            int tt = t0 + t - (DCONV - 1) + k;
            if (tt >= 0)
                acc = fmaf(__half2float(zx[((size_t)(b * TT + tt)) * PROJ + DI + ch]),
                           cw[k * CCH + ch], acc);
        }
        float v = siluf(acc);
        sBC[t][j] = v;
        bc[(rowbase + t) * 32 + j] = v;
    }
    // per-head dt AND dA: NHH*LC = 256 elements (dedupes the per-thread exp)
    for (int i = tid; i < NHH * LC; i += 512) {
        int hh = i >> 5, t = i & 31;
        float dtsp = softplusf(
            __half2float(zx[(rowbase + t) * PROJ + 2 * DI + 2 * DS + hh]) + dt_bias[hh]);
        sdt[hh][t] = dtsp;
        sdA[hh][t] = __expf(-dtsp * __expf(A_log[hh]));
    }
    __syncthreads();

    int ch = h * HD + d;
    float w0 = cw[0 * CCH + ch], w1 = cw[1 * CCH + ch];
    float w2 = cw[2 * CCH + ch], w3 = cw[3 * CCH + ch];
    float cb0 = cbv[ch];
    const __half* xcol = zx + DI + ch;
    float r0 = 0.f, r1 = 0.f, r2 = 0.f;
    {
        int tb = t0 - 3;
        if (tb >= 0)     r0 = __half2float(xcol[(size_t)(b * TT + tb) * PROJ]);
        if (tb + 1 >= 0) r1 = __half2float(xcol[(size_t)(b * TT + tb + 1) * PROJ]);
        if (tb + 2 >= 0) r2 = __half2float(xcol[(size_t)(b * TT + tb + 2) * PROJ]);
    }

    float Dh = Dp[h];
    float hr[DS];
#pragma unroll
    for (int s = 0; s < DS; s++) hr[s] = 0.f;
    float cm = 1.f;

    __half* yp = y + rowbase * DI + h * HD + d;
    float* cmp = cum + ((size_t)(b * NHH + h)) * TT + t0;

    for (int t = 0; t < LC; t++) {
        float raw = __half2float(xcol[(rowbase + t) * PROJ]);
        float x = siluf(fmaf(raw, w3, fmaf(r2, w2, fmaf(r1, w1, fmaf(r0, w0, cb0)))));
        r0 = r1; r1 = r2; r2 = raw;

        float dtsp = sdt[h][t];
        float dA = sdA[h][t];
        cm *= dA;
        if (d == 0) cmp[t] = cm;
        float dtx = dtsp * x;
        float yvp[4] = {Dh * x, 0.f, 0.f, 0.f};
        float Bv[16], Cv[16];
        *(float4*)&Bv[0]  = *(const float4*)&sBC[t][0];
        *(float4*)&Bv[4]  = *(const float4*)&sBC[t][4];
        *(float4*)&Bv[8]  = *(const float4*)&sBC[t][8];
        *(float4*)&Bv[12] = *(const float4*)&sBC[t][12];
        *(float4*)&Cv[0]  = *(const float4*)&sBC[t][16];
        *(float4*)&Cv[4]  = *(const float4*)&sBC[t][20];
        *(float4*)&Cv[8]  = *(const float4*)&sBC[t][24];
        *(float4*)&Cv[12] = *(const float4*)&sBC[t][28];
#pragma unroll
        for (int s = 0; s < DS; s++) {
            hr[s] = fmaf(hr[s], dA, dtx * Bv[s]);
            yvp[s & 3] = fmaf(hr[s], Cv[s], yvp[s & 3]);
        }
        yp[(size_t)t * DI] = __float2half_rn((yvp[0] + yvp[1]) + (yvp[2] + yvp[3]));
    }

    float* hl = hloc + ((size_t)((b * NHH + h) * NC + c)) * (DS * HD);
#pragma unroll
    for (int s = 0; s < DS; s++) hl[s * HD + d] = hr[s];
}

// ---------------- 4b) chain chunk states ------------------------------------
__global__ __launch_bounds__(64) void scanB_k(const float* __restrict__ hloc,
                                              const float* __restrict__ cum,
                                              float* __restrict__ hstart)
{
    int h = blockIdx.x, b = blockIdx.y, d = threadIdx.x;
    size_t base = (size_t)(b * NHH + h);
    float hs[DS];
#pragma unroll
    for (int s = 0; s < DS; s++) hs[s] = 0.f;
    for (int c = 0; c < NC; c++) {
        float* hsp = hstart + (base * NC + c) * (DS * HD);
#pragma unroll
        for (int s = 0; s < DS; s++) hsp[s * HD + d] = hs[s];
        float P = cum[base * TT + c * LC + LC - 1];
        const float* hl = hloc + (base * NC + c) * (DS * HD);
#pragma unroll
        for (int s = 0; s < DS; s++) hs[s] = fmaf(hs[s], P, hl[s * HD + d]);
    }
}

// ---------------- 4c) correction (fp16 RMW on y) -----------------------------
__global__ __launch_bounds__(64) void scanC_k(const float* __restrict__ bc,
                                              const float* __restrict__ hstart,
                                              const float* __restrict__ cum,
                                              __half* __restrict__ y)
{
    __shared__ float sC[LC][16];
    __shared__ float scm[LC];
    int h = blockIdx.x, b = blockIdx.y, c = blockIdx.z + 1;
    int d = threadIdx.x;
    int t0 = c * LC;
    size_t rowbase = (size_t)(b * TT + t0);
    size_t base = (size_t)(b * NHH + h);

    for (int i = d; i < LC * 16; i += 64) {
        int t = i >> 4, j = i & 15;
        sC[t][j] = bc[(rowbase + t) * 32 + 16 + j];
    }
    for (int i = d; i < LC; i += 64) scm[i] = cum[base * TT + t0 + i];

    float hs[DS];
    const float* hsp = hstart + (base * NC + c) * (DS * HD);
#pragma unroll
    for (int s = 0; s < DS; s++) hs[s] = hsp[s * HD + d];
    __syncthreads();

    __half* yp = y + rowbase * DI + h * HD + d;
    for (int t = 0; t < LC; t++) {
        float Cv[16];
        *(float4*)&Cv[0]  = *(const float4*)&sC[t][0];
        *(float4*)&Cv[4]  = *(const float4*)&sC[t][4];
        *(float4*)&Cv[8]  = *(const float4*)&sC[t][8];
        *(float4*)&Cv[12] = *(const float4*)&sC[t][12];
        float acc = 0.f;
#pragma unroll
        for (int s = 0; s < DS; s++) acc = fmaf(hs[s], Cv[s], acc);
        float v = __half2float(yp[(size_t)t * DI]) + acc * scm[t];
        yp[(size_t)t * DI] = __float2half_rn(v);
    }
}

// ---------------- 5) gate + rmsnorm -> fp16 (warp per row) ------------------
__global__ void gatenorm_cvt_k(const __half* __restrict__ y, const __half* __restrict__ zx,
                               const float* __restrict__ gw,
                               __half* __restrict__ oh) {
    int r = blockIdx.x * 4 + (threadIdx.x >> 5);
    int lane = threadIdx.x & 31;
    const __half* yr = y + (size_t)r * DI;
    const __half* zr = zx + (size_t)r * PROJ;
    float4 g[4];
    float ss = 0.f;
#pragma unroll
    for (int k = 0; k < 4; k++) {
        uint2 yu = *(const uint2*)(yr + (lane + 32 * k) * 4);
        __half2 ya = *(__half2*)&yu.x, yb = *(__half2*)&yu.y;
        uint2 zu = *(const uint2*)(zr + (lane + 32 * k) * 4);
        __half2 za = *(__half2*)&zu.x, zb = *(__half2*)&zu.y;
        g[k].x = __half2float(ya.x) * siluf(__half2float(za.x));
        g[k].y = __half2float(ya.y) * siluf(__half2float(za.y));
        g[k].z = __half2float(yb.x) * siluf(__half2float(zb.x));
        g[k].w = __half2float(yb.y) * siluf(__half2float(zb.y));
        ss += g[k].x*g[k].x + g[k].y*g[k].y + g[k].z*g[k].z + g[k].w*g[k].w;
    }
    ss = warpSum(ss);
    float sc = rsqrtf(ss / DI + 1e-5f);
    const float4* wr = (const float4*)gw;
    size_t base = (size_t)r * DI;
#pragma unroll
    for (int k = 0; k < 4; k++) {
        float4 wv = wr[lane + 32 * k];
        __half hh[4] = {__float2half_rn(g[k].x*sc*wv.x), __float2half_rn(g[k].y*sc*wv.y),
                        __float2half_rn(g[k].z*sc*wv.z), __float2half_rn(g[k].w*sc*wv.w)};
        *(uint2*)(oh + base + (lane + 32 * k) * 4) = *(uint2*)hh;
    }
}

// ---------------- 7b) Kalman finish (warp per row) ---------------------------
__global__ __launch_bounds__(256) void kalman_fin_k(
    const float* __restrict__ AP, const float* __restrict__ z_t,
    const float* __restrict__ kg_w1,
    const float* __restrict__ kp_w2, const float* __restrict__ kp_b2,
    const float* __restrict__ km_w1, const float* __restrict__ km_b1,
    const float* __restrict__ km_w2, const float* __restrict__ km_b2,
    const float* __restrict__ kg_w2, const float* __restrict__ kg_b2,
    const float* __restrict__ kW, float* __restrict__ out)
{
    int r = blockIdx.x * 8 + (threadIdx.x >> 5);
    int lane = threadIdx.x & 31;
    float z = z_t[r];
    const float* aprow = AP + (size_t)r * 128;

    float ap0 = aprow[lane], ap1 = aprow[lane + 32];
    float ag0 = fmaf(z, kg_w1[HID * 64 + lane],      aprow[64 + lane]);
    float ag1 = fmaf(z, kg_w1[HID * 64 + lane + 32], aprow[96 + lane]);
    float vp = siluf(ap0) * kp_w2[lane] + siluf(ap1) * kp_w2[lane + 32];
    float gp = siluf(ag0) * kg_w2[lane] + siluf(ag1) * kg_w2[lane + 32];
    float mp = siluf(fmaf(z, km_w1[lane], km_b1[lane])) * km_w2[lane];
    vp = warpSum(vp);
    gp = warpSum(gp);
    mp = warpSum(mp);
    if (lane == 0) {
        float v_prior = softplusf(vp + kp_b2[0]);
        float Kt = sigmoidf_(gp + kg_b2[0]);
        float m_t = softplusf(mp + km_b2[0]);
        float vpost = v_prior + Kt * (m_t - kW[0] * v_prior);
        vpost = fminf(fmaxf(vpost, 1e-6f), 10.f);
        out[r] = vpost;
    }
}

// ---------------- 8) per-batch softmax reductions ---------------------------
__global__ void reduce_k(float* __restrict__ out) {
    __shared__ float sa[256], sb[256];
    int b = blockIdx.x;
    int tid = threadIdx.x;
    const float* v = out + (size_t)b * TT;
    float v0 = v[tid], v1 = v[tid + 256];

    sa[tid] = fmaxf(v0, v1);
    sb[tid] = fminf(v0, v1);
    __syncthreads();
    for (int s = 128; s > 0; s >>= 1) {
        if (tid < s) {
            sa[tid] = fmaxf(sa[tid], sa[tid + s]);
            sb[tid] = fminf(sb[tid], sb[tid + s]);
        }
        __syncthreads();
    }
    float mx = sa[0], mn = sb[0];
    __syncthreads();

    float e0 = __expf(v0 - mx), e1 = __expf(v1 - mx);
    sa[tid] = e0 + e1;
    sb[tid] = e0 * v0 + e1 * v1;
    __syncthreads();
    for (int s = 128; s > 0; s >>= 1) {
        if (tid < s) { sa[tid] += sa[tid + s]; sb[tid] += sb[tid + s]; }
        __syncthreads();
    }
    float spden = sa[0], spnum = sb[0];
    __syncthreads();

    float f0 = __expf(mn - v0), f1 = __expf(mn - v1);
    sa[tid] = f0 + f1;
    sb[tid] = f0 * v0 + f1 * v1;
    __syncthreads();
    for (int s = 128; s > 0; s >>= 1) {
        if (tid < s) { sa[tid] += sa[tid + s]; sb[tid] += sb[tid + s]; }
        __syncthreads();
    }
    if (tid == 0) {
        out[ROWS + b] = spnum / spden;
        out[ROWS + BB + b] = sb[0] / sa[0];
    }
}

// ---------------- launcher ---------------------------------------------------
extern "C" void kernel_launch(void* const* d_in, const int* in_sizes, int n_in,
                              void* d_out, int out_size) {
    const float* tokens   = (const float*)d_in[0];
    const float* z_t      = (const float*)d_in[1];
    const float* norm_w   = (const float*)d_in[2];
    const float* in_w     = (const float*)d_in[3];
    const float* in_b     = (const float*)d_in[4];
    const float* conv_w   = (const float*)d_in[5];
    const float* conv_b   = (const float*)d_in[6];
    const float* dt_bias  = (const float*)d_in[7];
    const float* A_log    = (const float*)d_in[8];
    const float* Dp       = (const float*)d_in[9];
    const float* gnorm_w  = (const float*)d_in[10];
    const float* out_w    = (const float*)d_in[11];
    const float* out_b    = (const float*)d_in[12];
    const float* kp_w1    = (const float*)d_in[13];
    const float* kp_b1    = (const float*)d_in[14];
    const float* kp_w2    = (const float*)d_in[15];
    const float* kp_b2    = (const float*)d_in[16];
    const float* km_w1    = (const float*)d_in[17];
    const float* km_b1    = (const float*)d_in[18];
    const float* km_w2    = (const float*)d_in[19];
    const float* km_b2    = (const float*)d_in[20];
    const float* kg_w1    = (const float*)d_in[21];
    const float* kg_b1    = (const float*)d_in[22];
    const float* kg_w2    = (const float*)d_in[23];
    const float* kg_b2    = (const float*)d_in[24];
    const float* kW       = (const float*)d_in[25];
    const float* init_st  = (const float*)d_in[26];
    float* out = (float*)d_out;

    float *bc, *hloc, *hstart, *cum, *ap, *kb;
    __half *zx, *y, *xh, *yh, *ph, *wt1, *wt2, *wk;
    cudaGetSymbolAddress((void**)&zx,     g_zx);
    cudaGetSymbolAddress((void**)&y,      g_y);
    cudaGetSymbolAddress((void**)&bc,     g_bc);
    cudaGetSymbolAddress((void**)&hloc,   g_hloc);
    cudaGetSymbolAddress((void**)&hstart, g_hstart);
    cudaGetSymbolAddress((void**)&cum,    g_cum);
    cudaGetSymbolAddress((void**)&ap,     g_ap);
    cudaGetSymbolAddress((void**)&kb,     g_kb);
    cudaGetSymbolAddress((void**)&xh,     g_xh);
    cudaGetSymbolAddress((void**)&yh,     g_yh);
    cudaGetSymbolAddress((void**)&ph,     g_ph);
    cudaGetSymbolAddress((void**)&wt1,    g_wt1);
    cudaGetSymbolAddress((void**)&wt2,    g_wt2);
    cudaGetSymbolAddress((void**)&wk,     g_wk);

    cudaFuncSetAttribute(gemm_mma, cudaFuncAttributeMaxDynamicSharedMemorySize,
                         2 * GSM_STAGE);

    // weight prep (merged, single fp16) + t=0 Kalman rows
    prep_k<<<(W1SZ + W2SZ + WKSZ + IRSZ + 255) / 256, 256>>>(
        in_w, out_w, kp_w1, kg_w1, kp_b1, kg_b1, init_st,
        wt1, wt2, wk, kb, ph);

    // 1) rmsnorm -> fp16 (warp per row)
    rmsnorm_cvt_k<<<ROWS / 4, 128>>>(tokens, norm_w, xh);
    // 2) in-proj GEMM -> fp16 zx
    gemm_mma<<<dim3(NT1 / 128, ROWS / 128), 256, 2 * GSM_STAGE>>>(
        xh, wt1, in_b, nullptr, nullptr, zx, nullptr, HID, PROJ);
    // 3+4) fused conv + chunked scan (one block per (b,c), 8 heads/block)
    scanA_k<<<dim3(BB, NC), 512>>>(zx, conv_w, conv_b, dt_bias, A_log, Dp,
                                   y, hloc, cum, bc);
    scanB_k<<<dim3(NHH, BB), 64>>>(hloc, cum, hstart);
    scanC_k<<<dim3(NHH, BB, NC - 1), 64>>>(bc, hstart, cum, y);
    // 5) gate + rmsnorm (warp per row)
    gatenorm_cvt_k<<<ROWS / 4, 128>>>(y, zx, gnorm_w, yh);
    // 6) out-proj GEMM + residual, fused shift+cvt into ph
    gemm_mma<<<dim3(HID / 128, ROWS / 128), 256, 2 * GSM_STAGE>>>(
        yh, wt2, out_b, tokens, nullptr, nullptr, ph, DI, HID);
    // 7) Kalman GEMM -> finish (warp per row)
    gemm_mma<<<dim3(1, ROWS / 128), 256, 2 * GSM_STAGE>>>(
        ph, wk, kb, nullptr, ap, nullptr, nullptr, HID, 128);
    kalman_fin_k<<<ROWS / 8, 256>>>(ap, z_t, kg_w1,
                                    kp_w2, kp_b2, km_w1, km_b1, km_w2, km_b2,
                                    kg_w2, kg_b2, kW, out);
    // 8) per-batch reductions
    reduce_k<<<BB, 256>>>(out);
}